// round 9
// baseline (speedup 1.0000x reference)
#include <cuda_runtime.h>
#include <cuda_bf16.h>
#include <math.h>
#include <stdint.h>

#define BB 2
#define NN 320
#define DD 128
#define LL 4
#define OHH 100
#define KS 136   // smem row stride in bf16 elems (272 bytes)

// ---------------- device scratch (no allocs allowed) ----------------
__device__ float g_h[BB*NN*DD];
__device__ float g_x[BB*NN*3];
__device__ float g_A[BB*NN*DD];
__device__ float g_Bv[BB*NN*DD];
__device__ float g_S[BB*NN*DD];
__device__ float g_invC[BB*9];
__device__ unsigned short g_We2bf[LL*DD*DD];   // per-layer B[n][k] = We2[k][n] in bf16

// ---------------- math helpers ----------------
__device__ __forceinline__ float tanh_ap(float x){
    float t; asm("tanh.approx.f32 %0, %1;" : "=f"(t) : "f"(x)); return t;
}
__device__ __forceinline__ float silu_f(float x){
    return 0.5f*x*(1.f + tanh_ap(0.5f*x));
}
__device__ __forceinline__ float sigm_f(float x){
    return 0.5f*(1.f + tanh_ap(0.5f*x));
}
__device__ __forceinline__ uint32_t bf16x2_pack(float lo, float hi){
    uint32_t r;
    asm("cvt.rn.bf16x2.f32 %0, %1, %2;" : "=r"(r) : "f"(hi), "f"(lo));  // first src -> high half
    return r;
}

__device__ __forceinline__ uint32_t smem_u32(const void* p){
    uint32_t a;
    asm("{ .reg .u64 t; cvta.to.shared.u64 t, %1; cvt.u32.u64 %0, t; }" : "=r"(a) : "l"(p));
    return a;
}
__device__ __forceinline__ void ldsm4(uint32_t& r0, uint32_t& r1, uint32_t& r2, uint32_t& r3, uint32_t a){
    asm volatile("ldmatrix.sync.aligned.m8n8.x4.shared.b16 {%0,%1,%2,%3}, [%4];"
                 : "=r"(r0),"=r"(r1),"=r"(r2),"=r"(r3) : "r"(a));
}
__device__ __forceinline__ void mma16816(float* c, uint32_t a0,uint32_t a1,uint32_t a2,uint32_t a3,
                                         uint32_t b0,uint32_t b1){
    asm volatile("mma.sync.aligned.m16n8k16.row.col.f32.bf16.bf16.f32 "
        "{%0,%1,%2,%3}, {%4,%5,%6,%7}, {%8,%9}, {%0,%1,%2,%3};"
        : "+f"(c[0]),"+f"(c[1]),"+f"(c[2]),"+f"(c[3])
        : "r"(a0),"r"(a1),"r"(a2),"r"(a3),"r"(b0),"r"(b1));
}

// ---------------- small kernels ----------------
__global__ void k_inv(const float* __restrict__ cell){
    int b = threadIdx.x;
    if (b >= BB) return;
    const float* c = cell + b*9;
    float a00=c[0],a01=c[1],a02=c[2];
    float a10=c[3],a11=c[4],a12=c[5];
    float a20=c[6],a21=c[7],a22=c[8];
    float C00 =  a11*a22 - a12*a21;
    float C01 = -(a10*a22 - a12*a20);
    float C02 =  a10*a21 - a11*a20;
    float C10 = -(a01*a22 - a02*a21);
    float C11 =  a00*a22 - a02*a20;
    float C12 = -(a00*a21 - a01*a20);
    float C20 =  a01*a12 - a02*a11;
    float C21 = -(a00*a12 - a02*a10);
    float C22 =  a00*a11 - a01*a10;
    float det = a00*C00 + a01*C01 + a02*C02;
    float id = 1.f/det;
    float* o = g_invC + b*9;
    o[0]=C00*id; o[1]=C10*id; o[2]=C20*id;
    o[3]=C01*id; o[4]=C11*id; o[5]=C21*id;
    o[6]=C02*id; o[7]=C12*id; o[8]=C22*id;
}

__global__ void k_init(const float* __restrict__ pos){
    int t = blockIdx.x*blockDim.x + threadIdx.x;
    if (t < BB*NN*3) g_x[t] = pos[t];
}

// prepare We2^T bf16: B[n][k] = We2[k][n];  grid = LL*8 blocks
__global__ void k_prepW(const float* __restrict__ We2){
    int l = blockIdx.x >> 3, part = blockIdx.x & 7, tid = threadIdx.x;
    const float* W = We2 + l*DD*DD;
    unsigned short* dst = g_We2bf + l*DD*DD;
    int e0 = part*2048;
    for (int q = 0; q < 8; q++){
        int e = e0 + q*256 + tid;
        int n = e >> 7, k = e & 127;
        dst[e] = __bfloat16_as_ushort(__float2bfloat16_rn(W[k*DD + n]));
    }
}

// blocked input embedding: 4 atoms/block, 160 blocks
__global__ void __launch_bounds__(128) k_embed4(
    const float* __restrict__ pos, const float* __restrict__ oneh,
    const float* __restrict__ W1, const float* __restrict__ b1,
    const float* __restrict__ W2, const float* __restrict__ b2)
{
    __shared__ float sin_[4*104], sh1[4*128];
    int g0 = blockIdx.x*4, tid = threadIdx.x;
    for (int e = tid; e < 4*(OHH+3); e += 128){
        int q = e / (OHH+3), k = e % (OHH+3);
        sin_[q*104+k] = (k < 3) ? pos[(g0+q)*3 + k] : oneh[(g0+q)*OHH + (k-3)];
    }
    __syncthreads();
    float acc[4];
    {
        float b1v = b1[tid];
        #pragma unroll
        for (int q = 0; q < 4; q++) acc[q] = b1v;
        for (int k = 0; k < OHH+3; k++){
            float w = W1[k*DD + tid];
            #pragma unroll
            for (int q = 0; q < 4; q++) acc[q] = fmaf(sin_[q*104+k], w, acc[q]);
        }
        #pragma unroll
        for (int q = 0; q < 4; q++) sh1[q*128+tid] = silu_f(acc[q]);
    }
    __syncthreads();
    {
        float b2v = b2[tid];
        #pragma unroll
        for (int q = 0; q < 4; q++) acc[q] = b2v;
        for (int k = 0; k < DD; k += 4){
            float w0 = W2[(k+0)*DD + tid];
            float w1 = W2[(k+1)*DD + tid];
            float w2 = W2[(k+2)*DD + tid];
            float w3 = W2[(k+3)*DD + tid];
            #pragma unroll
            for (int q = 0; q < 4; q++){
                float4 h4 = *(const float4*)(sh1 + q*128 + k);
                acc[q] += h4.x*w0 + h4.y*w1 + h4.z*w2 + h4.w*w3;
            }
        }
        #pragma unroll
        for (int q = 0; q < 4; q++) g_h[(g0+q)*DD + tid] = acc[q];
    }
}

// blocked A/Bv: 4 atoms/block, 160 blocks
__global__ void __launch_bounds__(128) k_A4(const float* __restrict__ We1l){
    __shared__ float sh[4*128];
    int g0 = blockIdx.x*4, tid = threadIdx.x;
    #pragma unroll
    for (int q = 0; q < 4; q++) sh[q*128+tid] = g_h[(g0+q)*DD + tid];
    __syncthreads();
    float a[4], bv[4];
    #pragma unroll
    for (int q = 0; q < 4; q++){ a[q] = 0.f; bv[q] = 0.f; }
    for (int k = 0; k < DD; k += 4){
        float w1a = We1l[(k+0)*DD + tid], w2a = We1l[(DD+k+0)*DD + tid];
        float w1b = We1l[(k+1)*DD + tid], w2b = We1l[(DD+k+1)*DD + tid];
        float w1c = We1l[(k+2)*DD + tid], w2c = We1l[(DD+k+2)*DD + tid];
        float w1d = We1l[(k+3)*DD + tid], w2d = We1l[(DD+k+3)*DD + tid];
        #pragma unroll
        for (int q = 0; q < 4; q++){
            float4 h4 = *(const float4*)(sh + q*128 + k);
            a[q]  += h4.x*w1a + h4.y*w1b + h4.z*w1c + h4.w*w1d;
            bv[q] += h4.x*w2a + h4.y*w2b + h4.z*w2c + h4.w*w2d;
        }
    }
    #pragma unroll
    for (int q = 0; q < 4; q++){
        g_A[(g0+q)*DD + tid]  = a[q];
        g_Bv[(g0+q)*DD + tid] = bv[q];
    }
}

// ---------------- heavy kernel: per-(b,i), tcore GEMM + messages ----------------
// smem byte offsets (32-row j tiles):
#define OFF_B    0                       // bf16 [128][KS]  = 34816
#define OFF_M1   34816                   // bf16 [32][KS]   = 8704
#define OFF_GEO  43520                   // 5 x 320 floats  = 6400
#define OFF_WT   49920                   // 1280 floats     = 5120
#define OFF_MIJ  55040                   // 320 floats      = 1280
#define OFF_PART 56320                   // 128 floats      = 512
#define OFF_RED  56832                   // 32 floats       = 128
#define SMEMB    56960

__global__ void __launch_bounds__(256, 4) k_edge(
    const float* __restrict__ We1l, const float* __restrict__ be1l,
    const float* __restrict__ be2l, const float* __restrict__ We3l,
    const float* __restrict__ be3l,
    const float* __restrict__ Wm1l, const float* __restrict__ bm1l,
    const float* __restrict__ Wp1l, const float* __restrict__ bp1l,
    const float* __restrict__ Wp2l, const float* __restrict__ bp2l,
    const float* __restrict__ cell, const float* __restrict__ mask, int layer)
{
    extern __shared__ char base[];
    __nv_bfloat16* sB  = (__nv_bfloat16*)(base + OFF_B);
    __nv_bfloat16* sM1 = (__nv_bfloat16*)(base + OFF_M1);
    float* sDij = (float*)(base + OFF_GEO);
    float* sRx  = sDij + 320;
    float* sRy  = sRx + 320;
    float* sRz  = sRy + 320;
    float* sPm  = sRz + 320;
    float* sWt  = (float*)(base + OFF_WT);
    float* sMij = (float*)(base + OFF_MIJ);
    float* sPart= (float*)(base + OFF_PART);
    float* sRed = (float*)(base + OFF_RED);

    int i = blockIdx.x, b = blockIdx.y;
    int tid = threadIdx.x, wid = tid >> 5, lane = tid & 31;

    // stage B[n][k] bf16 into padded smem
    {
        const uint4* src = (const uint4*)(g_We2bf + layer*DD*DD);
        #pragma unroll
        for (int q = 0; q < 8; q++){
            int e = tid + q*256;
            int n = e >> 4, k0 = (e & 15) << 3;
            *(uint4*)(sB + n*KS + k0) = src[e];
        }
    }
    if (tid < 128){
        sWt[tid]       = be2l[tid];
        sWt[128+tid]   = We3l[tid];
        sWt[256+tid]   = Wm1l[tid];
        sWt[384+tid]   = bm1l[tid];
        ((float4*)(sWt+512))[tid] = make_float4(Wp1l[tid], bp1l[tid], Wp2l[tid], 0.f);
        sWt[1024+tid]  = g_A[(b*NN+i)*DD + tid] + be1l[tid];   // tb
        sWt[1152+tid]  = We1l[256*DD + tid];                    // wd
    }
    float mi = mask[b*NN + i];
    // geometry for all 320 j, frac computed inline from g_x
    {
        const float* ic = g_invC + b*9;
        float i0=ic[0],i1=ic[1],i2=ic[2],i3=ic[3],i4=ic[4],i5=ic[5],i6=ic[6],i7=ic[7],i8=ic[8];
        float xi0=g_x[(b*NN+i)*3+0], xi1=g_x[(b*NN+i)*3+1], xi2=g_x[(b*NN+i)*3+2];
        float fi0 = xi0*i0 + xi1*i3 + xi2*i6;
        float fi1 = xi0*i1 + xi1*i4 + xi2*i7;
        float fi2 = xi0*i2 + xi1*i5 + xi2*i8;
        float c0=cell[b*9+0],c1=cell[b*9+1],c2=cell[b*9+2];
        float c3=cell[b*9+3],c4=cell[b*9+4],c5=cell[b*9+5];
        float c6=cell[b*9+6],c7=cell[b*9+7],c8=cell[b*9+8];
        for (int j = tid; j < NN; j += 256){
            float xj0=g_x[(b*NN+j)*3+0], xj1=g_x[(b*NN+j)*3+1], xj2=g_x[(b*NN+j)*3+2];
            float f0 = xj0*i0 + xj1*i3 + xj2*i6 - fi0;
            float f1 = xj0*i1 + xj1*i4 + xj2*i7 - fi1;
            float f2 = xj0*i2 + xj1*i5 + xj2*i8 - fi2;
            f0 -= rintf(f0); f1 -= rintf(f1); f2 -= rintf(f2);
            float rx = f0*c0 + f1*c3 + f2*c6;
            float ry = f0*c1 + f1*c4 + f2*c7;
            float rz = f0*c2 + f1*c5 + f2*c8;
            float dij = sqrtf(rx*rx + ry*ry + rz*rz + 1e-12f);
            float pm = mi * mask[b*NN + j];
            sDij[j] = dij*pm + (1.f - pm)*1e6f;
            sRx[j] = rx*pm; sRy[j] = ry*pm; sRz[j] = rz*pm;
            sPm[j] = pm;
        }
    }
    __syncthreads();

    float be3v = be3l[0], bp2v = bp2l[0];

    // warp tiling: 2 M-chunks of 16 rows, 4 N-chunks of 32 cols
    int wm = (wid & 1) * 16;
    int wn = (wid >> 1) * 32;

    uint32_t sM1a = smem_u32(sM1);
    uint32_t sBa  = smem_u32(sB);
    int lr = lane & 7;
    int lb3 = (lane >> 3) & 1;
    int lb4 = lane >> 4;
    uint32_t aBase = sM1a + (uint32_t)(((wm + (lane & 15))*KS + lb4*8) * 2);
    uint32_t bBase0 = sBa + (uint32_t)(((wn + lb4*8 + lr)*KS + lb3*8) * 2);
    uint32_t bBase1 = sBa + (uint32_t)(((wn + (2 + lb4)*8 + lr)*KS + lb3*8) * 2);

    int m1row = tid >> 3;          // 0..31
    int m1k0 = (tid & 7) * 16;     // 16 cols per thread

    for (int T = 0; T < 10; T++){
        // ---- m1: 32 rows x 128 k bf16; 8 threads per row ----
        {
            int jg = T*32 + m1row;
            float dij = sDij[jg];
            const float4* bv = (const float4*)(g_Bv + (size_t)(b*NN + jg)*DD + m1k0);
            const float4* tb = (const float4*)(sWt + 1024 + m1k0);
            const float4* wd = (const float4*)(sWt + 1152 + m1k0);
            __nv_bfloat16* row_p = sM1 + m1row*KS + m1k0;
            #pragma unroll
            for (int u = 0; u < 2; u++){
                float4 bva = bv[2*u],   bvb = bv[2*u+1];
                float4 tba = tb[2*u],   tbb = tb[2*u+1];
                float4 wda = wd[2*u],   wdb = wd[2*u+1];
                uint4 pk;
                pk.x = bf16x2_pack(silu_f(tba.x + bva.x + dij*wda.x),
                                   silu_f(tba.y + bva.y + dij*wda.y));
                pk.y = bf16x2_pack(silu_f(tba.z + bva.z + dij*wda.z),
                                   silu_f(tba.w + bva.w + dij*wda.w));
                pk.z = bf16x2_pack(silu_f(tbb.x + bvb.x + dij*wdb.x),
                                   silu_f(tbb.y + bvb.y + dij*wdb.y));
                pk.w = bf16x2_pack(silu_f(tbb.z + bvb.z + dij*wdb.z),
                                   silu_f(tbb.w + bvb.w + dij*wdb.w));
                *(uint4*)(row_p + u*8) = pk;
            }
        }
        __syncthreads();

        // ---- GEMM: warp computes C[16 j][32 t] ----
        float acc[4][4];
        #pragma unroll
        for (int nt = 0; nt < 4; nt++)
            #pragma unroll
            for (int c = 0; c < 4; c++) acc[nt][c] = 0.f;

        uint32_t aA = aBase, bA0 = bBase0, bA1 = bBase1;
        #pragma unroll
        for (int ks = 0; ks < 8; ks++){
            uint32_t a0,a1,a2,a3;
            ldsm4(a0,a1,a2,a3, aA);
            uint32_t b0,b1,b2,b3;
            ldsm4(b0,b1,b2,b3, bA0);
            mma16816(acc[0], a0,a1,a2,a3, b0,b1);
            mma16816(acc[1], a0,a1,a2,a3, b2,b3);
            ldsm4(b0,b1,b2,b3, bA1);
            mma16816(acc[2], a0,a1,a2,a3, b0,b1);
            mma16816(acc[3], a0,a1,a2,a3, b2,b3);
            aA += 32; bA0 += 32; bA1 += 32;
        }

        // ---- m2 = silu(C + be2), dot with we3 per j ----
        {
            int colq = wn + (lane & 3)*2;
            float d0 = 0.f, d1 = 0.f;
            #pragma unroll
            for (int nt = 0; nt < 4; nt++){
                int col = colq + nt*8;
                float w0 = sWt[128+col], w1 = sWt[128+col+1];
                float e0 = sWt[col], e1 = sWt[col+1];
                d0 += silu_f(acc[nt][0] + e0)*w0 + silu_f(acc[nt][1] + e1)*w1;
                d1 += silu_f(acc[nt][2] + e0)*w0 + silu_f(acc[nt][3] + e1)*w1;
            }
            d0 += __shfl_xor_sync(0xffffffffu, d0, 1);
            d0 += __shfl_xor_sync(0xffffffffu, d0, 2);
            d1 += __shfl_xor_sync(0xffffffffu, d1, 1);
            d1 += __shfl_xor_sync(0xffffffffu, d1, 2);
            if ((lane & 3) == 0){
                int row = wm + (lane >> 2);
                sPart[(wid >> 1)*32 + row]     = d0;
                sPart[(wid >> 1)*32 + row + 8] = d1;
            }
        }
        __syncthreads();
        if (tid < 32){
            int j = T*32 + tid;
            sMij[j] = (sPart[tid] + sPart[32+tid] + sPart[64+tid] + sPart[96+tid] + be3v) * sPm[j];
        }
        __syncthreads();
    }

    // -------- balanced warp-split tail: Sacc (warps 0-3) vs phi (warps 4-7) --------
    if (wid < 4){
        int t = tid;   // 0..127
        float wm1 = sWt[256+t], bm1v = sWt[384+t];
        float s = 0.f;
        #pragma unroll 4
        for (int j = 0; j < NN; j++)
            s += silu_f(fmaf(sMij[j], wm1, bm1v));
        g_S[(b*NN+i)*DD + t] = s;
    } else {
        int p = tid - 128;
        const float4* phi4 = (const float4*)(sWt + 512);
        float dx0=0.f,dx1=0.f,dx2=0.f, sr0=0.f,sr1=0.f,sr2=0.f;
        #pragma unroll
        for (int rep = 0; rep < 3; rep++){
            int j = p + rep*128;
            if (j < NN){
                float mij = sMij[j];
                float inner = 0.f;
                #pragma unroll 4
                for (int t2 = 0; t2 < DD; t2++){
                    float4 w = phi4[t2];
                    inner += silu_f(fmaf(mij, w.x, w.y)) * w.z;
                }
                dx0 += sRx[j]*inner; dx1 += sRy[j]*inner; dx2 += sRz[j]*inner;
                sr0 += sRx[j]; sr1 += sRy[j]; sr2 += sRz[j];
            }
        }
        float v[6] = {dx0,dx1,dx2,sr0,sr1,sr2};
        #pragma unroll
        for (int c = 0; c < 6; c++)
            #pragma unroll
            for (int o = 16; o; o >>= 1) v[c] += __shfl_xor_sync(0xffffffffu, v[c], o);
        if (lane == 0){
            #pragma unroll
            for (int c = 0; c < 6; c++) sRed[(wid-4)*6 + c] = v[c];
        }
    }
    __syncthreads();
    if (tid == 0){
        float a0=0,a1=0,a2=0,s0=0,s1=0,s2=0;
        #pragma unroll
        for (int w = 0; w < 4; w++){
            a0 += sRed[w*6+0]; a1 += sRed[w*6+1]; a2 += sRed[w*6+2];
            s0 += sRed[w*6+3]; s1 += sRed[w*6+4]; s2 += sRed[w*6+5];
        }
        g_x[(b*NN+i)*3+0] += a0 + bp2v*s0;
        g_x[(b*NN+i)*3+1] += a1 + bp2v*s1;
        g_x[(b*NN+i)*3+2] += a2 + bp2v*s2;
    }
}

// ---------------- blocked node update: S@Wm2 -> GRU, 8 nodes/block, 256 threads ----------------
__global__ void __launch_bounds__(256) k_node(
    const float* __restrict__ Wm2l, const float* __restrict__ bm2l,
    const float* __restrict__ Wihl, const float* __restrict__ Whhl,
    const float* __restrict__ bihl, const float* __restrict__ bhhl,
    const float* __restrict__ mask)
{
    __shared__ float sS[8*128], shh[8*128], smn[8*128], sG[8*384], sHn[8*128];
    int g0 = blockIdx.x*8, tid = threadIdx.x;
    int col = tid & 127, half = tid >> 7;      // half 0: atoms 0-3, half 1: atoms 4-7

    #pragma unroll
    for (int qq = 0; qq < 4; qq++){
        int q = half*4 + qq;
        sS[q*128+col]  = g_S[(g0+q)*DD + col];
        shh[q*128+col] = g_h[(g0+q)*DD + col];
    }
    __syncthreads();

    // mn = S @ Wm2 + NN*bm2 (4 atoms per thread-half)
    {
        float acc[4];
        float bm = (float)NN * bm2l[col];
        #pragma unroll
        for (int qq = 0; qq < 4; qq++) acc[qq] = bm;
        for (int k = 0; k < DD; k += 4){
            float w0 = Wm2l[(k+0)*DD + col];
            float w1 = Wm2l[(k+1)*DD + col];
            float w2 = Wm2l[(k+2)*DD + col];
            float w3 = Wm2l[(k+3)*DD + col];
            #pragma unroll
            for (int qq = 0; qq < 4; qq++){
                float4 s4 = *(const float4*)(sS + (half*4+qq)*128 + k);
                acc[qq] += s4.x*w0 + s4.y*w1 + s4.z*w2 + s4.w*w3;
            }
        }
        #pragma unroll
        for (int qq = 0; qq < 4; qq++) smn[(half*4+qq)*128+col] = acc[qq];
    }
    __syncthreads();

    // gates: thread owns cols col, col+128, col+256 for its 4 atoms
    for (int c3 = 0; c3 < 3; c3++){
        int colg = col + c3*128;
        float gi[4], gh[4];
        float bi = bihl[colg], bh = bhhl[colg];
        #pragma unroll
        for (int qq = 0; qq < 4; qq++){ gi[qq] = bi; gh[qq] = bh; }
        for (int k = 0; k < DD; k += 4){
            #pragma unroll
            for (int kk = 0; kk < 4; kk++){
                float wi = Wihl[(k+kk)*384 + colg];
                float wh = Whhl[(k+kk)*384 + colg];
                #pragma unroll
                for (int qq = 0; qq < 4; qq++){
                    int q = half*4 + qq;
                    gi[qq] = fmaf(smn[q*128 + k+kk], wi, gi[qq]);
                    gh[qq] = fmaf(shh[q*128 + k+kk], wh, gh[qq]);
                }
            }
        }
        if (c3 < 2){
            #pragma unroll
            for (int qq = 0; qq < 4; qq++) sG[(half*4+qq)*384+colg] = gi[qq] + gh[qq];
        } else {
            #pragma unroll
            for (int qq = 0; qq < 4; qq++){
                int q = half*4 + qq;
                sG[q*384+colg] = gi[qq];
                sHn[q*128+col] = gh[qq];
            }
        }
    }
    __syncthreads();

    // finalize h (4 atoms per thread-half)
    #pragma unroll
    for (int qq = 0; qq < 4; qq++){
        int q = half*4 + qq;
        float r = sigm_f(sG[q*384 + col]);
        float z = sigm_f(sG[q*384 + 128 + col]);
        float n = tanh_ap(sG[q*384 + 256 + col] + r*sHn[q*128+col]);
        float hn = (1.f - z)*n + z*shh[q*128+col];
        g_h[(g0+q)*DD + col] = hn * mask[g0+q];
    }
}

// ---------------- pool + head ----------------
__global__ void k_pool(const float* __restrict__ mask,
                       const float* __restrict__ Wc1, const float* __restrict__ bc1,
                       const float* __restrict__ Wc2, const float* __restrict__ bc2,
                       const float* __restrict__ Wc3, const float* __restrict__ bc3,
                       float* __restrict__ out){
    int b = blockIdx.x, tid = threadIdx.x;
    __shared__ float feat[DD], o1[DD], o2[64];
    float s = 0.f, ms = 0.f;
    for (int i = 0; i < NN; i++){
        float mk = mask[b*NN + i];
        s  += g_h[(b*NN+i)*DD + tid]*mk;
        ms += mk;
    }
    feat[tid] = s / fmaxf(ms, 1.f);
    __syncthreads();
    float t = bc1[tid];
    #pragma unroll 8
    for (int k = 0; k < DD; k++) t += feat[k]*Wc1[k*DD + tid];
    o1[tid] = silu_f(t);
    __syncthreads();
    if (tid < 64){
        float t2 = bc2[tid];
        #pragma unroll 8
        for (int k = 0; k < DD; k++) t2 += o1[k]*Wc2[k*64 + tid];
        o2[tid] = silu_f(t2);
    }
    __syncthreads();
    if (tid < 6){
        float t3 = bc3[tid];
        #pragma unroll
        for (int k = 0; k < 64; k++) t3 += o2[k]*Wc3[k*6 + tid];
        float r;
        if (tid < 3){
            r = (t3 > 20.f) ? t3 : log1pf(expf(t3));
        } else {
            r = (1.f / (1.f + expf(-t3))) * 180.f;
        }
        out[b*6 + tid] = r;
    }
}

extern "C" void kernel_launch(void* const* d_in, const int* in_sizes, int n_in,
                              void* d_out, int out_size){
    const float* pos   = (const float*)d_in[0];
    const float* oneh  = (const float*)d_in[1];
    const float* mask  = (const float*)d_in[2];
    const float* cell  = (const float*)d_in[3];
    const float* W_in1 = (const float*)d_in[4];
    const float* b_in1 = (const float*)d_in[5];
    const float* W_in2 = (const float*)d_in[6];
    const float* b_in2 = (const float*)d_in[7];
    const float* We1   = (const float*)d_in[8];
    const float* be1   = (const float*)d_in[9];
    const float* We2   = (const float*)d_in[10];
    const float* be2   = (const float*)d_in[11];
    const float* We3   = (const float*)d_in[12];
    const float* be3   = (const float*)d_in[13];
    const float* Wm1   = (const float*)d_in[14];
    const float* bm1   = (const float*)d_in[15];
    const float* Wm2   = (const float*)d_in[16];
    const float* bm2   = (const float*)d_in[17];
    const float* Wp1   = (const float*)d_in[18];
    const float* bp1   = (const float*)d_in[19];
    const float* Wp2   = (const float*)d_in[20];
    const float* bp2   = (const float*)d_in[21];
    const float* W_ih  = (const float*)d_in[22];
    const float* W_hh  = (const float*)d_in[23];
    const float* b_ih  = (const float*)d_in[24];
    const float* b_hh  = (const float*)d_in[25];
    const float* Wc1   = (const float*)d_in[26];
    const float* bc1   = (const float*)d_in[27];
    const float* Wc2   = (const float*)d_in[28];
    const float* bc2   = (const float*)d_in[29];
    const float* Wc3   = (const float*)d_in[30];
    const float* bc3   = (const float*)d_in[31];
    float* out = (float*)d_out;

    cudaFuncSetAttribute(k_edge, cudaFuncAttributeMaxDynamicSharedMemorySize, SMEMB);

    k_inv<<<1, 32>>>(cell);
    k_init<<<(BB*NN*3 + 127)/128, 128>>>(pos);
    k_prepW<<<LL*8, 256>>>(We2);
    k_embed4<<<BB*NN/4, 128>>>(pos, oneh, W_in1, b_in1, W_in2, b_in2);

    for (int l = 0; l < LL; l++){
        k_A4<<<BB*NN/4, 128>>>(We1 + l*257*DD);
        k_edge<<<dim3(NN, BB), 256, SMEMB>>>(We1 + l*257*DD, be1 + l*DD,
                                    be2 + l*DD, We3 + l*DD, be3 + l,
                                    Wm1 + l*DD, bm1 + l*DD,
                                    Wp1 + l*DD, bp1 + l*DD,
                                    Wp2 + l*DD, bp2 + l,
                                    cell, mask, l);
        k_node<<<BB*NN/8, 256>>>(Wm2 + l*DD*DD, bm2 + l*DD,
                                 W_ih + l*DD*3*DD, W_hh + l*DD*3*DD,
                                 b_ih + l*3*DD,    b_hh + l*3*DD, mask);
    }

    k_pool<<<BB, 128>>>(mask, Wc1, bc1, Wc2, bc2, Wc3, bc3, out);
}

// round 10
// speedup vs baseline: 1.0902x; 1.0902x over previous
#include <cuda_runtime.h>
#include <cuda_bf16.h>
#include <math.h>
#include <stdint.h>

#define BB 2
#define NN 320
#define DD 128
#define LL 4
#define OHH 100
#define KS 136   // smem row stride in bf16 elems (272 bytes)

// ---------------- device scratch (no allocs allowed) ----------------
__device__ float g_h[BB*NN*DD];
__device__ float g_x[BB*NN*3];
__device__ float g_A[BB*NN*DD];
__device__ float g_Bv[BB*NN*DD];
__device__ float g_S[BB*NN*DD];
__device__ float g_invC[BB*9];
__device__ unsigned short g_We2bf[LL*DD*DD];   // per-layer B[n][k] = We2[k][n] in bf16

// ---------------- math helpers ----------------
__device__ __forceinline__ float tanh_ap(float x){
    float t; asm("tanh.approx.f32 %0, %1;" : "=f"(t) : "f"(x)); return t;
}
__device__ __forceinline__ float silu_f(float x){
    return 0.5f*x*(1.f + tanh_ap(0.5f*x));
}
__device__ __forceinline__ float sigm_f(float x){
    return 0.5f*(1.f + tanh_ap(0.5f*x));
}
__device__ __forceinline__ uint32_t bf16x2_pack(float lo, float hi){
    uint32_t r;
    asm("cvt.rn.bf16x2.f32 %0, %1, %2;" : "=r"(r) : "f"(hi), "f"(lo));  // first src -> high half
    return r;
}

__device__ __forceinline__ uint32_t smem_u32(const void* p){
    uint32_t a;
    asm("{ .reg .u64 t; cvta.to.shared.u64 t, %1; cvt.u32.u64 %0, t; }" : "=r"(a) : "l"(p));
    return a;
}
__device__ __forceinline__ void ldsm4(uint32_t& r0, uint32_t& r1, uint32_t& r2, uint32_t& r3, uint32_t a){
    asm volatile("ldmatrix.sync.aligned.m8n8.x4.shared.b16 {%0,%1,%2,%3}, [%4];"
                 : "=r"(r0),"=r"(r1),"=r"(r2),"=r"(r3) : "r"(a));
}
__device__ __forceinline__ void mma16816(float* c, uint32_t a0,uint32_t a1,uint32_t a2,uint32_t a3,
                                         uint32_t b0,uint32_t b1){
    asm volatile("mma.sync.aligned.m16n8k16.row.col.f32.bf16.bf16.f32 "
        "{%0,%1,%2,%3}, {%4,%5,%6,%7}, {%8,%9}, {%0,%1,%2,%3};"
        : "+f"(c[0]),"+f"(c[1]),"+f"(c[2]),"+f"(c[3])
        : "r"(a0),"r"(a1),"r"(a2),"r"(a3),"r"(b0),"r"(b1));
}

// ---------------- small kernels ----------------
__global__ void k_inv(const float* __restrict__ cell){
    int b = threadIdx.x;
    if (b >= BB) return;
    const float* c = cell + b*9;
    float a00=c[0],a01=c[1],a02=c[2];
    float a10=c[3],a11=c[4],a12=c[5];
    float a20=c[6],a21=c[7],a22=c[8];
    float C00 =  a11*a22 - a12*a21;
    float C01 = -(a10*a22 - a12*a20);
    float C02 =  a10*a21 - a11*a20;
    float C10 = -(a01*a22 - a02*a21);
    float C11 =  a00*a22 - a02*a20;
    float C12 = -(a00*a21 - a01*a20);
    float C20 =  a01*a12 - a02*a11;
    float C21 = -(a00*a12 - a02*a10);
    float C22 =  a00*a11 - a01*a10;
    float det = a00*C00 + a01*C01 + a02*C02;
    float id = 1.f/det;
    float* o = g_invC + b*9;
    o[0]=C00*id; o[1]=C10*id; o[2]=C20*id;
    o[3]=C01*id; o[4]=C11*id; o[5]=C21*id;
    o[6]=C02*id; o[7]=C12*id; o[8]=C22*id;
}

__global__ void k_init(const float* __restrict__ pos){
    int t = blockIdx.x*blockDim.x + threadIdx.x;
    if (t < BB*NN*3) g_x[t] = pos[t];
}

// prepare We2^T bf16: B[n][k] = We2[k][n];  grid = LL*8 blocks
__global__ void k_prepW(const float* __restrict__ We2){
    int l = blockIdx.x >> 3, part = blockIdx.x & 7, tid = threadIdx.x;
    const float* W = We2 + l*DD*DD;
    unsigned short* dst = g_We2bf + l*DD*DD;
    int e0 = part*2048;
    for (int q = 0; q < 8; q++){
        int e = e0 + q*256 + tid;
        int n = e >> 7, k = e & 127;
        dst[e] = __bfloat16_as_ushort(__float2bfloat16_rn(W[k*DD + n]));
    }
}

// per-atom input embedding (640 blocks — measured best shape)
__global__ void k_embed(const float* __restrict__ pos, const float* __restrict__ oneh,
                        const float* __restrict__ W1, const float* __restrict__ b1,
                        const float* __restrict__ W2, const float* __restrict__ b2){
    int i = blockIdx.x, b = blockIdx.y, tid = threadIdx.x;
    __shared__ float sin_[OHH+3];
    __shared__ float sh1[DD];
    if (tid < OHH+3){
        sin_[tid] = (tid < 3) ? pos[(b*NN+i)*3 + tid] : oneh[(b*NN+i)*OHH + (tid-3)];
    }
    __syncthreads();
    float t = b1[tid];
    #pragma unroll 8
    for (int k = 0; k < OHH+3; k++) t += sin_[k]*W1[k*DD + tid];
    sh1[tid] = silu_f(t);
    __syncthreads();
    float t2 = b2[tid];
    #pragma unroll 8
    for (int k = 0; k < DD; k++) t2 += sh1[k]*W2[k*DD + tid];
    g_h[(b*NN+i)*DD + tid] = t2;
}

// blocked A/Bv: 8 atoms/block
__global__ void __launch_bounds__(128) k_A8(const float* __restrict__ We1l){
    __shared__ float sh[8*128];
    int g0 = blockIdx.x*8, tid = threadIdx.x;
    #pragma unroll
    for (int q = 0; q < 8; q++) sh[q*128+tid] = g_h[(g0+q)*DD + tid];
    __syncthreads();
    float a[8], bv[8];
    #pragma unroll
    for (int q = 0; q < 8; q++){ a[q] = 0.f; bv[q] = 0.f; }
    for (int k = 0; k < DD; k += 4){
        float w1a = We1l[(k+0)*DD + tid], w2a = We1l[(DD+k+0)*DD + tid];
        float w1b = We1l[(k+1)*DD + tid], w2b = We1l[(DD+k+1)*DD + tid];
        float w1c = We1l[(k+2)*DD + tid], w2c = We1l[(DD+k+2)*DD + tid];
        float w1d = We1l[(k+3)*DD + tid], w2d = We1l[(DD+k+3)*DD + tid];
        #pragma unroll
        for (int q = 0; q < 8; q++){
            float4 h4 = *(const float4*)(sh + q*128 + k);
            a[q]  += h4.x*w1a + h4.y*w1b + h4.z*w1c + h4.w*w1d;
            bv[q] += h4.x*w2a + h4.y*w2b + h4.z*w2c + h4.w*w2d;
        }
    }
    #pragma unroll
    for (int q = 0; q < 8; q++){
        g_A[(g0+q)*DD + tid]  = a[q];
        g_Bv[(g0+q)*DD + tid] = bv[q];
    }
}

// ---------------- heavy kernel: per-(b,i), tcore GEMM + messages ----------------
// smem byte offsets (32-row j tiles):
#define OFF_B    0                       // bf16 [128][KS]  = 34816
#define OFF_M1   34816                   // bf16 [32][KS]   = 8704
#define OFF_GEO  43520                   // 5 x 320 floats  = 6400
#define OFF_WT   49920                   // 1280 floats     = 5120
#define OFF_MIJ  55040                   // 320 floats      = 1280
#define OFF_PART 56320                   // 128 floats      = 512
#define OFF_RED  56832                   // 32 floats       = 128
#define SMEMB    56960

__global__ void __launch_bounds__(256, 4) k_edge(
    const float* __restrict__ We1l, const float* __restrict__ be1l,
    const float* __restrict__ be2l, const float* __restrict__ We3l,
    const float* __restrict__ be3l,
    const float* __restrict__ Wm1l, const float* __restrict__ bm1l,
    const float* __restrict__ Wp1l, const float* __restrict__ bp1l,
    const float* __restrict__ Wp2l, const float* __restrict__ bp2l,
    const float* __restrict__ cell, const float* __restrict__ mask, int layer)
{
    extern __shared__ char base[];
    __nv_bfloat16* sB  = (__nv_bfloat16*)(base + OFF_B);
    __nv_bfloat16* sM1 = (__nv_bfloat16*)(base + OFF_M1);
    float* sDij = (float*)(base + OFF_GEO);
    float* sRx  = sDij + 320;
    float* sRy  = sRx + 320;
    float* sRz  = sRy + 320;
    float* sPm  = sRz + 320;
    float* sWt  = (float*)(base + OFF_WT);
    float* sMij = (float*)(base + OFF_MIJ);
    float* sPart= (float*)(base + OFF_PART);
    float* sRed = (float*)(base + OFF_RED);

    int i = blockIdx.x, b = blockIdx.y;
    int tid = threadIdx.x, wid = tid >> 5, lane = tid & 31;

    // stage B[n][k] bf16 into padded smem
    {
        const uint4* src = (const uint4*)(g_We2bf + layer*DD*DD);
        #pragma unroll
        for (int q = 0; q < 8; q++){
            int e = tid + q*256;
            int n = e >> 4, k0 = (e & 15) << 3;
            *(uint4*)(sB + n*KS + k0) = src[e];
        }
    }
    if (tid < 128){
        sWt[tid]       = be2l[tid];
        sWt[128+tid]   = We3l[tid];
        sWt[256+tid]   = Wm1l[tid];
        sWt[384+tid]   = bm1l[tid];
        ((float4*)(sWt+512))[tid] = make_float4(Wp1l[tid], bp1l[tid], Wp2l[tid], 0.f);
        sWt[1024+tid]  = g_A[(b*NN+i)*DD + tid] + be1l[tid];   // tb
        sWt[1152+tid]  = We1l[256*DD + tid];                    // wd
    }
    float mi = mask[b*NN + i];
    // geometry for all 320 j, frac computed inline from g_x
    {
        const float* ic = g_invC + b*9;
        float i0=ic[0],i1=ic[1],i2=ic[2],i3=ic[3],i4=ic[4],i5=ic[5],i6=ic[6],i7=ic[7],i8=ic[8];
        float xi0=g_x[(b*NN+i)*3+0], xi1=g_x[(b*NN+i)*3+1], xi2=g_x[(b*NN+i)*3+2];
        float fi0 = xi0*i0 + xi1*i3 + xi2*i6;
        float fi1 = xi0*i1 + xi1*i4 + xi2*i7;
        float fi2 = xi0*i2 + xi1*i5 + xi2*i8;
        float c0=cell[b*9+0],c1=cell[b*9+1],c2=cell[b*9+2];
        float c3=cell[b*9+3],c4=cell[b*9+4],c5=cell[b*9+5];
        float c6=cell[b*9+6],c7=cell[b*9+7],c8=cell[b*9+8];
        for (int j = tid; j < NN; j += 256){
            float xj0=g_x[(b*NN+j)*3+0], xj1=g_x[(b*NN+j)*3+1], xj2=g_x[(b*NN+j)*3+2];
            float f0 = xj0*i0 + xj1*i3 + xj2*i6 - fi0;
            float f1 = xj0*i1 + xj1*i4 + xj2*i7 - fi1;
            float f2 = xj0*i2 + xj1*i5 + xj2*i8 - fi2;
            f0 -= rintf(f0); f1 -= rintf(f1); f2 -= rintf(f2);
            float rx = f0*c0 + f1*c3 + f2*c6;
            float ry = f0*c1 + f1*c4 + f2*c7;
            float rz = f0*c2 + f1*c5 + f2*c8;
            float dij = sqrtf(rx*rx + ry*ry + rz*rz + 1e-12f);
            float pm = mi * mask[b*NN + j];
            sDij[j] = dij*pm + (1.f - pm)*1e6f;
            sRx[j] = rx*pm; sRy[j] = ry*pm; sRz[j] = rz*pm;
            sPm[j] = pm;
        }
    }
    __syncthreads();

    float be3v = be3l[0], bp2v = bp2l[0];

    // warp tiling: 2 M-chunks of 16 rows, 4 N-chunks of 32 cols
    int wm = (wid & 1) * 16;
    int wn = (wid >> 1) * 32;

    uint32_t sM1a = smem_u32(sM1);
    uint32_t sBa  = smem_u32(sB);
    int lr = lane & 7;
    int lb3 = (lane >> 3) & 1;
    int lb4 = lane >> 4;
    uint32_t aBase = sM1a + (uint32_t)(((wm + (lane & 15))*KS + lb4*8) * 2);
    uint32_t bBase0 = sBa + (uint32_t)(((wn + lb4*8 + lr)*KS + lb3*8) * 2);
    uint32_t bBase1 = sBa + (uint32_t)(((wn + (2 + lb4)*8 + lr)*KS + lb3*8) * 2);

    int m1row = tid >> 3;          // 0..31
    int m1k0 = (tid & 7) * 16;     // 16 cols per thread

    for (int T = 0; T < 10; T++){
        // ---- m1: 32 rows x 128 k bf16; 8 threads per row ----
        {
            int jg = T*32 + m1row;
            float dij = sDij[jg];
            const float4* bv = (const float4*)(g_Bv + (size_t)(b*NN + jg)*DD + m1k0);
            const float4* tb = (const float4*)(sWt + 1024 + m1k0);
            const float4* wd = (const float4*)(sWt + 1152 + m1k0);
            __nv_bfloat16* row_p = sM1 + m1row*KS + m1k0;
            #pragma unroll
            for (int u = 0; u < 2; u++){
                float4 bva = bv[2*u],   bvb = bv[2*u+1];
                float4 tba = tb[2*u],   tbb = tb[2*u+1];
                float4 wda = wd[2*u],   wdb = wd[2*u+1];
                uint4 pk;
                pk.x = bf16x2_pack(silu_f(tba.x + bva.x + dij*wda.x),
                                   silu_f(tba.y + bva.y + dij*wda.y));
                pk.y = bf16x2_pack(silu_f(tba.z + bva.z + dij*wda.z),
                                   silu_f(tba.w + bva.w + dij*wda.w));
                pk.z = bf16x2_pack(silu_f(tbb.x + bvb.x + dij*wdb.x),
                                   silu_f(tbb.y + bvb.y + dij*wdb.y));
                pk.w = bf16x2_pack(silu_f(tbb.z + bvb.z + dij*wdb.z),
                                   silu_f(tbb.w + bvb.w + dij*wdb.w));
                *(uint4*)(row_p + u*8) = pk;
            }
        }
        __syncthreads();

        // ---- GEMM: warp computes C[16 j][32 t] ----
        float acc[4][4];
        #pragma unroll
        for (int nt = 0; nt < 4; nt++)
            #pragma unroll
            for (int c = 0; c < 4; c++) acc[nt][c] = 0.f;

        uint32_t aA = aBase, bA0 = bBase0, bA1 = bBase1;
        #pragma unroll
        for (int ks = 0; ks < 8; ks++){
            uint32_t a0,a1,a2,a3;
            ldsm4(a0,a1,a2,a3, aA);
            uint32_t b0,b1,b2,b3;
            ldsm4(b0,b1,b2,b3, bA0);
            mma16816(acc[0], a0,a1,a2,a3, b0,b1);
            mma16816(acc[1], a0,a1,a2,a3, b2,b3);
            ldsm4(b0,b1,b2,b3, bA1);
            mma16816(acc[2], a0,a1,a2,a3, b0,b1);
            mma16816(acc[3], a0,a1,a2,a3, b2,b3);
            aA += 32; bA0 += 32; bA1 += 32;
        }

        // ---- m2 = silu(C + be2), dot with we3 per j ----
        {
            int colq = wn + (lane & 3)*2;
            float d0 = 0.f, d1 = 0.f;
            #pragma unroll
            for (int nt = 0; nt < 4; nt++){
                int col = colq + nt*8;
                float w0 = sWt[128+col], w1 = sWt[128+col+1];
                float e0 = sWt[col], e1 = sWt[col+1];
                d0 += silu_f(acc[nt][0] + e0)*w0 + silu_f(acc[nt][1] + e1)*w1;
                d1 += silu_f(acc[nt][2] + e0)*w0 + silu_f(acc[nt][3] + e1)*w1;
            }
            d0 += __shfl_xor_sync(0xffffffffu, d0, 1);
            d0 += __shfl_xor_sync(0xffffffffu, d0, 2);
            d1 += __shfl_xor_sync(0xffffffffu, d1, 1);
            d1 += __shfl_xor_sync(0xffffffffu, d1, 2);
            if ((lane & 3) == 0){
                int row = wm + (lane >> 2);
                sPart[(wid >> 1)*32 + row]     = d0;
                sPart[(wid >> 1)*32 + row + 8] = d1;
            }
        }
        __syncthreads();
        if (tid < 32){
            int j = T*32 + tid;
            sMij[j] = (sPart[tid] + sPart[32+tid] + sPart[64+tid] + sPart[96+tid] + be3v) * sPm[j];
        }
        __syncthreads();
    }

    // -------- balanced warp-split tail: Sacc (warps 0-3) vs phi (warps 4-7) --------
    if (wid < 4){
        int t = tid;   // 0..127
        float wm1 = sWt[256+t], bm1v = sWt[384+t];
        float s = 0.f;
        #pragma unroll 4
        for (int j = 0; j < NN; j++)
            s += silu_f(fmaf(sMij[j], wm1, bm1v));
        g_S[(b*NN+i)*DD + t] = s;
    } else {
        int p = tid - 128;
        const float4* phi4 = (const float4*)(sWt + 512);
        float dx0=0.f,dx1=0.f,dx2=0.f, sr0=0.f,sr1=0.f,sr2=0.f;
        #pragma unroll
        for (int rep = 0; rep < 3; rep++){
            int j = p + rep*128;
            if (j < NN){
                float mij = sMij[j];
                float inner = 0.f;
                #pragma unroll 4
                for (int t2 = 0; t2 < DD; t2++){
                    float4 w = phi4[t2];
                    inner += silu_f(fmaf(mij, w.x, w.y)) * w.z;
                }
                dx0 += sRx[j]*inner; dx1 += sRy[j]*inner; dx2 += sRz[j]*inner;
                sr0 += sRx[j]; sr1 += sRy[j]; sr2 += sRz[j];
            }
        }
        float v[6] = {dx0,dx1,dx2,sr0,sr1,sr2};
        #pragma unroll
        for (int c = 0; c < 6; c++)
            #pragma unroll
            for (int o = 16; o; o >>= 1) v[c] += __shfl_xor_sync(0xffffffffu, v[c], o);
        if (lane == 0){
            #pragma unroll
            for (int c = 0; c < 6; c++) sRed[(wid-4)*6 + c] = v[c];
        }
    }
    __syncthreads();
    if (tid == 0){
        float a0=0,a1=0,a2=0,s0=0,s1=0,s2=0;
        #pragma unroll
        for (int w = 0; w < 4; w++){
            a0 += sRed[w*6+0]; a1 += sRed[w*6+1]; a2 += sRed[w*6+2];
            s0 += sRed[w*6+3]; s1 += sRed[w*6+4]; s2 += sRed[w*6+5];
        }
        g_x[(b*NN+i)*3+0] += a0 + bp2v*s0;
        g_x[(b*NN+i)*3+1] += a1 + bp2v*s1;
        g_x[(b*NN+i)*3+2] += a2 + bp2v*s2;
    }
}

// ---------------- blocked node update: S@Wm2 -> GRU, 8 nodes/block ----------------
__global__ void __launch_bounds__(128) k_node(
    const float* __restrict__ Wm2l, const float* __restrict__ bm2l,
    const float* __restrict__ Wihl, const float* __restrict__ Whhl,
    const float* __restrict__ bihl, const float* __restrict__ bhhl,
    const float* __restrict__ mask)
{
    __shared__ float sS[8*128], shh[8*128], smn[8*128], sG[8*384], sHn[8*128];
    int g0 = blockIdx.x*8, tid = threadIdx.x;

    #pragma unroll
    for (int q = 0; q < 8; q++){
        sS[q*128+tid]  = g_S[(g0+q)*DD + tid];
        shh[q*128+tid] = g_h[(g0+q)*DD + tid];
    }
    __syncthreads();

    // mn = S @ Wm2 + NN*bm2 (col = tid)
    {
        float acc[8];
        float bm = (float)NN * bm2l[tid];
        #pragma unroll
        for (int q = 0; q < 8; q++) acc[q] = bm;
        for (int k = 0; k < DD; k += 4){
            float4 w4;
            w4.x = Wm2l[(k+0)*DD + tid];
            w4.y = Wm2l[(k+1)*DD + tid];
            w4.z = Wm2l[(k+2)*DD + tid];
            w4.w = Wm2l[(k+3)*DD + tid];
            #pragma unroll
            for (int q = 0; q < 8; q++){
                float4 s4 = *(const float4*)(sS + q*128 + k);
                acc[q] += s4.x*w4.x + s4.y*w4.y + s4.z*w4.z + s4.w*w4.w;
            }
        }
        #pragma unroll
        for (int q = 0; q < 8; q++) smn[q*128+tid] = acc[q];
    }
    __syncthreads();

    // gates: thread owns cols tid, tid+128, tid+256
    for (int c3 = 0; c3 < 3; c3++){
        int col = tid + c3*128;
        float gi[8], gh[8];
        float bi = bihl[col], bh = bhhl[col];
        #pragma unroll
        for (int q = 0; q < 8; q++){ gi[q] = bi; gh[q] = bh; }
        for (int k = 0; k < DD; k += 4){
            #pragma unroll
            for (int kk = 0; kk < 4; kk++){
                float wi = Wihl[(k+kk)*384 + col];
                float wh = Whhl[(k+kk)*384 + col];
                #pragma unroll
                for (int q = 0; q < 8; q++){
                    gi[q] = fmaf(smn[q*128 + k+kk], wi, gi[q]);
                    gh[q] = fmaf(shh[q*128 + k+kk], wh, gh[q]);
                }
            }
        }
        if (c3 < 2){
            #pragma unroll
            for (int q = 0; q < 8; q++) sG[q*384+col] = gi[q] + gh[q];
        } else {
            #pragma unroll
            for (int q = 0; q < 8; q++){ sG[q*384+col] = gi[q]; sHn[q*128+tid] = gh[q]; }
        }
    }
    __syncthreads();

    // finalize h
    #pragma unroll
    for (int q = 0; q < 8; q++){
        float r = sigm_f(sG[q*384 + tid]);
        float z = sigm_f(sG[q*384 + 128 + tid]);
        float n = tanh_ap(sG[q*384 + 256 + tid] + r*sHn[q*128+tid]);
        float hn = (1.f - z)*n + z*shh[q*128+tid];
        g_h[(g0+q)*DD + tid] = hn * mask[g0+q];
    }
}

// ---------------- pool + head ----------------
__global__ void k_pool(const float* __restrict__ mask,
                       const float* __restrict__ Wc1, const float* __restrict__ bc1,
                       const float* __restrict__ Wc2, const float* __restrict__ bc2,
                       const float* __restrict__ Wc3, const float* __restrict__ bc3,
                       float* __restrict__ out){
    int b = blockIdx.x, tid = threadIdx.x;
    __shared__ float feat[DD], o1[DD], o2[64];
    float s = 0.f, ms = 0.f;
    for (int i = 0; i < NN; i++){
        float mk = mask[b*NN + i];
        s  += g_h[(b*NN+i)*DD + tid]*mk;
        ms += mk;
    }
    feat[tid] = s / fmaxf(ms, 1.f);
    __syncthreads();
    float t = bc1[tid];
    #pragma unroll 8
    for (int k = 0; k < DD; k++) t += feat[k]*Wc1[k*DD + tid];
    o1[tid] = silu_f(t);
    __syncthreads();
    if (tid < 64){
        float t2 = bc2[tid];
        #pragma unroll 8
        for (int k = 0; k < DD; k++) t2 += o1[k]*Wc2[k*64 + tid];
        o2[tid] = silu_f(t2);
    }
    __syncthreads();
    if (tid < 6){
        float t3 = bc3[tid];
        #pragma unroll
        for (int k = 0; k < 64; k++) t3 += o2[k]*Wc3[k*6 + tid];
        float r;
        if (tid < 3){
            r = (t3 > 20.f) ? t3 : log1pf(expf(t3));
        } else {
            r = (1.f / (1.f + expf(-t3))) * 180.f;
        }
        out[b*6 + tid] = r;
    }
}

extern "C" void kernel_launch(void* const* d_in, const int* in_sizes, int n_in,
                              void* d_out, int out_size){
    const float* pos   = (const float*)d_in[0];
    const float* oneh  = (const float*)d_in[1];
    const float* mask  = (const float*)d_in[2];
    const float* cell  = (const float*)d_in[3];
    const float* W_in1 = (const float*)d_in[4];
    const float* b_in1 = (const float*)d_in[5];
    const float* W_in2 = (const float*)d_in[6];
    const float* b_in2 = (const float*)d_in[7];
    const float* We1   = (const float*)d_in[8];
    const float* be1   = (const float*)d_in[9];
    const float* We2   = (const float*)d_in[10];
    const float* be2   = (const float*)d_in[11];
    const float* We3   = (const float*)d_in[12];
    const float* be3   = (const float*)d_in[13];
    const float* Wm1   = (const float*)d_in[14];
    const float* bm1   = (const float*)d_in[15];
    const float* Wm2   = (const float*)d_in[16];
    const float* bm2   = (const float*)d_in[17];
    const float* Wp1   = (const float*)d_in[18];
    const float* bp1   = (const float*)d_in[19];
    const float* Wp2   = (const float*)d_in[20];
    const float* bp2   = (const float*)d_in[21];
    const float* W_ih  = (const float*)d_in[22];
    const float* W_hh  = (const float*)d_in[23];
    const float* b_ih  = (const float*)d_in[24];
    const float* b_hh  = (const float*)d_in[25];
    const float* Wc1   = (const float*)d_in[26];
    const float* bc1   = (const float*)d_in[27];
    const float* Wc2   = (const float*)d_in[28];
    const float* bc2   = (const float*)d_in[29];
    const float* Wc3   = (const float*)d_in[30];
    const float* bc3   = (const float*)d_in[31];
    float* out = (float*)d_out;

    cudaFuncSetAttribute(k_edge, cudaFuncAttributeMaxDynamicSharedMemorySize, SMEMB);

    k_inv<<<1, 32>>>(cell);
    k_init<<<(BB*NN*3 + 127)/128, 128>>>(pos);
    k_prepW<<<LL*8, 256>>>(We2);
    k_embed<<<dim3(NN, BB), 128>>>(pos, oneh, W_in1, b_in1, W_in2, b_in2);

    for (int l = 0; l < LL; l++){
        k_A8<<<BB*NN/8, 128>>>(We1 + l*257*DD);
        k_edge<<<dim3(NN, BB), 256, SMEMB>>>(We1 + l*257*DD, be1 + l*DD,
                                    be2 + l*DD, We3 + l*DD, be3 + l,
                                    Wm1 + l*DD, bm1 + l*DD,
                                    Wp1 + l*DD, bp1 + l*DD,
                                    Wp2 + l*DD, bp2 + l,
                                    cell, mask, l);
        k_node<<<BB*NN/8, 128>>>(Wm2 + l*DD*DD, bm2 + l*DD,
                                 W_ih + l*DD*3*DD, W_hh + l*DD*3*DD,
                                 b_ih + l*3*DD,    b_hh + l*3*DD, mask);
    }

    k_pool<<<BB, 128>>>(mask, Wc1, bc1, Wc2, bc2, Wc3, bc3, out);
}

// round 11
// speedup vs baseline: 1.2124x; 1.1121x over previous
#include <cuda_runtime.h>
#include <cuda_bf16.h>
#include <math.h>
#include <stdint.h>

#define BB 2
#define NN 320
#define DD 128
#define LL 4
#define OHH 100
#define KS 136   // smem row stride in bf16 elems (272 bytes)

// ---------------- device scratch (no allocs allowed) ----------------
__device__ float g_h[BB*NN*DD];
__device__ float g_x[BB*NN*3];
__device__ float g_A[BB*NN*DD];
__device__ float g_Bv[BB*NN*DD];
__device__ float g_S[BB*NN*DD];
__device__ float g_invC[BB*9];
__device__ unsigned short g_We2bf[LL*DD*DD];   // per-layer B[n][k] = We2[k][n] in bf16

// ---------------- math helpers ----------------
__device__ __forceinline__ float tanh_ap(float x){
    float t; asm("tanh.approx.f32 %0, %1;" : "=f"(t) : "f"(x)); return t;
}
__device__ __forceinline__ float silu_f(float x){
    return 0.5f*x*(1.f + tanh_ap(0.5f*x));
}
__device__ __forceinline__ float sigm_f(float x){
    return 0.5f*(1.f + tanh_ap(0.5f*x));
}
__device__ __forceinline__ uint32_t bf16x2_pack(float lo, float hi){
    uint32_t r;
    asm("cvt.rn.bf16x2.f32 %0, %1, %2;" : "=r"(r) : "f"(hi), "f"(lo));  // first src -> high half
    return r;
}

__device__ __forceinline__ uint32_t smem_u32(const void* p){
    uint32_t a;
    asm("{ .reg .u64 t; cvta.to.shared.u64 t, %1; cvt.u32.u64 %0, t; }" : "=r"(a) : "l"(p));
    return a;
}
__device__ __forceinline__ void ldsm4(uint32_t& r0, uint32_t& r1, uint32_t& r2, uint32_t& r3, uint32_t a){
    asm volatile("ldmatrix.sync.aligned.m8n8.x4.shared.b16 {%0,%1,%2,%3}, [%4];"
                 : "=r"(r0),"=r"(r1),"=r"(r2),"=r"(r3) : "r"(a));
}
__device__ __forceinline__ void mma16816(float* c, uint32_t a0,uint32_t a1,uint32_t a2,uint32_t a3,
                                         uint32_t b0,uint32_t b1){
    asm volatile("mma.sync.aligned.m16n8k16.row.col.f32.bf16.bf16.f32 "
        "{%0,%1,%2,%3}, {%4,%5,%6,%7}, {%8,%9}, {%0,%1,%2,%3};"
        : "+f"(c[0]),"+f"(c[1]),"+f"(c[2]),"+f"(c[3])
        : "r"(a0),"r"(a1),"r"(a2),"r"(a3),"r"(b0),"r"(b1));
}

// ---------------- small kernels ----------------
__global__ void k_inv(const float* __restrict__ cell){
    int b = threadIdx.x;
    if (b >= BB) return;
    const float* c = cell + b*9;
    float a00=c[0],a01=c[1],a02=c[2];
    float a10=c[3],a11=c[4],a12=c[5];
    float a20=c[6],a21=c[7],a22=c[8];
    float C00 =  a11*a22 - a12*a21;
    float C01 = -(a10*a22 - a12*a20);
    float C02 =  a10*a21 - a11*a20;
    float C10 = -(a01*a22 - a02*a21);
    float C11 =  a00*a22 - a02*a20;
    float C12 = -(a00*a21 - a01*a20);
    float C20 =  a01*a12 - a02*a11;
    float C21 = -(a00*a12 - a02*a10);
    float C22 =  a00*a11 - a01*a10;
    float det = a00*C00 + a01*C01 + a02*C02;
    float id = 1.f/det;
    float* o = g_invC + b*9;
    o[0]=C00*id; o[1]=C10*id; o[2]=C20*id;
    o[3]=C01*id; o[4]=C11*id; o[5]=C21*id;
    o[6]=C02*id; o[7]=C12*id; o[8]=C22*id;
}

__global__ void k_init(const float* __restrict__ pos){
    int t = blockIdx.x*blockDim.x + threadIdx.x;
    if (t < BB*NN*3) g_x[t] = pos[t];
}

// prepare We2^T bf16: B[n][k] = We2[k][n];  grid = LL*8 blocks
__global__ void k_prepW(const float* __restrict__ We2){
    int l = blockIdx.x >> 3, part = blockIdx.x & 7, tid = threadIdx.x;
    const float* W = We2 + l*DD*DD;
    unsigned short* dst = g_We2bf + l*DD*DD;
    int e0 = part*2048;
    for (int q = 0; q < 8; q++){
        int e = e0 + q*256 + tid;
        int n = e >> 7, k = e & 127;
        dst[e] = __bfloat16_as_ushort(__float2bfloat16_rn(W[k*DD + n]));
    }
}

// per-atom input embedding (640 blocks — measured best shape)
__global__ void k_embed(const float* __restrict__ pos, const float* __restrict__ oneh,
                        const float* __restrict__ W1, const float* __restrict__ b1,
                        const float* __restrict__ W2, const float* __restrict__ b2){
    int i = blockIdx.x, b = blockIdx.y, tid = threadIdx.x;
    __shared__ float sin_[OHH+3];
    __shared__ float sh1[DD];
    if (tid < OHH+3){
        sin_[tid] = (tid < 3) ? pos[(b*NN+i)*3 + tid] : oneh[(b*NN+i)*OHH + (tid-3)];
    }
    __syncthreads();
    float t = b1[tid];
    #pragma unroll 8
    for (int k = 0; k < OHH+3; k++) t += sin_[k]*W1[k*DD + tid];
    sh1[tid] = silu_f(t);
    __syncthreads();
    float t2 = b2[tid];
    #pragma unroll 8
    for (int k = 0; k < DD; k++) t2 += sh1[k]*W2[k*DD + tid];
    g_h[(b*NN+i)*DD + tid] = t2;
}

// blocked A/Bv: 8 atoms/block
__global__ void __launch_bounds__(128) k_A8(const float* __restrict__ We1l){
    __shared__ float sh[8*128];
    int g0 = blockIdx.x*8, tid = threadIdx.x;
    #pragma unroll
    for (int q = 0; q < 8; q++) sh[q*128+tid] = g_h[(g0+q)*DD + tid];
    __syncthreads();
    float a[8], bv[8];
    #pragma unroll
    for (int q = 0; q < 8; q++){ a[q] = 0.f; bv[q] = 0.f; }
    for (int k = 0; k < DD; k += 4){
        float w1a = We1l[(k+0)*DD + tid], w2a = We1l[(DD+k+0)*DD + tid];
        float w1b = We1l[(k+1)*DD + tid], w2b = We1l[(DD+k+1)*DD + tid];
        float w1c = We1l[(k+2)*DD + tid], w2c = We1l[(DD+k+2)*DD + tid];
        float w1d = We1l[(k+3)*DD + tid], w2d = We1l[(DD+k+3)*DD + tid];
        #pragma unroll
        for (int q = 0; q < 8; q++){
            float4 h4 = *(const float4*)(sh + q*128 + k);
            a[q]  += h4.x*w1a + h4.y*w1b + h4.z*w1c + h4.w*w1d;
            bv[q] += h4.x*w2a + h4.y*w2b + h4.z*w2c + h4.w*w2d;
        }
    }
    #pragma unroll
    for (int q = 0; q < 8; q++){
        g_A[(g0+q)*DD + tid]  = a[q];
        g_Bv[(g0+q)*DD + tid] = bv[q];
    }
}

// ---------------- heavy kernel: per-(b,i), pipelined tcore GEMM + messages ----------------
// smem byte offsets (16-row j tiles, DOUBLE buffered):
#define TROWS    16
#define NT       (NN/TROWS)              // 20 tiles
#define OFF_B    0                       // bf16 [128][KS]  = 34816
#define OFF_M1   34816                   // 2 x bf16[16][KS] = 8704
#define M1BUF    4352                    // bytes per buffer
#define OFF_GEO  43520                   // 5 x 320 floats  = 6400
#define OFF_WT   49920                   // 1280 floats     = 5120
#define OFF_MIJ  55040                   // 320 floats      = 1280
#define OFF_PART 56320                   // 2 x 128 floats  = 1024
#define OFF_RED  57344                   // 32 floats       = 128
#define SMEMB    57472

__global__ void __launch_bounds__(256, 4) k_edge(
    const float* __restrict__ We1l, const float* __restrict__ be1l,
    const float* __restrict__ be2l, const float* __restrict__ We3l,
    const float* __restrict__ be3l,
    const float* __restrict__ Wm1l, const float* __restrict__ bm1l,
    const float* __restrict__ Wp1l, const float* __restrict__ bp1l,
    const float* __restrict__ Wp2l, const float* __restrict__ bp2l,
    const float* __restrict__ cell, const float* __restrict__ mask, int layer)
{
    extern __shared__ char base[];
    __nv_bfloat16* sB  = (__nv_bfloat16*)(base + OFF_B);
    float* sDij = (float*)(base + OFF_GEO);
    float* sRx  = sDij + 320;
    float* sRy  = sRx + 320;
    float* sRz  = sRy + 320;
    float* sPm  = sRz + 320;
    float* sWt  = (float*)(base + OFF_WT);
    float* sMij = (float*)(base + OFF_MIJ);
    float* sPart= (float*)(base + OFF_PART);   // [2][128]
    float* sRed = (float*)(base + OFF_RED);

    int i = blockIdx.x, b = blockIdx.y;
    int tid = threadIdx.x, wid = tid >> 5, lane = tid & 31;

    // stage B[n][k] bf16 into padded smem
    {
        const uint4* src = (const uint4*)(g_We2bf + layer*DD*DD);
        #pragma unroll
        for (int q = 0; q < 8; q++){
            int e = tid + q*256;
            int n = e >> 4, k0 = (e & 15) << 3;
            *(uint4*)(sB + n*KS + k0) = src[e];
        }
    }
    if (tid < 128){
        sWt[tid]       = be2l[tid];
        sWt[128+tid]   = We3l[tid];
        sWt[256+tid]   = Wm1l[tid];
        sWt[384+tid]   = bm1l[tid];
        ((float4*)(sWt+512))[tid] = make_float4(Wp1l[tid], bp1l[tid], Wp2l[tid], 0.f);
        sWt[1024+tid]  = g_A[(b*NN+i)*DD + tid] + be1l[tid];   // tb
        sWt[1152+tid]  = We1l[256*DD + tid];                    // wd
    }
    float mi = mask[b*NN + i];
    // geometry for all 320 j, frac computed inline from g_x
    {
        const float* ic = g_invC + b*9;
        float i0=ic[0],i1=ic[1],i2=ic[2],i3=ic[3],i4=ic[4],i5=ic[5],i6=ic[6],i7=ic[7],i8=ic[8];
        float xi0=g_x[(b*NN+i)*3+0], xi1=g_x[(b*NN+i)*3+1], xi2=g_x[(b*NN+i)*3+2];
        float fi0 = xi0*i0 + xi1*i3 + xi2*i6;
        float fi1 = xi0*i1 + xi1*i4 + xi2*i7;
        float fi2 = xi0*i2 + xi1*i5 + xi2*i8;
        float c0=cell[b*9+0],c1=cell[b*9+1],c2=cell[b*9+2];
        float c3=cell[b*9+3],c4=cell[b*9+4],c5=cell[b*9+5];
        float c6=cell[b*9+6],c7=cell[b*9+7],c8=cell[b*9+8];
        for (int j = tid; j < NN; j += 256){
            float xj0=g_x[(b*NN+j)*3+0], xj1=g_x[(b*NN+j)*3+1], xj2=g_x[(b*NN+j)*3+2];
            float f0 = xj0*i0 + xj1*i3 + xj2*i6 - fi0;
            float f1 = xj0*i1 + xj1*i4 + xj2*i7 - fi1;
            float f2 = xj0*i2 + xj1*i5 + xj2*i8 - fi2;
            f0 -= rintf(f0); f1 -= rintf(f1); f2 -= rintf(f2);
            float rx = f0*c0 + f1*c3 + f2*c6;
            float ry = f0*c1 + f1*c4 + f2*c7;
            float rz = f0*c2 + f1*c5 + f2*c8;
            float dij = sqrtf(rx*rx + ry*ry + rz*rz + 1e-12f);
            float pm = mi * mask[b*NN + j];
            sDij[j] = dij*pm + (1.f - pm)*1e6f;
            sRx[j] = rx*pm; sRy[j] = ry*pm; sRz[j] = rz*pm;
            sPm[j] = pm;
        }
    }
    __syncthreads();

    float be3v = be3l[0], bp2v = bp2l[0];

    // warp tiling: all 8 warps share the 16-row tile, each owns 16 N-cols
    int wn = wid * 16;

    uint32_t sM1a = smem_u32(base + OFF_M1);
    uint32_t sBa  = smem_u32(sB);
    // A frag address (within a buffer): rows = lane&15, k-half = lane>>4
    uint32_t aOff = (uint32_t)(((lane & 15)*KS + (lane >> 4)*8) * 2);
    // B frag address: rows(n) = wn + lr + lb4*8... same formula family as R8
    int lr = lane & 7;
    int lb3 = (lane >> 3) & 1;
    int lb4 = lane >> 4;
    uint32_t bBase = sBa + (uint32_t)(((wn + lb4*8 + lr)*KS + lb3*8) * 2);

    // m1 thread mapping: row = tid>>4 (0..15), k0 = (tid&15)*8
    int m1row = tid >> 4;
    int m1k0 = (tid & 15) * 8;
    const float4* tb4 = (const float4*)(sWt + 1024 + m1k0);
    const float4* wd4 = (const float4*)(sWt + 1152 + m1k0);

    // ---- prologue: m1 tile 0 into buffer 0 ----
    {
        float dij = sDij[m1row];
        const float4* bv = (const float4*)(g_Bv + (size_t)(b*NN + m1row)*DD + m1k0);
        float4 bva = bv[0], bvb = bv[1];
        float4 tba = tb4[0], tbb = tb4[1];
        float4 wda = wd4[0], wdb = wd4[1];
        uint4 pk;
        pk.x = bf16x2_pack(silu_f(tba.x + bva.x + dij*wda.x), silu_f(tba.y + bva.y + dij*wda.y));
        pk.y = bf16x2_pack(silu_f(tba.z + bva.z + dij*wda.z), silu_f(tba.w + bva.w + dij*wda.w));
        pk.z = bf16x2_pack(silu_f(tbb.x + bvb.x + dij*wdb.x), silu_f(tbb.y + bvb.y + dij*wdb.y));
        pk.w = bf16x2_pack(silu_f(tbb.z + bvb.z + dij*wdb.z), silu_f(tbb.w + bvb.w + dij*wdb.w));
        *(uint4*)(base + OFF_M1 + m1row*(KS*2) + m1k0*2) = pk;
    }
    __syncthreads();

    for (int T = 0; T < NT; T++){
        int buf = T & 1;

        // ---- GEMM(T): warp computes C[16 j][16 t] from buf ----
        float acc[2][4];
        #pragma unroll
        for (int s = 0; s < 2; s++)
            #pragma unroll
            for (int c = 0; c < 4; c++) acc[s][c] = 0.f;

        uint32_t aA = sM1a + buf*M1BUF + aOff;
        uint32_t bA = bBase;
        #pragma unroll
        for (int ks = 0; ks < 8; ks++){
            uint32_t a0,a1,a2,a3, b0,b1,b2,b3;
            ldsm4(a0,a1,a2,a3, aA);
            ldsm4(b0,b1,b2,b3, bA);
            mma16816(acc[0], a0,a1,a2,a3, b0,b1);
            mma16816(acc[1], a0,a1,a2,a3, b2,b3);
            aA += 32; bA += 32;
        }

        // ---- m1(T+1) into other buffer (no barrier needed: disjoint buffer) ----
        if (T + 1 < NT){
            int jg = (T+1)*TROWS + m1row;
            float dij = sDij[jg];
            const float4* bv = (const float4*)(g_Bv + (size_t)(b*NN + jg)*DD + m1k0);
            float4 bva = bv[0], bvb = bv[1];
            float4 tba = tb4[0], tbb = tb4[1];
            float4 wda = wd4[0], wdb = wd4[1];
            uint4 pk;
            pk.x = bf16x2_pack(silu_f(tba.x + bva.x + dij*wda.x), silu_f(tba.y + bva.y + dij*wda.y));
            pk.y = bf16x2_pack(silu_f(tba.z + bva.z + dij*wda.z), silu_f(tba.w + bva.w + dij*wda.w));
            pk.z = bf16x2_pack(silu_f(tbb.x + bvb.x + dij*wdb.x), silu_f(tbb.y + bvb.y + dij*wdb.y));
            pk.w = bf16x2_pack(silu_f(tbb.z + bvb.z + dij*wdb.z), silu_f(tbb.w + bvb.w + dij*wdb.w));
            *(uint4*)(base + OFF_M1 + (buf^1)*M1BUF + m1row*(KS*2) + m1k0*2) = pk;
        }

        // ---- epilogue(T): m2 = silu(C + be2), dot with we3 over this warp's 16 cols ----
        {
            int colq = wn + (lane & 3)*2;
            float d0 = 0.f, d1 = 0.f;
            #pragma unroll
            for (int s = 0; s < 2; s++){
                int col = colq + s*8;
                float w0 = sWt[128+col], w1 = sWt[128+col+1];
                float e0 = sWt[col], e1 = sWt[col+1];
                d0 += silu_f(acc[s][0] + e0)*w0 + silu_f(acc[s][1] + e1)*w1;
                d1 += silu_f(acc[s][2] + e0)*w0 + silu_f(acc[s][3] + e1)*w1;
            }
            d0 += __shfl_xor_sync(0xffffffffu, d0, 1);
            d0 += __shfl_xor_sync(0xffffffffu, d0, 2);
            d1 += __shfl_xor_sync(0xffffffffu, d1, 1);
            d1 += __shfl_xor_sync(0xffffffffu, d1, 2);
            if ((lane & 3) == 0){
                int row = lane >> 2;   // 0..7
                sPart[buf*128 + wid*16 + row]     = d0;
                sPart[buf*128 + wid*16 + row + 8] = d1;
            }
        }
        __syncthreads();   // the ONE barrier per tile

        // ---- fold sMij(T) (tid<16) — overlaps next iteration's GEMM for other threads ----
        if (tid < 16){
            int j = T*TROWS + tid;
            float s = 0.f;
            #pragma unroll
            for (int w = 0; w < 8; w++) s += sPart[buf*128 + w*16 + tid];
            sMij[j] = (s + be3v) * sPm[j];
        }
    }
    __syncthreads();

    // -------- balanced warp-split tail: Sacc (warps 0-3) vs phi (warps 4-7) --------
    if (wid < 4){
        int t = tid;   // 0..127
        float wm1 = sWt[256+t], bm1v = sWt[384+t];
        float s = 0.f;
        #pragma unroll 4
        for (int j = 0; j < NN; j++)
            s += silu_f(fmaf(sMij[j], wm1, bm1v));
        g_S[(b*NN+i)*DD + t] = s;
    } else {
        int p = tid - 128;
        const float4* phi4 = (const float4*)(sWt + 512);
        float dx0=0.f,dx1=0.f,dx2=0.f, sr0=0.f,sr1=0.f,sr2=0.f;
        #pragma unroll
        for (int rep = 0; rep < 3; rep++){
            int j = p + rep*128;
            if (j < NN){
                float mij = sMij[j];
                float inner = 0.f;
                #pragma unroll 4
                for (int t2 = 0; t2 < DD; t2++){
                    float4 w = phi4[t2];
                    inner += silu_f(fmaf(mij, w.x, w.y)) * w.z;
                }
                dx0 += sRx[j]*inner; dx1 += sRy[j]*inner; dx2 += sRz[j]*inner;
                sr0 += sRx[j]; sr1 += sRy[j]; sr2 += sRz[j];
            }
        }
        float v[6] = {dx0,dx1,dx2,sr0,sr1,sr2};
        #pragma unroll
        for (int c = 0; c < 6; c++)
            #pragma unroll
            for (int o = 16; o; o >>= 1) v[c] += __shfl_xor_sync(0xffffffffu, v[c], o);
        if (lane == 0){
            #pragma unroll
            for (int c = 0; c < 6; c++) sRed[(wid-4)*6 + c] = v[c];
        }
    }
    __syncthreads();
    if (tid == 0){
        float a0=0,a1=0,a2=0,s0=0,s1=0,s2=0;
        #pragma unroll
        for (int w = 0; w < 4; w++){
            a0 += sRed[w*6+0]; a1 += sRed[w*6+1]; a2 += sRed[w*6+2];
            s0 += sRed[w*6+3]; s1 += sRed[w*6+4]; s2 += sRed[w*6+5];
        }
        g_x[(b*NN+i)*3+0] += a0 + bp2v*s0;
        g_x[(b*NN+i)*3+1] += a1 + bp2v*s1;
        g_x[(b*NN+i)*3+2] += a2 + bp2v*s2;
    }
}

// ---------------- blocked node update: S@Wm2 -> GRU, 8 nodes/block ----------------
__global__ void __launch_bounds__(128) k_node(
    const float* __restrict__ Wm2l, const float* __restrict__ bm2l,
    const float* __restrict__ Wihl, const float* __restrict__ Whhl,
    const float* __restrict__ bihl, const float* __restrict__ bhhl,
    const float* __restrict__ mask)
{
    __shared__ float sS[8*128], shh[8*128], smn[8*128], sG[8*384], sHn[8*128];
    int g0 = blockIdx.x*8, tid = threadIdx.x;

    #pragma unroll
    for (int q = 0; q < 8; q++){
        sS[q*128+tid]  = g_S[(g0+q)*DD + tid];
        shh[q*128+tid] = g_h[(g0+q)*DD + tid];
    }
    __syncthreads();

    // mn = S @ Wm2 + NN*bm2 (col = tid)
    {
        float acc[8];
        float bm = (float)NN * bm2l[tid];
        #pragma unroll
        for (int q = 0; q < 8; q++) acc[q] = bm;
        for (int k = 0; k < DD; k += 4){
            float4 w4;
            w4.x = Wm2l[(k+0)*DD + tid];
            w4.y = Wm2l[(k+1)*DD + tid];
            w4.z = Wm2l[(k+2)*DD + tid];
            w4.w = Wm2l[(k+3)*DD + tid];
            #pragma unroll
            for (int q = 0; q < 8; q++){
                float4 s4 = *(const float4*)(sS + q*128 + k);
                acc[q] += s4.x*w4.x + s4.y*w4.y + s4.z*w4.z + s4.w*w4.w;
            }
        }
        #pragma unroll
        for (int q = 0; q < 8; q++) smn[q*128+tid] = acc[q];
    }
    __syncthreads();

    // gates: thread owns cols tid, tid+128, tid+256
    for (int c3 = 0; c3 < 3; c3++){
        int col = tid + c3*128;
        float gi[8], gh[8];
        float bi = bihl[col], bh = bhhl[col];
        #pragma unroll
        for (int q = 0; q < 8; q++){ gi[q] = bi; gh[q] = bh; }
        for (int k = 0; k < DD; k += 4){
            #pragma unroll
            for (int kk = 0; kk < 4; kk++){
                float wi = Wihl[(k+kk)*384 + col];
                float wh = Whhl[(k+kk)*384 + col];
                #pragma unroll
                for (int q = 0; q < 8; q++){
                    gi[q] = fmaf(smn[q*128 + k+kk], wi, gi[q]);
                    gh[q] = fmaf(shh[q*128 + k+kk], wh, gh[q]);
                }
            }
        }
        if (c3 < 2){
            #pragma unroll
            for (int q = 0; q < 8; q++) sG[q*384+col] = gi[q] + gh[q];
        } else {
            #pragma unroll
            for (int q = 0; q < 8; q++){ sG[q*384+col] = gi[q]; sHn[q*128+tid] = gh[q]; }
        }
    }
    __syncthreads();

    // finalize h
    #pragma unroll
    for (int q = 0; q < 8; q++){
        float r = sigm_f(sG[q*384 + tid]);
        float z = sigm_f(sG[q*384 + 128 + tid]);
        float n = tanh_ap(sG[q*384 + 256 + tid] + r*sHn[q*128+tid]);
        float hn = (1.f - z)*n + z*shh[q*128+tid];
        g_h[(g0+q)*DD + tid] = hn * mask[g0+q];
    }
}

// ---------------- pool + head ----------------
__global__ void k_pool(const float* __restrict__ mask,
                       const float* __restrict__ Wc1, const float* __restrict__ bc1,
                       const float* __restrict__ Wc2, const float* __restrict__ bc2,
                       const float* __restrict__ Wc3, const float* __restrict__ bc3,
                       float* __restrict__ out){
    int b = blockIdx.x, tid = threadIdx.x;
    __shared__ float feat[DD], o1[DD], o2[64];
    float s = 0.f, ms = 0.f;
    for (int i = 0; i < NN; i++){
        float mk = mask[b*NN + i];
        s  += g_h[(b*NN+i)*DD + tid]*mk;
        ms += mk;
    }
    feat[tid] = s / fmaxf(ms, 1.f);
    __syncthreads();
    float t = bc1[tid];
    #pragma unroll 8
    for (int k = 0; k < DD; k++) t += feat[k]*Wc1[k*DD + tid];
    o1[tid] = silu_f(t);
    __syncthreads();
    if (tid < 64){
        float t2 = bc2[tid];
        #pragma unroll 8
        for (int k = 0; k < DD; k++) t2 += o1[k]*Wc2[k*64 + tid];
        o2[tid] = silu_f(t2);
    }
    __syncthreads();
    if (tid < 6){
        float t3 = bc3[tid];
        #pragma unroll
        for (int k = 0; k < 64; k++) t3 += o2[k]*Wc3[k*6 + tid];
        float r;
        if (tid < 3){
            r = (t3 > 20.f) ? t3 : log1pf(expf(t3));
        } else {
            r = (1.f / (1.f + expf(-t3))) * 180.f;
        }
        out[b*6 + tid] = r;
    }
}

extern "C" void kernel_launch(void* const* d_in, const int* in_sizes, int n_in,
                              void* d_out, int out_size){
    const float* pos   = (const float*)d_in[0];
    const float* oneh  = (const float*)d_in[1];
    const float* mask  = (const float*)d_in[2];
    const float* cell  = (const float*)d_in[3];
    const float* W_in1 = (const float*)d_in[4];
    const float* b_in1 = (const float*)d_in[5];
    const float* W_in2 = (const float*)d_in[6];
    const float* b_in2 = (const float*)d_in[7];
    const float* We1   = (const float*)d_in[8];
    const float* be1   = (const float*)d_in[9];
    const float* We2   = (const float*)d_in[10];
    const float* be2   = (const float*)d_in[11];
    const float* We3   = (const float*)d_in[12];
    const float* be3   = (const float*)d_in[13];
    const float* Wm1   = (const float*)d_in[14];
    const float* bm1   = (const float*)d_in[15];
    const float* Wm2   = (const float*)d_in[16];
    const float* bm2   = (const float*)d_in[17];
    const float* Wp1   = (const float*)d_in[18];
    const float* bp1   = (const float*)d_in[19];
    const float* Wp2   = (const float*)d_in[20];
    const float* bp2   = (const float*)d_in[21];
    const float* W_ih  = (const float*)d_in[22];
    const float* W_hh  = (const float*)d_in[23];
    const float* b_ih  = (const float*)d_in[24];
    const float* b_hh  = (const float*)d_in[25];
    const float* Wc1   = (const float*)d_in[26];
    const float* bc1   = (const float*)d_in[27];
    const float* Wc2   = (const float*)d_in[28];
    const float* bc2   = (const float*)d_in[29];
    const float* Wc3   = (const float*)d_in[30];
    const float* bc3   = (const float*)d_in[31];
    float* out = (float*)d_out;

    cudaFuncSetAttribute(k_edge, cudaFuncAttributeMaxDynamicSharedMemorySize, SMEMB);

    k_inv<<<1, 32>>>(cell);
    k_init<<<(BB*NN*3 + 127)/128, 128>>>(pos);
    k_prepW<<<LL*8, 256>>>(We2);
    k_embed<<<dim3(NN, BB), 128>>>(pos, oneh, W_in1, b_in1, W_in2, b_in2);

    for (int l = 0; l < LL; l++){
        k_A8<<<BB*NN/8, 128>>>(We1 + l*257*DD);
        k_edge<<<dim3(NN, BB), 256, SMEMB>>>(We1 + l*257*DD, be1 + l*DD,
                                    be2 + l*DD, We3 + l*DD, be3 + l,
                                    Wm1 + l*DD, bm1 + l*DD,
                                    Wp1 + l*DD, bp1 + l*DD,
                                    Wp2 + l*DD, bp2 + l,
                                    cell, mask, l);
        k_node<<<BB*NN/8, 128>>>(Wm2 + l*DD*DD, bm2 + l*DD,
                                 W_ih + l*DD*3*DD, W_hh + l*DD*3*DD,
                                 b_ih + l*3*DD,    b_hh + l*3*DD, mask);
    }

    k_pool<<<BB, 128>>>(mask, Wc1, bc1, Wc2, bc2, Wc3, bc3, out);
}

// round 12
// speedup vs baseline: 1.2168x; 1.0036x over previous
#include <cuda_runtime.h>
#include <cuda_bf16.h>
#include <math.h>
#include <stdint.h>

#define BB 2
#define NN 320
#define DD 128
#define LL 4
#define OHH 100
#define KS 136   // smem row stride in bf16 elems (272 bytes)

// ---------------- device scratch (no allocs allowed) ----------------
__device__ float g_h[BB*NN*DD];
__device__ float g_x[BB*NN*3];
__device__ float g_A[BB*NN*DD];
__device__ float g_Bv[BB*NN*DD];
__device__ float g_S[BB*NN*DD];
__device__ float g_invC[BB*9];
__device__ unsigned short g_We2bf[LL*DD*DD];   // per-layer B[n][k] = We2[k][n] in bf16

// ---------------- math helpers ----------------
__device__ __forceinline__ float tanh_ap(float x){
    float t; asm("tanh.approx.f32 %0, %1;" : "=f"(t) : "f"(x)); return t;
}
__device__ __forceinline__ float silu_f(float x){
    return 0.5f*x*(1.f + tanh_ap(0.5f*x));
}
__device__ __forceinline__ float sigm_f(float x){
    return 0.5f*(1.f + tanh_ap(0.5f*x));
}
__device__ __forceinline__ uint32_t bf16x2_pack(float lo, float hi){
    uint32_t r;
    asm("cvt.rn.bf16x2.f32 %0, %1, %2;" : "=r"(r) : "f"(hi), "f"(lo));  // first src -> high half
    return r;
}

__device__ __forceinline__ uint32_t smem_u32(const void* p){
    uint32_t a;
    asm("{ .reg .u64 t; cvta.to.shared.u64 t, %1; cvt.u32.u64 %0, t; }" : "=r"(a) : "l"(p));
    return a;
}
__device__ __forceinline__ void ldsm4(uint32_t& r0, uint32_t& r1, uint32_t& r2, uint32_t& r3, uint32_t a){
    asm volatile("ldmatrix.sync.aligned.m8n8.x4.shared.b16 {%0,%1,%2,%3}, [%4];"
                 : "=r"(r0),"=r"(r1),"=r"(r2),"=r"(r3) : "r"(a));
}
__device__ __forceinline__ void mma16816(float* c, uint32_t a0,uint32_t a1,uint32_t a2,uint32_t a3,
                                         uint32_t b0,uint32_t b1){
    asm volatile("mma.sync.aligned.m16n8k16.row.col.f32.bf16.bf16.f32 "
        "{%0,%1,%2,%3}, {%4,%5,%6,%7}, {%8,%9}, {%0,%1,%2,%3};"
        : "+f"(c[0]),"+f"(c[1]),"+f"(c[2]),"+f"(c[3])
        : "r"(a0),"r"(a1),"r"(a2),"r"(a3),"r"(b0),"r"(b1));
}

// ---------------- small kernels ----------------
__global__ void k_inv(const float* __restrict__ cell){
    int b = threadIdx.x;
    if (b >= BB) return;
    const float* c = cell + b*9;
    float a00=c[0],a01=c[1],a02=c[2];
    float a10=c[3],a11=c[4],a12=c[5];
    float a20=c[6],a21=c[7],a22=c[8];
    float C00 =  a11*a22 - a12*a21;
    float C01 = -(a10*a22 - a12*a20);
    float C02 =  a10*a21 - a11*a20;
    float C10 = -(a01*a22 - a02*a21);
    float C11 =  a00*a22 - a02*a20;
    float C12 = -(a00*a21 - a01*a20);
    float C20 =  a01*a12 - a02*a11;
    float C21 = -(a00*a12 - a02*a10);
    float C22 =  a00*a11 - a01*a10;
    float det = a00*C00 + a01*C01 + a02*C02;
    float id = 1.f/det;
    float* o = g_invC + b*9;
    o[0]=C00*id; o[1]=C10*id; o[2]=C20*id;
    o[3]=C01*id; o[4]=C11*id; o[5]=C21*id;
    o[6]=C02*id; o[7]=C12*id; o[8]=C22*id;
}

__global__ void k_init(const float* __restrict__ pos){
    int t = blockIdx.x*blockDim.x + threadIdx.x;
    if (t < BB*NN*3) g_x[t] = pos[t];
}

// prepare We2^T bf16: B[n][k] = We2[k][n];  grid = LL*8 blocks
__global__ void k_prepW(const float* __restrict__ We2){
    int l = blockIdx.x >> 3, part = blockIdx.x & 7, tid = threadIdx.x;
    const float* W = We2 + l*DD*DD;
    unsigned short* dst = g_We2bf + l*DD*DD;
    int e0 = part*2048;
    for (int q = 0; q < 8; q++){
        int e = e0 + q*256 + tid;
        int n = e >> 7, k = e & 127;
        dst[e] = __bfloat16_as_ushort(__float2bfloat16_rn(W[k*DD + n]));
    }
}

// per-atom input embedding (640 blocks — measured best shape)
__global__ void k_embed(const float* __restrict__ pos, const float* __restrict__ oneh,
                        const float* __restrict__ W1, const float* __restrict__ b1,
                        const float* __restrict__ W2, const float* __restrict__ b2){
    int i = blockIdx.x, b = blockIdx.y, tid = threadIdx.x;
    __shared__ float sin_[OHH+3];
    __shared__ float sh1[DD];
    if (tid < OHH+3){
        sin_[tid] = (tid < 3) ? pos[(b*NN+i)*3 + tid] : oneh[(b*NN+i)*OHH + (tid-3)];
    }
    __syncthreads();
    float t = b1[tid];
    #pragma unroll 8
    for (int k = 0; k < OHH+3; k++) t += sin_[k]*W1[k*DD + tid];
    sh1[tid] = silu_f(t);
    __syncthreads();
    float t2 = b2[tid];
    #pragma unroll 8
    for (int k = 0; k < DD; k++) t2 += sh1[k]*W2[k*DD + tid];
    g_h[(b*NN+i)*DD + tid] = t2;
}

// blocked A/Bv: 8 atoms/block
__global__ void __launch_bounds__(128) k_A8(const float* __restrict__ We1l){
    __shared__ float sh[8*128];
    int g0 = blockIdx.x*8, tid = threadIdx.x;
    #pragma unroll
    for (int q = 0; q < 8; q++) sh[q*128+tid] = g_h[(g0+q)*DD + tid];
    __syncthreads();
    float a[8], bv[8];
    #pragma unroll
    for (int q = 0; q < 8; q++){ a[q] = 0.f; bv[q] = 0.f; }
    for (int k = 0; k < DD; k += 4){
        float w1a = We1l[(k+0)*DD + tid], w2a = We1l[(DD+k+0)*DD + tid];
        float w1b = We1l[(k+1)*DD + tid], w2b = We1l[(DD+k+1)*DD + tid];
        float w1c = We1l[(k+2)*DD + tid], w2c = We1l[(DD+k+2)*DD + tid];
        float w1d = We1l[(k+3)*DD + tid], w2d = We1l[(DD+k+3)*DD + tid];
        #pragma unroll
        for (int q = 0; q < 8; q++){
            float4 h4 = *(const float4*)(sh + q*128 + k);
            a[q]  += h4.x*w1a + h4.y*w1b + h4.z*w1c + h4.w*w1d;
            bv[q] += h4.x*w2a + h4.y*w2b + h4.z*w2c + h4.w*w2d;
        }
    }
    #pragma unroll
    for (int q = 0; q < 8; q++){
        g_A[(g0+q)*DD + tid]  = a[q];
        g_Bv[(g0+q)*DD + tid] = bv[q];
    }
}

// ---------------- heavy kernel: per-(b,i), pipelined tcore GEMM + messages ----------------
// smem byte offsets (16-row j tiles, DOUBLE buffered):
#define TROWS    16
#define NT       (NN/TROWS)              // 20 tiles
#define OFF_B    0                       // bf16 [128][KS]  = 34816
#define OFF_M1   34816                   // 2 x bf16[16][KS] = 8704
#define M1BUF    4352                    // bytes per buffer
#define OFF_GEO  43520                   // 5 x 320 floats  = 6400
#define OFF_WT   49920                   // 1280 floats     = 5120
#define OFF_MIJ  55040                   // 320 floats      = 1280
#define OFF_PART 56320                   // 2 x 128 floats  = 1024
#define OFF_RED  57344                   // 32 floats       = 128
#define SMEMB    57472

__global__ void __launch_bounds__(256, 4) k_edge(
    const float* __restrict__ We1l, const float* __restrict__ be1l,
    const float* __restrict__ be2l, const float* __restrict__ We3l,
    const float* __restrict__ be3l,
    const float* __restrict__ Wm1l, const float* __restrict__ bm1l,
    const float* __restrict__ Wp1l, const float* __restrict__ bp1l,
    const float* __restrict__ Wp2l, const float* __restrict__ bp2l,
    const float* __restrict__ cell, const float* __restrict__ mask, int layer)
{
    extern __shared__ char base[];
    __nv_bfloat16* sB  = (__nv_bfloat16*)(base + OFF_B);
    float* sDij = (float*)(base + OFF_GEO);
    float* sRx  = sDij + 320;
    float* sRy  = sRx + 320;
    float* sRz  = sRy + 320;
    float* sPm  = sRz + 320;
    float* sWt  = (float*)(base + OFF_WT);
    float* sMij = (float*)(base + OFF_MIJ);
    float* sPart= (float*)(base + OFF_PART);   // [2][128]
    float* sRed = (float*)(base + OFF_RED);

    int i = blockIdx.x, b = blockIdx.y;
    int tid = threadIdx.x, wid = tid >> 5, lane = tid & 31;

    // stage B[n][k] bf16 into padded smem
    {
        const uint4* src = (const uint4*)(g_We2bf + layer*DD*DD);
        #pragma unroll
        for (int q = 0; q < 8; q++){
            int e = tid + q*256;
            int n = e >> 4, k0 = (e & 15) << 3;
            *(uint4*)(sB + n*KS + k0) = src[e];
        }
    }
    if (tid < 128){
        sWt[tid]       = be2l[tid];
        sWt[128+tid]   = We3l[tid];
        sWt[256+tid]   = Wm1l[tid];
        sWt[384+tid]   = bm1l[tid];
        ((float4*)(sWt+512))[tid] = make_float4(Wp1l[tid], bp1l[tid], Wp2l[tid], 0.f);
        sWt[1024+tid]  = g_A[(b*NN+i)*DD + tid] + be1l[tid];   // tb
        sWt[1152+tid]  = We1l[256*DD + tid];                    // wd
    }
    float mi = mask[b*NN + i];
    // geometry for all 320 j, frac computed inline from g_x
    {
        const float* ic = g_invC + b*9;
        float i0=ic[0],i1=ic[1],i2=ic[2],i3=ic[3],i4=ic[4],i5=ic[5],i6=ic[6],i7=ic[7],i8=ic[8];
        float xi0=g_x[(b*NN+i)*3+0], xi1=g_x[(b*NN+i)*3+1], xi2=g_x[(b*NN+i)*3+2];
        float fi0 = xi0*i0 + xi1*i3 + xi2*i6;
        float fi1 = xi0*i1 + xi1*i4 + xi2*i7;
        float fi2 = xi0*i2 + xi1*i5 + xi2*i8;
        float c0=cell[b*9+0],c1=cell[b*9+1],c2=cell[b*9+2];
        float c3=cell[b*9+3],c4=cell[b*9+4],c5=cell[b*9+5];
        float c6=cell[b*9+6],c7=cell[b*9+7],c8=cell[b*9+8];
        for (int j = tid; j < NN; j += 256){
            float xj0=g_x[(b*NN+j)*3+0], xj1=g_x[(b*NN+j)*3+1], xj2=g_x[(b*NN+j)*3+2];
            float f0 = xj0*i0 + xj1*i3 + xj2*i6 - fi0;
            float f1 = xj0*i1 + xj1*i4 + xj2*i7 - fi1;
            float f2 = xj0*i2 + xj1*i5 + xj2*i8 - fi2;
            f0 -= rintf(f0); f1 -= rintf(f1); f2 -= rintf(f2);
            float rx = f0*c0 + f1*c3 + f2*c6;
            float ry = f0*c1 + f1*c4 + f2*c7;
            float rz = f0*c2 + f1*c5 + f2*c8;
            float dij = sqrtf(rx*rx + ry*ry + rz*rz + 1e-12f);
            float pm = mi * mask[b*NN + j];
            sDij[j] = dij*pm + (1.f - pm)*1e6f;
            sRx[j] = rx*pm; sRy[j] = ry*pm; sRz[j] = rz*pm;
            sPm[j] = pm;
        }
    }
    __syncthreads();

    float be3v = be3l[0], bp2v = bp2l[0];

    // warp tiling: all 8 warps share the 16-row tile, each owns 16 N-cols
    int wn = wid * 16;

    uint32_t sM1a = smem_u32(base + OFF_M1);
    uint32_t sBa  = smem_u32(sB);
    uint32_t aOff = (uint32_t)(((lane & 15)*KS + (lane >> 4)*8) * 2);
    int lr = lane & 7;
    int lb3 = (lane >> 3) & 1;
    int lb4 = lane >> 4;
    uint32_t bBase = sBa + (uint32_t)(((wn + lb4*8 + lr)*KS + lb3*8) * 2);

    // m1 thread mapping: row = tid>>4 (0..15), k0 = (tid&15)*8
    int m1row = tid >> 4;
    int m1k0 = (tid & 15) * 8;
    const float4* tb4 = (const float4*)(sWt + 1024 + m1k0);
    const float4* wd4 = (const float4*)(sWt + 1152 + m1k0);

    // ---- prologue: m1 tile 0 into buffer 0 ----
    {
        float dij = sDij[m1row];
        const float4* bv = (const float4*)(g_Bv + (size_t)(b*NN + m1row)*DD + m1k0);
        float4 bva = bv[0], bvb = bv[1];
        float4 tba = tb4[0], tbb = tb4[1];
        float4 wda = wd4[0], wdb = wd4[1];
        uint4 pk;
        pk.x = bf16x2_pack(silu_f(tba.x + bva.x + dij*wda.x), silu_f(tba.y + bva.y + dij*wda.y));
        pk.y = bf16x2_pack(silu_f(tba.z + bva.z + dij*wda.z), silu_f(tba.w + bva.w + dij*wda.w));
        pk.z = bf16x2_pack(silu_f(tbb.x + bvb.x + dij*wdb.x), silu_f(tbb.y + bvb.y + dij*wdb.y));
        pk.w = bf16x2_pack(silu_f(tbb.z + bvb.z + dij*wdb.z), silu_f(tbb.w + bvb.w + dij*wdb.w));
        *(uint4*)(base + OFF_M1 + m1row*(KS*2) + m1k0*2) = pk;
    }
    __syncthreads();

    for (int T = 0; T < NT; T++){
        int buf = T & 1;

        // ---- prefetch g_Bv for tile T+1 into registers BEFORE GEMM ----
        float4 nbva, nbvb;
        float ndij = 0.f;
        if (T + 1 < NT){
            int jg = (T+1)*TROWS + m1row;
            ndij = sDij[jg];
            const float4* bv = (const float4*)(g_Bv + (size_t)(b*NN + jg)*DD + m1k0);
            nbva = bv[0];
            nbvb = bv[1];
        }

        // ---- GEMM(T): warp computes C[16 j][16 t] from buf ----
        float acc[2][4];
        #pragma unroll
        for (int s = 0; s < 2; s++)
            #pragma unroll
            for (int c = 0; c < 4; c++) acc[s][c] = 0.f;

        uint32_t aA = sM1a + buf*M1BUF + aOff;
        uint32_t bA = bBase;
        #pragma unroll
        for (int ks = 0; ks < 8; ks++){
            uint32_t a0,a1,a2,a3, b0,b1,b2,b3;
            ldsm4(a0,a1,a2,a3, aA);
            ldsm4(b0,b1,b2,b3, bA);
            mma16816(acc[0], a0,a1,a2,a3, b0,b1);
            mma16816(acc[1], a0,a1,a2,a3, b2,b3);
            aA += 32; bA += 32;
        }

        // ---- m1(T+1) into other buffer from prefetched registers ----
        if (T + 1 < NT){
            float4 tba = tb4[0], tbb = tb4[1];
            float4 wda = wd4[0], wdb = wd4[1];
            uint4 pk;
            pk.x = bf16x2_pack(silu_f(tba.x + nbva.x + ndij*wda.x), silu_f(tba.y + nbva.y + ndij*wda.y));
            pk.y = bf16x2_pack(silu_f(tba.z + nbva.z + ndij*wda.z), silu_f(tba.w + nbva.w + ndij*wda.w));
            pk.z = bf16x2_pack(silu_f(tbb.x + nbvb.x + ndij*wdb.x), silu_f(tbb.y + nbvb.y + ndij*wdb.y));
            pk.w = bf16x2_pack(silu_f(tbb.z + nbvb.z + ndij*wdb.z), silu_f(tbb.w + nbvb.w + ndij*wdb.w));
            *(uint4*)(base + OFF_M1 + (buf^1)*M1BUF + m1row*(KS*2) + m1k0*2) = pk;
        }

        // ---- epilogue(T): m2 = silu(C + be2), dot with we3 over this warp's 16 cols ----
        {
            int colq = wn + (lane & 3)*2;
            float d0 = 0.f, d1 = 0.f;
            #pragma unroll
            for (int s = 0; s < 2; s++){
                int col = colq + s*8;
                float w0 = sWt[128+col], w1 = sWt[128+col+1];
                float e0 = sWt[col], e1 = sWt[col+1];
                d0 += silu_f(acc[s][0] + e0)*w0 + silu_f(acc[s][1] + e1)*w1;
                d1 += silu_f(acc[s][2] + e0)*w0 + silu_f(acc[s][3] + e1)*w1;
            }
            d0 += __shfl_xor_sync(0xffffffffu, d0, 1);
            d0 += __shfl_xor_sync(0xffffffffu, d0, 2);
            d1 += __shfl_xor_sync(0xffffffffu, d1, 1);
            d1 += __shfl_xor_sync(0xffffffffu, d1, 2);
            if ((lane & 3) == 0){
                int row = lane >> 2;   // 0..7
                sPart[buf*128 + wid*16 + row]     = d0;
                sPart[buf*128 + wid*16 + row + 8] = d1;
            }
        }
        __syncthreads();   // the ONE barrier per tile

        // ---- fold sMij(T) (tid<16) — overlaps next iteration's GEMM for other threads ----
        if (tid < 16){
            int j = T*TROWS + tid;
            float s = 0.f;
            #pragma unroll
            for (int w = 0; w < 8; w++) s += sPart[buf*128 + w*16 + tid];
            sMij[j] = (s + be3v) * sPm[j];
        }
    }
    __syncthreads();

    // -------- balanced warp-split tail: Sacc (warps 0-3) vs phi (warps 4-7) --------
    if (wid < 4){
        int t = tid;   // 0..127
        float wm1 = sWt[256+t], bm1v = sWt[384+t];
        float s = 0.f;
        #pragma unroll 4
        for (int j = 0; j < NN; j++)
            s += silu_f(fmaf(sMij[j], wm1, bm1v));
        g_S[(b*NN+i)*DD + t] = s;
    } else {
        int p = tid - 128;
        const float4* phi4 = (const float4*)(sWt + 512);
        float dx0=0.f,dx1=0.f,dx2=0.f, sr0=0.f,sr1=0.f,sr2=0.f;
        #pragma unroll
        for (int rep = 0; rep < 3; rep++){
            int j = p + rep*128;
            if (j < NN){
                float mij = sMij[j];
                float inner = 0.f;
                #pragma unroll 4
                for (int t2 = 0; t2 < DD; t2++){
                    float4 w = phi4[t2];
                    inner += silu_f(fmaf(mij, w.x, w.y)) * w.z;
                }
                dx0 += sRx[j]*inner; dx1 += sRy[j]*inner; dx2 += sRz[j]*inner;
                sr0 += sRx[j]; sr1 += sRy[j]; sr2 += sRz[j];
            }
        }
        float v[6] = {dx0,dx1,dx2,sr0,sr1,sr2};
        #pragma unroll
        for (int c = 0; c < 6; c++)
            #pragma unroll
            for (int o = 16; o; o >>= 1) v[c] += __shfl_xor_sync(0xffffffffu, v[c], o);
        if (lane == 0){
            #pragma unroll
            for (int c = 0; c < 6; c++) sRed[(wid-4)*6 + c] = v[c];
        }
    }
    __syncthreads();
    if (tid == 0){
        float a0=0,a1=0,a2=0,s0=0,s1=0,s2=0;
        #pragma unroll
        for (int w = 0; w < 4; w++){
            a0 += sRed[w*6+0]; a1 += sRed[w*6+1]; a2 += sRed[w*6+2];
            s0 += sRed[w*6+3]; s1 += sRed[w*6+4]; s2 += sRed[w*6+5];
        }
        g_x[(b*NN+i)*3+0] += a0 + bp2v*s0;
        g_x[(b*NN+i)*3+1] += a1 + bp2v*s1;
        g_x[(b*NN+i)*3+2] += a2 + bp2v*s2;
    }
}

// ---------------- blocked node update: S@Wm2 -> GRU, 8 nodes/block ----------------
__global__ void __launch_bounds__(128) k_node(
    const float* __restrict__ Wm2l, const float* __restrict__ bm2l,
    const float* __restrict__ Wihl, const float* __restrict__ Whhl,
    const float* __restrict__ bihl, const float* __restrict__ bhhl,
    const float* __restrict__ mask)
{
    __shared__ float sS[8*128], shh[8*128], smn[8*128], sG[8*384], sHn[8*128];
    int g0 = blockIdx.x*8, tid = threadIdx.x;

    #pragma unroll
    for (int q = 0; q < 8; q++){
        sS[q*128+tid]  = g_S[(g0+q)*DD + tid];
        shh[q*128+tid] = g_h[(g0+q)*DD + tid];
    }
    __syncthreads();

    // mn = S @ Wm2 + NN*bm2 (col = tid)
    {
        float acc[8];
        float bm = (float)NN * bm2l[tid];
        #pragma unroll
        for (int q = 0; q < 8; q++) acc[q] = bm;
        for (int k = 0; k < DD; k += 4){
            float4 w4;
            w4.x = Wm2l[(k+0)*DD + tid];
            w4.y = Wm2l[(k+1)*DD + tid];
            w4.z = Wm2l[(k+2)*DD + tid];
            w4.w = Wm2l[(k+3)*DD + tid];
            #pragma unroll
            for (int q = 0; q < 8; q++){
                float4 s4 = *(const float4*)(sS + q*128 + k);
                acc[q] += s4.x*w4.x + s4.y*w4.y + s4.z*w4.z + s4.w*w4.w;
            }
        }
        #pragma unroll
        for (int q = 0; q < 8; q++) smn[q*128+tid] = acc[q];
    }
    __syncthreads();

    // gates: thread owns cols tid, tid+128, tid+256
    for (int c3 = 0; c3 < 3; c3++){
        int col = tid + c3*128;
        float gi[8], gh[8];
        float bi = bihl[col], bh = bhhl[col];
        #pragma unroll
        for (int q = 0; q < 8; q++){ gi[q] = bi; gh[q] = bh; }
        for (int k = 0; k < DD; k += 4){
            #pragma unroll
            for (int kk = 0; kk < 4; kk++){
                float wi = Wihl[(k+kk)*384 + col];
                float wh = Whhl[(k+kk)*384 + col];
                #pragma unroll
                for (int q = 0; q < 8; q++){
                    gi[q] = fmaf(smn[q*128 + k+kk], wi, gi[q]);
                    gh[q] = fmaf(shh[q*128 + k+kk], wh, gh[q]);
                }
            }
        }
        if (c3 < 2){
            #pragma unroll
            for (int q = 0; q < 8; q++) sG[q*384+col] = gi[q] + gh[q];
        } else {
            #pragma unroll
            for (int q = 0; q < 8; q++){ sG[q*384+col] = gi[q]; sHn[q*128+tid] = gh[q]; }
        }
    }
    __syncthreads();

    // finalize h
    #pragma unroll
    for (int q = 0; q < 8; q++){
        float r = sigm_f(sG[q*384 + tid]);
        float z = sigm_f(sG[q*384 + 128 + tid]);
        float n = tanh_ap(sG[q*384 + 256 + tid] + r*sHn[q*128+tid]);
        float hn = (1.f - z)*n + z*shh[q*128+tid];
        g_h[(g0+q)*DD + tid] = hn * mask[g0+q];
    }
}

// ---------------- pool + head ----------------
__global__ void k_pool(const float* __restrict__ mask,
                       const float* __restrict__ Wc1, const float* __restrict__ bc1,
                       const float* __restrict__ Wc2, const float* __restrict__ bc2,
                       const float* __restrict__ Wc3, const float* __restrict__ bc3,
                       float* __restrict__ out){
    int b = blockIdx.x, tid = threadIdx.x;
    __shared__ float feat[DD], o1[DD], o2[64];
    float s = 0.f, ms = 0.f;
    for (int i = 0; i < NN; i++){
        float mk = mask[b*NN + i];
        s  += g_h[(b*NN+i)*DD + tid]*mk;
        ms += mk;
    }
    feat[tid] = s / fmaxf(ms, 1.f);
    __syncthreads();
    float t = bc1[tid];
    #pragma unroll 8
    for (int k = 0; k < DD; k++) t += feat[k]*Wc1[k*DD + tid];
    o1[tid] = silu_f(t);
    __syncthreads();
    if (tid < 64){
        float t2 = bc2[tid];
        #pragma unroll 8
        for (int k = 0; k < DD; k++) t2 += o1[k]*Wc2[k*64 + tid];
        o2[tid] = silu_f(t2);
    }
    __syncthreads();
    if (tid < 6){
        float t3 = bc3[tid];
        #pragma unroll
        for (int k = 0; k < 64; k++) t3 += o2[k]*Wc3[k*6 + tid];
        float r;
        if (tid < 3){
            r = (t3 > 20.f) ? t3 : log1pf(expf(t3));
        } else {
            r = (1.f / (1.f + expf(-t3))) * 180.f;
        }
        out[b*6 + tid] = r;
    }
}

extern "C" void kernel_launch(void* const* d_in, const int* in_sizes, int n_in,
                              void* d_out, int out_size){
    const float* pos   = (const float*)d_in[0];
    const float* oneh  = (const float*)d_in[1];
    const float* mask  = (const float*)d_in[2];
    const float* cell  = (const float*)d_in[3];
    const float* W_in1 = (const float*)d_in[4];
    const float* b_in1 = (const float*)d_in[5];
    const float* W_in2 = (const float*)d_in[6];
    const float* b_in2 = (const float*)d_in[7];
    const float* We1   = (const float*)d_in[8];
    const float* be1   = (const float*)d_in[9];
    const float* We2   = (const float*)d_in[10];
    const float* be2   = (const float*)d_in[11];
    const float* We3   = (const float*)d_in[12];
    const float* be3   = (const float*)d_in[13];
    const float* Wm1   = (const float*)d_in[14];
    const float* bm1   = (const float*)d_in[15];
    const float* Wm2   = (const float*)d_in[16];
    const float* bm2   = (const float*)d_in[17];
    const float* Wp1   = (const float*)d_in[18];
    const float* bp1   = (const float*)d_in[19];
    const float* Wp2   = (const float*)d_in[20];
    const float* bp2   = (const float*)d_in[21];
    const float* W_ih  = (const float*)d_in[22];
    const float* W_hh  = (const float*)d_in[23];
    const float* b_ih  = (const float*)d_in[24];
    const float* b_hh  = (const float*)d_in[25];
    const float* Wc1   = (const float*)d_in[26];
    const float* bc1   = (const float*)d_in[27];
    const float* Wc2   = (const float*)d_in[28];
    const float* bc2   = (const float*)d_in[29];
    const float* Wc3   = (const float*)d_in[30];
    const float* bc3   = (const float*)d_in[31];
    float* out = (float*)d_out;

    cudaFuncSetAttribute(k_edge, cudaFuncAttributeMaxDynamicSharedMemorySize, SMEMB);

    k_inv<<<1, 32>>>(cell);
    k_init<<<(BB*NN*3 + 127)/128, 128>>>(pos);
    k_prepW<<<LL*8, 256>>>(We2);
    k_embed<<<dim3(NN, BB), 128>>>(pos, oneh, W_in1, b_in1, W_in2, b_in2);

    for (int l = 0; l < LL; l++){
        k_A8<<<BB*NN/8, 128>>>(We1 + l*257*DD);
        k_edge<<<dim3(NN, BB), 256, SMEMB>>>(We1 + l*257*DD, be1 + l*DD,
                                    be2 + l*DD, We3 + l*DD, be3 + l,
                                    Wm1 + l*DD, bm1 + l*DD,
                                    Wp1 + l*DD, bp1 + l*DD,
                                    Wp2 + l*DD, bp2 + l,
                                    cell, mask, l);
        k_node<<<BB*NN/8, 128>>>(Wm2 + l*DD*DD, bm2 + l*DD,
                                 W_ih + l*DD*3*DD, W_hh + l*DD*3*DD,
                                 b_ih + l*3*DD,    b_hh + l*3*DD, mask);
    }

    k_pool<<<BB, 128>>>(mask, Wc1, bc1, Wc2, bc2, Wc3, bc3, out);
}

// round 13
// speedup vs baseline: 1.2816x; 1.0532x over previous
#include <cuda_runtime.h>
#include <cuda_bf16.h>
#include <math.h>
#include <stdint.h>

#define BB 2
#define NN 320
#define DD 128
#define LL 4
#define OHH 100
#define KS 136   // smem row stride in bf16 elems (272 bytes)
#define JH 160   // j's per half-block

// ---------------- device scratch (no allocs allowed) ----------------
__device__ float g_h[BB*NN*DD];
__device__ float g_x[BB*NN*3];
__device__ float g_A[BB*NN*DD];
__device__ float g_Bv[BB*NN*DD];
__device__ float g_Sp[2*BB*NN*DD];     // per-half partial S
__device__ float g_dxp[2*BB*NN*3];     // per-half partial (dx + bp2*sum_r)
__device__ float g_invC[BB*9];
__device__ unsigned short g_We2bf[LL*DD*DD];   // per-layer B[n][k] = We2[k][n] in bf16

// ---------------- math helpers ----------------
__device__ __forceinline__ float tanh_ap(float x){
    float t; asm("tanh.approx.f32 %0, %1;" : "=f"(t) : "f"(x)); return t;
}
__device__ __forceinline__ float silu_f(float x){
    return 0.5f*x*(1.f + tanh_ap(0.5f*x));
}
__device__ __forceinline__ float sigm_f(float x){
    return 0.5f*(1.f + tanh_ap(0.5f*x));
}
__device__ __forceinline__ uint32_t bf16x2_pack(float lo, float hi){
    uint32_t r;
    asm("cvt.rn.bf16x2.f32 %0, %1, %2;" : "=r"(r) : "f"(hi), "f"(lo));  // first src -> high half
    return r;
}

__device__ __forceinline__ uint32_t smem_u32(const void* p){
    uint32_t a;
    asm("{ .reg .u64 t; cvta.to.shared.u64 t, %1; cvt.u32.u64 %0, t; }" : "=r"(a) : "l"(p));
    return a;
}
__device__ __forceinline__ void ldsm4(uint32_t& r0, uint32_t& r1, uint32_t& r2, uint32_t& r3, uint32_t a){
    asm volatile("ldmatrix.sync.aligned.m8n8.x4.shared.b16 {%0,%1,%2,%3}, [%4];"
                 : "=r"(r0),"=r"(r1),"=r"(r2),"=r"(r3) : "r"(a));
}
__device__ __forceinline__ void mma16816(float* c, uint32_t a0,uint32_t a1,uint32_t a2,uint32_t a3,
                                         uint32_t b0,uint32_t b1){
    asm volatile("mma.sync.aligned.m16n8k16.row.col.f32.bf16.bf16.f32 "
        "{%0,%1,%2,%3}, {%4,%5,%6,%7}, {%8,%9}, {%0,%1,%2,%3};"
        : "+f"(c[0]),"+f"(c[1]),"+f"(c[2]),"+f"(c[3])
        : "r"(a0),"r"(a1),"r"(a2),"r"(a3),"r"(b0),"r"(b1));
}

// ---------------- small kernels ----------------
__global__ void k_inv(const float* __restrict__ cell){
    int b = threadIdx.x;
    if (b >= BB) return;
    const float* c = cell + b*9;
    float a00=c[0],a01=c[1],a02=c[2];
    float a10=c[3],a11=c[4],a12=c[5];
    float a20=c[6],a21=c[7],a22=c[8];
    float C00 =  a11*a22 - a12*a21;
    float C01 = -(a10*a22 - a12*a20);
    float C02 =  a10*a21 - a11*a20;
    float C10 = -(a01*a22 - a02*a21);
    float C11 =  a00*a22 - a02*a20;
    float C12 = -(a00*a21 - a01*a20);
    float C20 =  a01*a12 - a02*a11;
    float C21 = -(a00*a12 - a02*a10);
    float C22 =  a00*a11 - a01*a10;
    float det = a00*C00 + a01*C01 + a02*C02;
    float id = 1.f/det;
    float* o = g_invC + b*9;
    o[0]=C00*id; o[1]=C10*id; o[2]=C20*id;
    o[3]=C01*id; o[4]=C11*id; o[5]=C21*id;
    o[6]=C02*id; o[7]=C12*id; o[8]=C22*id;
}

__global__ void k_init(const float* __restrict__ pos){
    int t = blockIdx.x*blockDim.x + threadIdx.x;
    if (t < BB*NN*3) g_x[t] = pos[t];
}

// prepare We2^T bf16: B[n][k] = We2[k][n];  grid = LL*8 blocks
__global__ void k_prepW(const float* __restrict__ We2){
    int l = blockIdx.x >> 3, part = blockIdx.x & 7, tid = threadIdx.x;
    const float* W = We2 + l*DD*DD;
    unsigned short* dst = g_We2bf + l*DD*DD;
    int e0 = part*2048;
    for (int q = 0; q < 8; q++){
        int e = e0 + q*256 + tid;
        int n = e >> 7, k = e & 127;
        dst[e] = __bfloat16_as_ushort(__float2bfloat16_rn(W[k*DD + n]));
    }
}

// per-atom input embedding (640 blocks — measured best shape)
__global__ void k_embed(const float* __restrict__ pos, const float* __restrict__ oneh,
                        const float* __restrict__ W1, const float* __restrict__ b1,
                        const float* __restrict__ W2, const float* __restrict__ b2){
    int i = blockIdx.x, b = blockIdx.y, tid = threadIdx.x;
    __shared__ float sin_[OHH+3];
    __shared__ float sh1[DD];
    if (tid < OHH+3){
        sin_[tid] = (tid < 3) ? pos[(b*NN+i)*3 + tid] : oneh[(b*NN+i)*OHH + (tid-3)];
    }
    __syncthreads();
    float t = b1[tid];
    #pragma unroll 8
    for (int k = 0; k < OHH+3; k++) t += sin_[k]*W1[k*DD + tid];
    sh1[tid] = silu_f(t);
    __syncthreads();
    float t2 = b2[tid];
    #pragma unroll 8
    for (int k = 0; k < DD; k++) t2 += sh1[k]*W2[k*DD + tid];
    g_h[(b*NN+i)*DD + tid] = t2;
}

// blocked A/Bv: 8 atoms/block
__global__ void __launch_bounds__(128) k_A8(const float* __restrict__ We1l){
    __shared__ float sh[8*128];
    int g0 = blockIdx.x*8, tid = threadIdx.x;
    #pragma unroll
    for (int q = 0; q < 8; q++) sh[q*128+tid] = g_h[(g0+q)*DD + tid];
    __syncthreads();
    float a[8], bv[8];
    #pragma unroll
    for (int q = 0; q < 8; q++){ a[q] = 0.f; bv[q] = 0.f; }
    for (int k = 0; k < DD; k += 4){
        float w1a = We1l[(k+0)*DD + tid], w2a = We1l[(DD+k+0)*DD + tid];
        float w1b = We1l[(k+1)*DD + tid], w2b = We1l[(DD+k+1)*DD + tid];
        float w1c = We1l[(k+2)*DD + tid], w2c = We1l[(DD+k+2)*DD + tid];
        float w1d = We1l[(k+3)*DD + tid], w2d = We1l[(DD+k+3)*DD + tid];
        #pragma unroll
        for (int q = 0; q < 8; q++){
            float4 h4 = *(const float4*)(sh + q*128 + k);
            a[q]  += h4.x*w1a + h4.y*w1b + h4.z*w1c + h4.w*w1d;
            bv[q] += h4.x*w2a + h4.y*w2b + h4.z*w2c + h4.w*w2d;
        }
    }
    #pragma unroll
    for (int q = 0; q < 8; q++){
        g_A[(g0+q)*DD + tid]  = a[q];
        g_Bv[(g0+q)*DD + tid] = bv[q];
    }
}

// ---------------- heavy kernel: per-(b,i,half), pipelined tcore GEMM + messages ----------------
// half-block processes j in [half*160, half*160+160); partials written to g_Sp/g_dxp
// smem byte offsets (16-row j tiles, DOUBLE buffered):
#define TROWS    16
#define NTH      (JH/TROWS)              // 10 tiles per half
#define OFF_B    0                       // bf16 [128][KS]  = 34816
#define OFF_M1   34816                   // 2 x bf16[16][KS] = 8704
#define M1BUF    4352
#define OFF_GEO  43520                   // 5 x 160 floats  = 3200
#define OFF_WT   46720                   // 1280 floats     = 5120
#define OFF_MIJ  51840                   // 160 floats      = 640
#define OFF_PART 52480                   // 2 x 128 floats  = 1024
#define OFF_RED  53504                   // 32 floats       = 128
#define SMEMB    53632

__global__ void __launch_bounds__(256, 4) k_edge(
    const float* __restrict__ We1l, const float* __restrict__ be1l,
    const float* __restrict__ be2l, const float* __restrict__ We3l,
    const float* __restrict__ be3l,
    const float* __restrict__ Wm1l, const float* __restrict__ bm1l,
    const float* __restrict__ Wp1l, const float* __restrict__ bp1l,
    const float* __restrict__ Wp2l, const float* __restrict__ bp2l,
    const float* __restrict__ cell, const float* __restrict__ mask, int layer)
{
    extern __shared__ char base[];
    __nv_bfloat16* sB  = (__nv_bfloat16*)(base + OFF_B);
    float* sDij = (float*)(base + OFF_GEO);       // [160] local j
    float* sRx  = sDij + JH;
    float* sRy  = sRx + JH;
    float* sRz  = sRy + JH;
    float* sPm  = sRz + JH;
    float* sWt  = (float*)(base + OFF_WT);
    float* sMij = (float*)(base + OFF_MIJ);       // [160]
    float* sPart= (float*)(base + OFF_PART);      // [2][128]
    float* sRed = (float*)(base + OFF_RED);

    int i = blockIdx.x, b = blockIdx.y, half = blockIdx.z;
    int j0 = half*JH;
    int tid = threadIdx.x, wid = tid >> 5, lane = tid & 31;

    // stage B[n][k] bf16 into padded smem
    {
        const uint4* src = (const uint4*)(g_We2bf + layer*DD*DD);
        #pragma unroll
        for (int q = 0; q < 8; q++){
            int e = tid + q*256;
            int n = e >> 4, k0 = (e & 15) << 3;
            *(uint4*)(sB + n*KS + k0) = src[e];
        }
    }
    if (tid < 128){
        sWt[tid]       = be2l[tid];
        sWt[128+tid]   = We3l[tid];
        sWt[256+tid]   = Wm1l[tid];
        sWt[384+tid]   = bm1l[tid];
        ((float4*)(sWt+512))[tid] = make_float4(Wp1l[tid], bp1l[tid], Wp2l[tid], 0.f);
        sWt[1024+tid]  = g_A[(b*NN+i)*DD + tid] + be1l[tid];   // tb
        sWt[1152+tid]  = We1l[256*DD + tid];                    // wd
    }
    float mi = mask[b*NN + i];
    // geometry for this half's 160 j, frac computed inline from g_x
    {
        const float* ic = g_invC + b*9;
        float i0=ic[0],i1=ic[1],i2=ic[2],i3=ic[3],i4=ic[4],i5=ic[5],i6=ic[6],i7=ic[7],i8=ic[8];
        float xi0=g_x[(b*NN+i)*3+0], xi1=g_x[(b*NN+i)*3+1], xi2=g_x[(b*NN+i)*3+2];
        float fi0 = xi0*i0 + xi1*i3 + xi2*i6;
        float fi1 = xi0*i1 + xi1*i4 + xi2*i7;
        float fi2 = xi0*i2 + xi1*i5 + xi2*i8;
        float c0=cell[b*9+0],c1=cell[b*9+1],c2=cell[b*9+2];
        float c3=cell[b*9+3],c4=cell[b*9+4],c5=cell[b*9+5];
        float c6=cell[b*9+6],c7=cell[b*9+7],c8=cell[b*9+8];
        for (int jl = tid; jl < JH; jl += 256){
            int j = j0 + jl;
            float xj0=g_x[(b*NN+j)*3+0], xj1=g_x[(b*NN+j)*3+1], xj2=g_x[(b*NN+j)*3+2];
            float f0 = xj0*i0 + xj1*i3 + xj2*i6 - fi0;
            float f1 = xj0*i1 + xj1*i4 + xj2*i7 - fi1;
            float f2 = xj0*i2 + xj1*i5 + xj2*i8 - fi2;
            f0 -= rintf(f0); f1 -= rintf(f1); f2 -= rintf(f2);
            float rx = f0*c0 + f1*c3 + f2*c6;
            float ry = f0*c1 + f1*c4 + f2*c7;
            float rz = f0*c2 + f1*c5 + f2*c8;
            float dij = sqrtf(rx*rx + ry*ry + rz*rz + 1e-12f);
            float pm = mi * mask[b*NN + j];
            sDij[jl] = dij*pm + (1.f - pm)*1e6f;
            sRx[jl] = rx*pm; sRy[jl] = ry*pm; sRz[jl] = rz*pm;
            sPm[jl] = pm;
        }
    }
    __syncthreads();

    float be3v = be3l[0], bp2v = bp2l[0];

    // warp tiling: all 8 warps share the 16-row tile, each owns 16 N-cols
    int wn = wid * 16;

    uint32_t sM1a = smem_u32(base + OFF_M1);
    uint32_t sBa  = smem_u32(sB);
    uint32_t aOff = (uint32_t)(((lane & 15)*KS + (lane >> 4)*8) * 2);
    int lr = lane & 7;
    int lb3 = (lane >> 3) & 1;
    int lb4 = lane >> 4;
    uint32_t bBase = sBa + (uint32_t)(((wn + lb4*8 + lr)*KS + lb3*8) * 2);

    // m1 thread mapping: row = tid>>4 (0..15), k0 = (tid&15)*8
    int m1row = tid >> 4;
    int m1k0 = (tid & 15) * 8;
    const float4* tb4 = (const float4*)(sWt + 1024 + m1k0);
    const float4* wd4 = (const float4*)(sWt + 1152 + m1k0);

    // ---- prologue: m1 tile 0 into buffer 0 ----
    {
        float dij = sDij[m1row];
        const float4* bv = (const float4*)(g_Bv + (size_t)(b*NN + j0 + m1row)*DD + m1k0);
        float4 bva = bv[0], bvb = bv[1];
        float4 tba = tb4[0], tbb = tb4[1];
        float4 wda = wd4[0], wdb = wd4[1];
        uint4 pk;
        pk.x = bf16x2_pack(silu_f(tba.x + bva.x + dij*wda.x), silu_f(tba.y + bva.y + dij*wda.y));
        pk.y = bf16x2_pack(silu_f(tba.z + bva.z + dij*wda.z), silu_f(tba.w + bva.w + dij*wda.w));
        pk.z = bf16x2_pack(silu_f(tbb.x + bvb.x + dij*wdb.x), silu_f(tbb.y + bvb.y + dij*wdb.y));
        pk.w = bf16x2_pack(silu_f(tbb.z + bvb.z + dij*wdb.z), silu_f(tbb.w + bvb.w + dij*wdb.w));
        *(uint4*)(base + OFF_M1 + m1row*(KS*2) + m1k0*2) = pk;
    }
    __syncthreads();

    for (int T = 0; T < NTH; T++){
        int buf = T & 1;

        // ---- prefetch g_Bv for tile T+1 into registers BEFORE GEMM ----
        float4 nbva, nbvb;
        float ndij = 0.f;
        if (T + 1 < NTH){
            int jl = (T+1)*TROWS + m1row;
            ndij = sDij[jl];
            const float4* bv = (const float4*)(g_Bv + (size_t)(b*NN + j0 + jl)*DD + m1k0);
            nbva = bv[0];
            nbvb = bv[1];
        }

        // ---- GEMM(T): warp computes C[16 j][16 t] from buf ----
        float acc[2][4];
        #pragma unroll
        for (int s = 0; s < 2; s++)
            #pragma unroll
            for (int c = 0; c < 4; c++) acc[s][c] = 0.f;

        uint32_t aA = sM1a + buf*M1BUF + aOff;
        uint32_t bA = bBase;
        #pragma unroll
        for (int ks = 0; ks < 8; ks++){
            uint32_t a0,a1,a2,a3, b0,b1,b2,b3;
            ldsm4(a0,a1,a2,a3, aA);
            ldsm4(b0,b1,b2,b3, bA);
            mma16816(acc[0], a0,a1,a2,a3, b0,b1);
            mma16816(acc[1], a0,a1,a2,a3, b2,b3);
            aA += 32; bA += 32;
        }

        // ---- m1(T+1) into other buffer from prefetched registers ----
        if (T + 1 < NTH){
            float4 tba = tb4[0], tbb = tb4[1];
            float4 wda = wd4[0], wdb = wd4[1];
            uint4 pk;
            pk.x = bf16x2_pack(silu_f(tba.x + nbva.x + ndij*wda.x), silu_f(tba.y + nbva.y + ndij*wda.y));
            pk.y = bf16x2_pack(silu_f(tba.z + nbva.z + ndij*wda.z), silu_f(tba.w + nbva.w + ndij*wda.w));
            pk.z = bf16x2_pack(silu_f(tbb.x + nbvb.x + ndij*wdb.x), silu_f(tbb.y + nbvb.y + ndij*wdb.y));
            pk.w = bf16x2_pack(silu_f(tbb.z + nbvb.z + ndij*wdb.z), silu_f(tbb.w + nbvb.w + ndij*wdb.w));
            *(uint4*)(base + OFF_M1 + (buf^1)*M1BUF + m1row*(KS*2) + m1k0*2) = pk;
        }

        // ---- epilogue(T): m2 = silu(C + be2), dot with we3 over this warp's 16 cols ----
        {
            int colq = wn + (lane & 3)*2;
            float d0 = 0.f, d1 = 0.f;
            #pragma unroll
            for (int s = 0; s < 2; s++){
                int col = colq + s*8;
                float w0 = sWt[128+col], w1 = sWt[128+col+1];
                float e0 = sWt[col], e1 = sWt[col+1];
                d0 += silu_f(acc[s][0] + e0)*w0 + silu_f(acc[s][1] + e1)*w1;
                d1 += silu_f(acc[s][2] + e0)*w0 + silu_f(acc[s][3] + e1)*w1;
            }
            d0 += __shfl_xor_sync(0xffffffffu, d0, 1);
            d0 += __shfl_xor_sync(0xffffffffu, d0, 2);
            d1 += __shfl_xor_sync(0xffffffffu, d1, 1);
            d1 += __shfl_xor_sync(0xffffffffu, d1, 2);
            if ((lane & 3) == 0){
                int row = lane >> 2;   // 0..7
                sPart[buf*128 + wid*16 + row]     = d0;
                sPart[buf*128 + wid*16 + row + 8] = d1;
            }
        }
        __syncthreads();   // the ONE barrier per tile

        // ---- fold sMij(T) (tid<16) — overlaps next iteration's GEMM for other threads ----
        if (tid < 16){
            int jl = T*TROWS + tid;
            float s = 0.f;
            #pragma unroll
            for (int w = 0; w < 8; w++) s += sPart[buf*128 + w*16 + tid];
            sMij[jl] = (s + be3v) * sPm[jl];
        }
    }
    __syncthreads();

    // -------- balanced warp-split tail over 160 local j's --------
    if (wid < 4){
        int t = tid;   // 0..127
        float wm1 = sWt[256+t], bm1v = sWt[384+t];
        float s = 0.f;
        #pragma unroll 4
        for (int jl = 0; jl < JH; jl++)
            s += silu_f(fmaf(sMij[jl], wm1, bm1v));
        g_Sp[half*(BB*NN*DD) + (b*NN+i)*DD + t] = s;
    } else {
        int p = tid - 128;
        const float4* phi4 = (const float4*)(sWt + 512);
        float dx0=0.f,dx1=0.f,dx2=0.f, sr0=0.f,sr1=0.f,sr2=0.f;
        #pragma unroll
        for (int rep = 0; rep < 2; rep++){
            int jl = p + rep*128;
            if (jl < JH){
                float mij = sMij[jl];
                float inner = 0.f;
                #pragma unroll 4
                for (int t2 = 0; t2 < DD; t2++){
                    float4 w = phi4[t2];
                    inner += silu_f(fmaf(mij, w.x, w.y)) * w.z;
                }
                dx0 += sRx[jl]*inner; dx1 += sRy[jl]*inner; dx2 += sRz[jl]*inner;
                sr0 += sRx[jl]; sr1 += sRy[jl]; sr2 += sRz[jl];
            }
        }
        float v[6] = {dx0,dx1,dx2,sr0,sr1,sr2};
        #pragma unroll
        for (int c = 0; c < 6; c++)
            #pragma unroll
            for (int o = 16; o; o >>= 1) v[c] += __shfl_xor_sync(0xffffffffu, v[c], o);
        if (lane == 0){
            #pragma unroll
            for (int c = 0; c < 6; c++) sRed[(wid-4)*6 + c] = v[c];
        }
    }
    __syncthreads();
    if (tid == 0){
        float a0=0,a1=0,a2=0,s0=0,s1=0,s2=0;
        #pragma unroll
        for (int w = 0; w < 4; w++){
            a0 += sRed[w*6+0]; a1 += sRed[w*6+1]; a2 += sRed[w*6+2];
            s0 += sRed[w*6+3]; s1 += sRed[w*6+4]; s2 += sRed[w*6+5];
        }
        int idx = (b*NN+i)*3;
        g_dxp[half*(BB*NN*3) + idx + 0] = a0 + bp2v*s0;
        g_dxp[half*(BB*NN*3) + idx + 1] = a1 + bp2v*s1;
        g_dxp[half*(BB*NN*3) + idx + 2] = a2 + bp2v*s2;
    }
}

// ---------------- blocked node update: fold halves, S@Wm2 -> GRU, x update; 8 nodes/block ----------------
__global__ void __launch_bounds__(128) k_node(
    const float* __restrict__ Wm2l, const float* __restrict__ bm2l,
    const float* __restrict__ Wihl, const float* __restrict__ Whhl,
    const float* __restrict__ bihl, const float* __restrict__ bhhl,
    const float* __restrict__ mask)
{
    __shared__ float sS[8*128], shh[8*128], smn[8*128], sG[8*384], sHn[8*128];
    int g0 = blockIdx.x*8, tid = threadIdx.x;

    // fold the two halves of S; also update x from dx partials
    #pragma unroll
    for (int q = 0; q < 8; q++){
        int idx = (g0+q)*DD + tid;
        sS[q*128+tid]  = g_Sp[idx] + g_Sp[BB*NN*DD + idx];
        shh[q*128+tid] = g_h[idx];
    }
    if (tid < 24){
        int q = tid / 3, c = tid % 3;
        int idx = (g0+q)*3 + c;
        g_x[idx] += g_dxp[idx] + g_dxp[BB*NN*3 + idx];
    }
    __syncthreads();

    // mn = S @ Wm2 + NN*bm2 (col = tid)
    {
        float acc[8];
        float bm = (float)NN * bm2l[tid];
        #pragma unroll
        for (int q = 0; q < 8; q++) acc[q] = bm;
        for (int k = 0; k < DD; k += 4){
            float4 w4;
            w4.x = Wm2l[(k+0)*DD + tid];
            w4.y = Wm2l[(k+1)*DD + tid];
            w4.z = Wm2l[(k+2)*DD + tid];
            w4.w = Wm2l[(k+3)*DD + tid];
            #pragma unroll
            for (int q = 0; q < 8; q++){
                float4 s4 = *(const float4*)(sS + q*128 + k);
                acc[q] += s4.x*w4.x + s4.y*w4.y + s4.z*w4.z + s4.w*w4.w;
            }
        }
        #pragma unroll
        for (int q = 0; q < 8; q++) smn[q*128+tid] = acc[q];
    }
    __syncthreads();

    // gates: thread owns cols tid, tid+128, tid+256
    for (int c3 = 0; c3 < 3; c3++){
        int col = tid + c3*128;
        float gi[8], gh[8];
        float bi = bihl[col], bh = bhhl[col];
        #pragma unroll
        for (int q = 0; q < 8; q++){ gi[q] = bi; gh[q] = bh; }
        for (int k = 0; k < DD; k += 4){
            #pragma unroll
            for (int kk = 0; kk < 4; kk++){
                float wi = Wihl[(k+kk)*384 + col];
                float wh = Whhl[(k+kk)*384 + col];
                #pragma unroll
                for (int q = 0; q < 8; q++){
                    gi[q] = fmaf(smn[q*128 + k+kk], wi, gi[q]);
                    gh[q] = fmaf(shh[q*128 + k+kk], wh, gh[q]);
                }
            }
        }
        if (c3 < 2){
            #pragma unroll
            for (int q = 0; q < 8; q++) sG[q*384+col] = gi[q] + gh[q];
        } else {
            #pragma unroll
            for (int q = 0; q < 8; q++){ sG[q*384+col] = gi[q]; sHn[q*128+tid] = gh[q]; }
        }
    }
    __syncthreads();

    // finalize h
    #pragma unroll
    for (int q = 0; q < 8; q++){
        float r = sigm_f(sG[q*384 + tid]);
        float z = sigm_f(sG[q*384 + 128 + tid]);
        float n = tanh_ap(sG[q*384 + 256 + tid] + r*sHn[q*128+tid]);
        float hn = (1.f - z)*n + z*shh[q*128+tid];
        g_h[(g0+q)*DD + tid] = hn * mask[g0+q];
    }
}

// ---------------- pool + head ----------------
__global__ void k_pool(const float* __restrict__ mask,
                       const float* __restrict__ Wc1, const float* __restrict__ bc1,
                       const float* __restrict__ Wc2, const float* __restrict__ bc2,
                       const float* __restrict__ Wc3, const float* __restrict__ bc3,
                       float* __restrict__ out){
    int b = blockIdx.x, tid = threadIdx.x;
    __shared__ float feat[DD], o1[DD], o2[64];
    float s = 0.f, ms = 0.f;
    for (int i = 0; i < NN; i++){
        float mk = mask[b*NN + i];
        s  += g_h[(b*NN+i)*DD + tid]*mk;
        ms += mk;
    }
    feat[tid] = s / fmaxf(ms, 1.f);
    __syncthreads();
    float t = bc1[tid];
    #pragma unroll 8
    for (int k = 0; k < DD; k++) t += feat[k]*Wc1[k*DD + tid];
    o1[tid] = silu_f(t);
    __syncthreads();
    if (tid < 64){
        float t2 = bc2[tid];
        #pragma unroll 8
        for (int k = 0; k < DD; k++) t2 += o1[k]*Wc2[k*64 + tid];
        o2[tid] = silu_f(t2);
    }
    __syncthreads();
    if (tid < 6){
        float t3 = bc3[tid];
        #pragma unroll
        for (int k = 0; k < 64; k++) t3 += o2[k]*Wc3[k*6 + tid];
        float r;
        if (tid < 3){
            r = (t3 > 20.f) ? t3 : log1pf(expf(t3));
        } else {
            r = (1.f / (1.f + expf(-t3))) * 180.f;
        }
        out[b*6 + tid] = r;
    }
}

extern "C" void kernel_launch(void* const* d_in, const int* in_sizes, int n_in,
                              void* d_out, int out_size){
    const float* pos   = (const float*)d_in[0];
    const float* oneh  = (const float*)d_in[1];
    const float* mask  = (const float*)d_in[2];
    const float* cell  = (const float*)d_in[3];
    const float* W_in1 = (const float*)d_in[4];
    const float* b_in1 = (const float*)d_in[5];
    const float* W_in2 = (const float*)d_in[6];
    const float* b_in2 = (const float*)d_in[7];
    const float* We1   = (const float*)d_in[8];
    const float* be1   = (const float*)d_in[9];
    const float* We2   = (const float*)d_in[10];
    const float* be2   = (const float*)d_in[11];
    const float* We3   = (const float*)d_in[12];
    const float* be3   = (const float*)d_in[13];
    const float* Wm1   = (const float*)d_in[14];
    const float* bm1   = (const float*)d_in[15];
    const float* Wm2   = (const float*)d_in[16];
    const float* bm2   = (const float*)d_in[17];
    const float* Wp1   = (const float*)d_in[18];
    const float* bp1   = (const float*)d_in[19];
    const float* Wp2   = (const float*)d_in[20];
    const float* bp2   = (const float*)d_in[21];
    const float* W_ih  = (const float*)d_in[22];
    const float* W_hh  = (const float*)d_in[23];
    const float* b_ih  = (const float*)d_in[24];
    const float* b_hh  = (const float*)d_in[25];
    const float* Wc1   = (const float*)d_in[26];
    const float* bc1   = (const float*)d_in[27];
    const float* Wc2   = (const float*)d_in[28];
    const float* bc2   = (const float*)d_in[29];
    const float* Wc3   = (const float*)d_in[30];
    const float* bc3   = (const float*)d_in[31];
    float* out = (float*)d_out;

    cudaFuncSetAttribute(k_edge, cudaFuncAttributeMaxDynamicSharedMemorySize, SMEMB);

    k_inv<<<1, 32>>>(cell);
    k_init<<<(BB*NN*3 + 127)/128, 128>>>(pos);
    k_prepW<<<LL*8, 256>>>(We2);
    k_embed<<<dim3(NN, BB), 128>>>(pos, oneh, W_in1, b_in1, W_in2, b_in2);

    for (int l = 0; l < LL; l++){
        k_A8<<<BB*NN/8, 128>>>(We1 + l*257*DD);
        k_edge<<<dim3(NN, BB, 2), 256, SMEMB>>>(We1 + l*257*DD, be1 + l*DD,
                                    be2 + l*DD, We3 + l*DD, be3 + l,
                                    Wm1 + l*DD, bm1 + l*DD,
                                    Wp1 + l*DD, bp1 + l*DD,
                                    Wp2 + l*DD, bp2 + l,
                                    cell, mask, l);
        k_node<<<BB*NN/8, 128>>>(Wm2 + l*DD*DD, bm2 + l*DD,
                                 W_ih + l*DD*3*DD, W_hh + l*DD*3*DD,
                                 b_ih + l*3*DD,    b_hh + l*3*DD, mask);
    }

    k_pool<<<BB, 128>>>(mask, Wc1, bc1, Wc2, bc2, Wc3, bc3, out);
}

// round 14
// speedup vs baseline: 1.3248x; 1.0338x over previous
#include <cuda_runtime.h>
#include <cuda_bf16.h>
#include <math.h>
#include <stdint.h>

#define BB 2
#define NN 320
#define DD 128
#define LL 4
#define OHH 100
#define KS 136   // smem row stride in bf16 elems (272 bytes)
#define JH 160   // j's per half-block

// ---------------- device scratch (no allocs allowed) ----------------
__device__ float g_h[BB*NN*DD];
__device__ float g_x[BB*NN*3];
__device__ float g_A[BB*NN*DD];
__device__ float g_Bv[BB*NN*DD];
__device__ float g_Sp[2*BB*NN*DD];     // per-half partial S
__device__ float g_dxp[2*BB*NN*3];     // per-half partial (dx + bp2*sum_r)
__device__ float g_invC[BB*9];
__device__ unsigned short g_We2bf[LL*DD*DD];   // per-layer B[n][k] = We2[k][n] in bf16

// ---------------- math helpers ----------------
__device__ __forceinline__ float tanh_ap(float x){
    float t; asm("tanh.approx.f32 %0, %1;" : "=f"(t) : "f"(x)); return t;
}
__device__ __forceinline__ float silu_f(float x){
    return 0.5f*x*(1.f + tanh_ap(0.5f*x));
}
__device__ __forceinline__ float sigm_f(float x){
    return 0.5f*(1.f + tanh_ap(0.5f*x));
}
__device__ __forceinline__ uint32_t bf16x2_pack(float lo, float hi){
    uint32_t r;
    asm("cvt.rn.bf16x2.f32 %0, %1, %2;" : "=r"(r) : "f"(hi), "f"(lo));  // first src -> high half
    return r;
}

__device__ __forceinline__ uint32_t smem_u32(const void* p){
    uint32_t a;
    asm("{ .reg .u64 t; cvta.to.shared.u64 t, %1; cvt.u32.u64 %0, t; }" : "=r"(a) : "l"(p));
    return a;
}
__device__ __forceinline__ void ldsm4(uint32_t& r0, uint32_t& r1, uint32_t& r2, uint32_t& r3, uint32_t a){
    asm volatile("ldmatrix.sync.aligned.m8n8.x4.shared.b16 {%0,%1,%2,%3}, [%4];"
                 : "=r"(r0),"=r"(r1),"=r"(r2),"=r"(r3) : "r"(a));
}
__device__ __forceinline__ void mma16816(float* c, uint32_t a0,uint32_t a1,uint32_t a2,uint32_t a3,
                                         uint32_t b0,uint32_t b1){
    asm volatile("mma.sync.aligned.m16n8k16.row.col.f32.bf16.bf16.f32 "
        "{%0,%1,%2,%3}, {%4,%5,%6,%7}, {%8,%9}, {%0,%1,%2,%3};"
        : "+f"(c[0]),"+f"(c[1]),"+f"(c[2]),"+f"(c[3])
        : "r"(a0),"r"(a1),"r"(a2),"r"(a3),"r"(b0),"r"(b1));
}

// ---------------- small kernels ----------------
__global__ void k_inv(const float* __restrict__ cell){
    int b = threadIdx.x;
    if (b >= BB) return;
    const float* c = cell + b*9;
    float a00=c[0],a01=c[1],a02=c[2];
    float a10=c[3],a11=c[4],a12=c[5];
    float a20=c[6],a21=c[7],a22=c[8];
    float C00 =  a11*a22 - a12*a21;
    float C01 = -(a10*a22 - a12*a20);
    float C02 =  a10*a21 - a11*a20;
    float C10 = -(a01*a22 - a02*a21);
    float C11 =  a00*a22 - a02*a20;
    float C12 = -(a00*a21 - a01*a20);
    float C20 =  a01*a12 - a02*a11;
    float C21 = -(a00*a12 - a02*a10);
    float C22 =  a00*a11 - a01*a10;
    float det = a00*C00 + a01*C01 + a02*C02;
    float id = 1.f/det;
    float* o = g_invC + b*9;
    o[0]=C00*id; o[1]=C10*id; o[2]=C20*id;
    o[3]=C01*id; o[4]=C11*id; o[5]=C21*id;
    o[6]=C02*id; o[7]=C12*id; o[8]=C22*id;
}

__global__ void k_init(const float* __restrict__ pos){
    int t = blockIdx.x*blockDim.x + threadIdx.x;
    if (t < BB*NN*3) g_x[t] = pos[t];
}

// prepare We2^T bf16: B[n][k] = We2[k][n];  grid = LL*8 blocks
__global__ void k_prepW(const float* __restrict__ We2){
    int l = blockIdx.x >> 3, part = blockIdx.x & 7, tid = threadIdx.x;
    const float* W = We2 + l*DD*DD;
    unsigned short* dst = g_We2bf + l*DD*DD;
    int e0 = part*2048;
    for (int q = 0; q < 8; q++){
        int e = e0 + q*256 + tid;
        int n = e >> 7, k = e & 127;
        dst[e] = __bfloat16_as_ushort(__float2bfloat16_rn(W[k*DD + n]));
    }
}

// per-atom input embedding (640 blocks — measured best shape)
__global__ void k_embed(const float* __restrict__ pos, const float* __restrict__ oneh,
                        const float* __restrict__ W1, const float* __restrict__ b1,
                        const float* __restrict__ W2, const float* __restrict__ b2){
    int i = blockIdx.x, b = blockIdx.y, tid = threadIdx.x;
    __shared__ float sin_[OHH+3];
    __shared__ float sh1[DD];
    if (tid < OHH+3){
        sin_[tid] = (tid < 3) ? pos[(b*NN+i)*3 + tid] : oneh[(b*NN+i)*OHH + (tid-3)];
    }
    __syncthreads();
    float t = b1[tid];
    #pragma unroll 8
    for (int k = 0; k < OHH+3; k++) t += sin_[k]*W1[k*DD + tid];
    sh1[tid] = silu_f(t);
    __syncthreads();
    float t2 = b2[tid];
    #pragma unroll 8
    for (int k = 0; k < DD; k++) t2 += sh1[k]*W2[k*DD + tid];
    g_h[(b*NN+i)*DD + tid] = t2;
}

// blocked A/Bv: 8 atoms/block (used once, for layer 0)
__global__ void __launch_bounds__(128) k_A8(const float* __restrict__ We1l){
    __shared__ float sh[8*128];
    int g0 = blockIdx.x*8, tid = threadIdx.x;
    #pragma unroll
    for (int q = 0; q < 8; q++) sh[q*128+tid] = g_h[(g0+q)*DD + tid];
    __syncthreads();
    float a[8], bv[8];
    #pragma unroll
    for (int q = 0; q < 8; q++){ a[q] = 0.f; bv[q] = 0.f; }
    for (int k = 0; k < DD; k += 4){
        float w1a = We1l[(k+0)*DD + tid], w2a = We1l[(DD+k+0)*DD + tid];
        float w1b = We1l[(k+1)*DD + tid], w2b = We1l[(DD+k+1)*DD + tid];
        float w1c = We1l[(k+2)*DD + tid], w2c = We1l[(DD+k+2)*DD + tid];
        float w1d = We1l[(k+3)*DD + tid], w2d = We1l[(DD+k+3)*DD + tid];
        #pragma unroll
        for (int q = 0; q < 8; q++){
            float4 h4 = *(const float4*)(sh + q*128 + k);
            a[q]  += h4.x*w1a + h4.y*w1b + h4.z*w1c + h4.w*w1d;
            bv[q] += h4.x*w2a + h4.y*w2b + h4.z*w2c + h4.w*w2d;
        }
    }
    #pragma unroll
    for (int q = 0; q < 8; q++){
        g_A[(g0+q)*DD + tid]  = a[q];
        g_Bv[(g0+q)*DD + tid] = bv[q];
    }
}

// ---------------- heavy kernel: per-(b,i,half), pipelined tcore GEMM + messages ----------------
#define TROWS    16
#define NTH      (JH/TROWS)              // 10 tiles per half
#define OFF_B    0                       // bf16 [128][KS]  = 34816
#define OFF_M1   34816                   // 2 x bf16[16][KS] = 8704
#define M1BUF    4352
#define OFF_GEO  43520                   // 5 x 160 floats  = 3200
#define OFF_WT   46720                   // 1280 floats     = 5120
#define OFF_MIJ  51840                   // 160 floats      = 640
#define OFF_PART 52480                   // 2 x 128 floats  = 1024
#define OFF_RED  53504                   // 32 floats       = 128
#define SMEMB    53632

__global__ void __launch_bounds__(256, 4) k_edge(
    const float* __restrict__ We1l, const float* __restrict__ be1l,
    const float* __restrict__ be2l, const float* __restrict__ We3l,
    const float* __restrict__ be3l,
    const float* __restrict__ Wm1l, const float* __restrict__ bm1l,
    const float* __restrict__ Wp1l, const float* __restrict__ bp1l,
    const float* __restrict__ Wp2l, const float* __restrict__ bp2l,
    const float* __restrict__ cell, const float* __restrict__ mask, int layer)
{
    extern __shared__ char base[];
    __nv_bfloat16* sB  = (__nv_bfloat16*)(base + OFF_B);
    float* sDij = (float*)(base + OFF_GEO);       // [160] local j
    float* sRx  = sDij + JH;
    float* sRy  = sRx + JH;
    float* sRz  = sRy + JH;
    float* sPm  = sRz + JH;
    float* sWt  = (float*)(base + OFF_WT);
    float* sMij = (float*)(base + OFF_MIJ);       // [160]
    float* sPart= (float*)(base + OFF_PART);      // [2][128]
    float* sRed = (float*)(base + OFF_RED);

    int i = blockIdx.x, b = blockIdx.y, half = blockIdx.z;
    int j0 = half*JH;
    int tid = threadIdx.x, wid = tid >> 5, lane = tid & 31;

    // stage B[n][k] bf16 into padded smem
    {
        const uint4* src = (const uint4*)(g_We2bf + layer*DD*DD);
        #pragma unroll
        for (int q = 0; q < 8; q++){
            int e = tid + q*256;
            int n = e >> 4, k0 = (e & 15) << 3;
            *(uint4*)(sB + n*KS + k0) = src[e];
        }
    }
    if (tid < 128){
        sWt[tid]       = be2l[tid];
        sWt[128+tid]   = We3l[tid];
        sWt[256+tid]   = Wm1l[tid];
        sWt[384+tid]   = bm1l[tid];
        ((float4*)(sWt+512))[tid] = make_float4(Wp1l[tid], bp1l[tid], Wp2l[tid], 0.f);
        sWt[1024+tid]  = g_A[(b*NN+i)*DD + tid] + be1l[tid];   // tb
        sWt[1152+tid]  = We1l[256*DD + tid];                    // wd
    }
    float mi = mask[b*NN + i];
    // geometry for this half's 160 j, frac computed inline from g_x
    {
        const float* ic = g_invC + b*9;
        float i0=ic[0],i1=ic[1],i2=ic[2],i3=ic[3],i4=ic[4],i5=ic[5],i6=ic[6],i7=ic[7],i8=ic[8];
        float xi0=g_x[(b*NN+i)*3+0], xi1=g_x[(b*NN+i)*3+1], xi2=g_x[(b*NN+i)*3+2];
        float fi0 = xi0*i0 + xi1*i3 + xi2*i6;
        float fi1 = xi0*i1 + xi1*i4 + xi2*i7;
        float fi2 = xi0*i2 + xi1*i5 + xi2*i8;
        float c0=cell[b*9+0],c1=cell[b*9+1],c2=cell[b*9+2];
        float c3=cell[b*9+3],c4=cell[b*9+4],c5=cell[b*9+5];
        float c6=cell[b*9+6],c7=cell[b*9+7],c8=cell[b*9+8];
        for (int jl = tid; jl < JH; jl += 256){
            int j = j0 + jl;
            float xj0=g_x[(b*NN+j)*3+0], xj1=g_x[(b*NN+j)*3+1], xj2=g_x[(b*NN+j)*3+2];
            float f0 = xj0*i0 + xj1*i3 + xj2*i6 - fi0;
            float f1 = xj0*i1 + xj1*i4 + xj2*i7 - fi1;
            float f2 = xj0*i2 + xj1*i5 + xj2*i8 - fi2;
            f0 -= rintf(f0); f1 -= rintf(f1); f2 -= rintf(f2);
            float rx = f0*c0 + f1*c3 + f2*c6;
            float ry = f0*c1 + f1*c4 + f2*c7;
            float rz = f0*c2 + f1*c5 + f2*c8;
            float dij = sqrtf(rx*rx + ry*ry + rz*rz + 1e-12f);
            float pm = mi * mask[b*NN + j];
            sDij[jl] = dij*pm + (1.f - pm)*1e6f;
            sRx[jl] = rx*pm; sRy[jl] = ry*pm; sRz[jl] = rz*pm;
            sPm[jl] = pm;
        }
    }
    __syncthreads();

    float be3v = be3l[0], bp2v = bp2l[0];

    // warp tiling: all 8 warps share the 16-row tile, each owns 16 N-cols
    int wn = wid * 16;

    uint32_t sM1a = smem_u32(base + OFF_M1);
    uint32_t sBa  = smem_u32(sB);
    uint32_t aOff = (uint32_t)(((lane & 15)*KS + (lane >> 4)*8) * 2);
    int lr = lane & 7;
    int lb3 = (lane >> 3) & 1;
    int lb4 = lane >> 4;
    uint32_t bBase = sBa + (uint32_t)(((wn + lb4*8 + lr)*KS + lb3*8) * 2);

    // m1 thread mapping: row = tid>>4 (0..15), k0 = (tid&15)*8
    int m1row = tid >> 4;
    int m1k0 = (tid & 15) * 8;
    const float4* tb4 = (const float4*)(sWt + 1024 + m1k0);
    const float4* wd4 = (const float4*)(sWt + 1152 + m1k0);

    // ---- prologue: m1 tile 0 into buffer 0 ----
    {
        float dij = sDij[m1row];
        const float4* bv = (const float4*)(g_Bv + (size_t)(b*NN + j0 + m1row)*DD + m1k0);
        float4 bva = bv[0], bvb = bv[1];
        float4 tba = tb4[0], tbb = tb4[1];
        float4 wda = wd4[0], wdb = wd4[1];
        uint4 pk;
        pk.x = bf16x2_pack(silu_f(tba.x + bva.x + dij*wda.x), silu_f(tba.y + bva.y + dij*wda.y));
        pk.y = bf16x2_pack(silu_f(tba.z + bva.z + dij*wda.z), silu_f(tba.w + bva.w + dij*wda.w));
        pk.z = bf16x2_pack(silu_f(tbb.x + bvb.x + dij*wdb.x), silu_f(tbb.y + bvb.y + dij*wdb.y));
        pk.w = bf16x2_pack(silu_f(tbb.z + bvb.z + dij*wdb.z), silu_f(tbb.w + bvb.w + dij*wdb.w));
        *(uint4*)(base + OFF_M1 + m1row*(KS*2) + m1k0*2) = pk;
    }
    __syncthreads();

    for (int T = 0; T < NTH; T++){
        int buf = T & 1;

        // ---- prefetch g_Bv for tile T+1 into registers BEFORE GEMM ----
        float4 nbva, nbvb;
        float ndij = 0.f;
        if (T + 1 < NTH){
            int jl = (T+1)*TROWS + m1row;
            ndij = sDij[jl];
            const float4* bv = (const float4*)(g_Bv + (size_t)(b*NN + j0 + jl)*DD + m1k0);
            nbva = bv[0];
            nbvb = bv[1];
        }

        // ---- GEMM(T): warp computes C[16 j][16 t] from buf ----
        float acc[2][4];
        #pragma unroll
        for (int s = 0; s < 2; s++)
            #pragma unroll
            for (int c = 0; c < 4; c++) acc[s][c] = 0.f;

        uint32_t aA = sM1a + buf*M1BUF + aOff;
        uint32_t bA = bBase;
        #pragma unroll
        for (int ks = 0; ks < 8; ks++){
            uint32_t a0,a1,a2,a3, b0,b1,b2,b3;
            ldsm4(a0,a1,a2,a3, aA);
            ldsm4(b0,b1,b2,b3, bA);
            mma16816(acc[0], a0,a1,a2,a3, b0,b1);
            mma16816(acc[1], a0,a1,a2,a3, b2,b3);
            aA += 32; bA += 32;
        }

        // ---- m1(T+1) into other buffer from prefetched registers ----
        if (T + 1 < NTH){
            float4 tba = tb4[0], tbb = tb4[1];
            float4 wda = wd4[0], wdb = wd4[1];
            uint4 pk;
            pk.x = bf16x2_pack(silu_f(tba.x + nbva.x + ndij*wda.x), silu_f(tba.y + nbva.y + ndij*wda.y));
            pk.y = bf16x2_pack(silu_f(tba.z + nbva.z + ndij*wda.z), silu_f(tba.w + nbva.w + ndij*wda.w));
            pk.z = bf16x2_pack(silu_f(tbb.x + nbvb.x + ndij*wdb.x), silu_f(tbb.y + nbvb.y + ndij*wdb.y));
            pk.w = bf16x2_pack(silu_f(tbb.z + nbvb.z + ndij*wdb.z), silu_f(tbb.w + nbvb.w + ndij*wdb.w));
            *(uint4*)(base + OFF_M1 + (buf^1)*M1BUF + m1row*(KS*2) + m1k0*2) = pk;
        }

        // ---- epilogue(T): m2 = silu(C + be2), dot with we3 over this warp's 16 cols ----
        {
            int colq = wn + (lane & 3)*2;
            float d0 = 0.f, d1 = 0.f;
            #pragma unroll
            for (int s = 0; s < 2; s++){
                int col = colq + s*8;
                float w0 = sWt[128+col], w1 = sWt[128+col+1];
                float e0 = sWt[col], e1 = sWt[col+1];
                d0 += silu_f(acc[s][0] + e0)*w0 + silu_f(acc[s][1] + e1)*w1;
                d1 += silu_f(acc[s][2] + e0)*w0 + silu_f(acc[s][3] + e1)*w1;
            }
            d0 += __shfl_xor_sync(0xffffffffu, d0, 1);
            d0 += __shfl_xor_sync(0xffffffffu, d0, 2);
            d1 += __shfl_xor_sync(0xffffffffu, d1, 1);
            d1 += __shfl_xor_sync(0xffffffffu, d1, 2);
            if ((lane & 3) == 0){
                int row = lane >> 2;   // 0..7
                sPart[buf*128 + wid*16 + row]     = d0;
                sPart[buf*128 + wid*16 + row + 8] = d1;
            }
        }
        __syncthreads();   // the ONE barrier per tile

        // ---- fold sMij(T) (tid<16) — overlaps next iteration's GEMM for other threads ----
        if (tid < 16){
            int jl = T*TROWS + tid;
            float s = 0.f;
            #pragma unroll
            for (int w = 0; w < 8; w++) s += sPart[buf*128 + w*16 + tid];
            sMij[jl] = (s + be3v) * sPm[jl];
        }
    }
    __syncthreads();

    // -------- balanced warp-split tail over 160 local j's --------
    if (wid < 4){
        int t = tid;   // 0..127
        float wm1 = sWt[256+t], bm1v = sWt[384+t];
        float s = 0.f;
        #pragma unroll 4
        for (int jl = 0; jl < JH; jl++)
            s += silu_f(fmaf(sMij[jl], wm1, bm1v));
        g_Sp[half*(BB*NN*DD) + (b*NN+i)*DD + t] = s;
        // warp 0 also computes sum_r (cheap)
        if (wid == 0){
            float s0=0.f, s1=0.f, s2=0.f;
            #pragma unroll
            for (int jl = lane; jl < JH; jl += 32){
                s0 += sRx[jl]; s1 += sRy[jl]; s2 += sRz[jl];
            }
            #pragma unroll
            for (int o = 16; o; o >>= 1){
                s0 += __shfl_xor_sync(0xffffffffu, s0, o);
                s1 += __shfl_xor_sync(0xffffffffu, s1, o);
                s2 += __shfl_xor_sync(0xffffffffu, s2, o);
            }
            if (lane == 0){ sRed[20] = s0; sRed[21] = s1; sRed[22] = s2; }
        }
    } else {
        // transposed phi: thread p owns hidden col p; loops all 160 j (160 silu, balanced)
        int p = tid - 128;
        float4 w = ((const float4*)(sWt + 512))[p];   // (wp1, bp1, wp2)
        float ux=0.f, uy=0.f, uz=0.f;
        #pragma unroll 4
        for (int jl = 0; jl < JH; jl++){
            float u = silu_f(fmaf(sMij[jl], w.x, w.y));
            ux = fmaf(u, sRx[jl], ux);
            uy = fmaf(u, sRy[jl], uy);
            uz = fmaf(u, sRz[jl], uz);
        }
        ux *= w.z; uy *= w.z; uz *= w.z;
        #pragma unroll
        for (int o = 16; o; o >>= 1){
            ux += __shfl_xor_sync(0xffffffffu, ux, o);
            uy += __shfl_xor_sync(0xffffffffu, uy, o);
            uz += __shfl_xor_sync(0xffffffffu, uz, o);
        }
        if (lane == 0){
            sRed[(wid-4)*4 + 0] = ux;
            sRed[(wid-4)*4 + 1] = uy;
            sRed[(wid-4)*4 + 2] = uz;
        }
    }
    __syncthreads();
    if (tid == 0){
        float a0=0,a1=0,a2=0;
        #pragma unroll
        for (int w = 0; w < 4; w++){
            a0 += sRed[w*4+0]; a1 += sRed[w*4+1]; a2 += sRed[w*4+2];
        }
        int idx = (b*NN+i)*3;
        g_dxp[half*(BB*NN*3) + idx + 0] = a0 + bp2v*sRed[20];
        g_dxp[half*(BB*NN*3) + idx + 1] = a1 + bp2v*sRed[21];
        g_dxp[half*(BB*NN*3) + idx + 2] = a2 + bp2v*sRed[22];
    }
}

// ---------------- blocked node update: fold halves, S@Wm2 -> GRU, x update; 8 nodes/block ----------------
// Also fused: compute A/Bv for the NEXT layer from the freshly produced h (doA != 0).
__global__ void __launch_bounds__(128) k_node(
    const float* __restrict__ Wm2l, const float* __restrict__ bm2l,
    const float* __restrict__ Wihl, const float* __restrict__ Whhl,
    const float* __restrict__ bihl, const float* __restrict__ bhhl,
    const float* __restrict__ mask,
    const float* __restrict__ We1n, int doA)
{
    __shared__ float sS[8*128], shh[8*128], smn[8*128], sG[8*384], sHn[8*128];
    int g0 = blockIdx.x*8, tid = threadIdx.x;

    // fold the two halves of S; also update x from dx partials
    #pragma unroll
    for (int q = 0; q < 8; q++){
        int idx = (g0+q)*DD + tid;
        sS[q*128+tid]  = g_Sp[idx] + g_Sp[BB*NN*DD + idx];
        shh[q*128+tid] = g_h[idx];
    }
    if (tid < 24){
        int q = tid / 3, c = tid % 3;
        int idx = (g0+q)*3 + c;
        g_x[idx] += g_dxp[idx] + g_dxp[BB*NN*3 + idx];
    }
    __syncthreads();

    // mn = S @ Wm2 + NN*bm2 (col = tid)
    {
        float acc[8];
        float bm = (float)NN * bm2l[tid];
        #pragma unroll
        for (int q = 0; q < 8; q++) acc[q] = bm;
        for (int k = 0; k < DD; k += 4){
            float4 w4;
            w4.x = Wm2l[(k+0)*DD + tid];
            w4.y = Wm2l[(k+1)*DD + tid];
            w4.z = Wm2l[(k+2)*DD + tid];
            w4.w = Wm2l[(k+3)*DD + tid];
            #pragma unroll
            for (int q = 0; q < 8; q++){
                float4 s4 = *(const float4*)(sS + q*128 + k);
                acc[q] += s4.x*w4.x + s4.y*w4.y + s4.z*w4.z + s4.w*w4.w;
            }
        }
        #pragma unroll
        for (int q = 0; q < 8; q++) smn[q*128+tid] = acc[q];
    }
    __syncthreads();

    // gates: thread owns cols tid, tid+128, tid+256
    for (int c3 = 0; c3 < 3; c3++){
        int col = tid + c3*128;
        float gi[8], gh[8];
        float bi = bihl[col], bh = bhhl[col];
        #pragma unroll
        for (int q = 0; q < 8; q++){ gi[q] = bi; gh[q] = bh; }
        for (int k = 0; k < DD; k += 4){
            #pragma unroll
            for (int kk = 0; kk < 4; kk++){
                float wi = Wihl[(k+kk)*384 + col];
                float wh = Whhl[(k+kk)*384 + col];
                #pragma unroll
                for (int q = 0; q < 8; q++){
                    gi[q] = fmaf(smn[q*128 + k+kk], wi, gi[q]);
                    gh[q] = fmaf(shh[q*128 + k+kk], wh, gh[q]);
                }
            }
        }
        if (c3 < 2){
            #pragma unroll
            for (int q = 0; q < 8; q++) sG[q*384+col] = gi[q] + gh[q];
        } else {
            #pragma unroll
            for (int q = 0; q < 8; q++){ sG[q*384+col] = gi[q]; sHn[q*128+tid] = gh[q]; }
        }
    }
    __syncthreads();

    // finalize h; overwrite shh with new h for the fused A/Bv stage
    #pragma unroll
    for (int q = 0; q < 8; q++){
        float r = sigm_f(sG[q*384 + tid]);
        float z = sigm_f(sG[q*384 + 128 + tid]);
        float n = tanh_ap(sG[q*384 + 256 + tid] + r*sHn[q*128+tid]);
        float hn = ((1.f - z)*n + z*shh[q*128+tid]) * mask[g0+q];
        g_h[(g0+q)*DD + tid] = hn;
        shh[q*128+tid] = hn;
    }

    if (doA){
        __syncthreads();
        float a[8], bv[8];
        #pragma unroll
        for (int q = 0; q < 8; q++){ a[q] = 0.f; bv[q] = 0.f; }
        for (int k = 0; k < DD; k += 4){
            float w1a = We1n[(k+0)*DD + tid], w2a = We1n[(DD+k+0)*DD + tid];
            float w1b = We1n[(k+1)*DD + tid], w2b = We1n[(DD+k+1)*DD + tid];
            float w1c = We1n[(k+2)*DD + tid], w2c = We1n[(DD+k+2)*DD + tid];
            float w1d = We1n[(k+3)*DD + tid], w2d = We1n[(DD+k+3)*DD + tid];
            #pragma unroll
            for (int q = 0; q < 8; q++){
                float4 h4 = *(const float4*)(shh + q*128 + k);
                a[q]  += h4.x*w1a + h4.y*w1b + h4.z*w1c + h4.w*w1d;
                bv[q] += h4.x*w2a + h4.y*w2b + h4.z*w2c + h4.w*w2d;
            }
        }
        #pragma unroll
        for (int q = 0; q < 8; q++){
            g_A[(g0+q)*DD + tid]  = a[q];
            g_Bv[(g0+q)*DD + tid] = bv[q];
        }
    }
}

// ---------------- pool + head ----------------
__global__ void k_pool(const float* __restrict__ mask,
                       const float* __restrict__ Wc1, const float* __restrict__ bc1,
                       const float* __restrict__ Wc2, const float* __restrict__ bc2,
                       const float* __restrict__ Wc3, const float* __restrict__ bc3,
                       float* __restrict__ out){
    int b = blockIdx.x, tid = threadIdx.x;
    __shared__ float feat[DD], o1[DD], o2[64];
    float s = 0.f, ms = 0.f;
    for (int i = 0; i < NN; i++){
        float mk = mask[b*NN + i];
        s  += g_h[(b*NN+i)*DD + tid]*mk;
        ms += mk;
    }
    feat[tid] = s / fmaxf(ms, 1.f);
    __syncthreads();
    float t = bc1[tid];
    #pragma unroll 8
    for (int k = 0; k < DD; k++) t += feat[k]*Wc1[k*DD + tid];
    o1[tid] = silu_f(t);
    __syncthreads();
    if (tid < 64){
        float t2 = bc2[tid];
        #pragma unroll 8
        for (int k = 0; k < DD; k++) t2 += o1[k]*Wc2[k*64 + tid];
        o2[tid] = silu_f(t2);
    }
    __syncthreads();
    if (tid < 6){
        float t3 = bc3[tid];
        #pragma unroll
        for (int k = 0; k < 64; k++) t3 += o2[k]*Wc3[k*6 + tid];
        float r;
        if (tid < 3){
            r = (t3 > 20.f) ? t3 : log1pf(expf(t3));
        } else {
            r = (1.f / (1.f + expf(-t3))) * 180.f;
        }
        out[b*6 + tid] = r;
    }
}

extern "C" void kernel_launch(void* const* d_in, const int* in_sizes, int n_in,
                              void* d_out, int out_size){
    const float* pos   = (const float*)d_in[0];
    const float* oneh  = (const float*)d_in[1];
    const float* mask  = (const float*)d_in[2];
    const float* cell  = (const float*)d_in[3];
    const float* W_in1 = (const float*)d_in[4];
    const float* b_in1 = (const float*)d_in[5];
    const float* W_in2 = (const float*)d_in[6];
    const float* b_in2 = (const float*)d_in[7];
    const float* We1   = (const float*)d_in[8];
    const float* be1   = (const float*)d_in[9];
    const float* We2   = (const float*)d_in[10];
    const float* be2   = (const float*)d_in[11];
    const float* We3   = (const float*)d_in[12];
    const float* be3   = (const float*)d_in[13];
    const float* Wm1   = (const float*)d_in[14];
    const float* bm1   = (const float*)d_in[15];
    const float* Wm2   = (const float*)d_in[16];
    const float* bm2   = (const float*)d_in[17];
    const float* Wp1   = (const float*)d_in[18];
    const float* bp1   = (const float*)d_in[19];
    const float* Wp2   = (const float*)d_in[20];
    const float* bp2   = (const float*)d_in[21];
    const float* W_ih  = (const float*)d_in[22];
    const float* W_hh  = (const float*)d_in[23];
    const float* b_ih  = (const float*)d_in[24];
    const float* b_hh  = (const float*)d_in[25];
    const float* Wc1   = (const float*)d_in[26];
    const float* bc1   = (const float*)d_in[27];
    const float* Wc2   = (const float*)d_in[28];
    const float* bc2   = (const float*)d_in[29];
    const float* Wc3   = (const float*)d_in[30];
    const float* bc3   = (const float*)d_in[31];
    float* out = (float*)d_out;

    cudaFuncSetAttribute(k_edge, cudaFuncAttributeMaxDynamicSharedMemorySize, SMEMB);

    k_inv<<<1, 32>>>(cell);
    k_init<<<(BB*NN*3 + 127)/128, 128>>>(pos);
    k_prepW<<<LL*8, 256>>>(We2);
    k_embed<<<dim3(NN, BB), 128>>>(pos, oneh, W_in1, b_in1, W_in2, b_in2);
    k_A8<<<BB*NN/8, 128>>>(We1);   // layer 0 A/Bv

    for (int l = 0; l < LL; l++){
        k_edge<<<dim3(NN, BB, 2), 256, SMEMB>>>(We1 + l*257*DD, be1 + l*DD,
                                    be2 + l*DD, We3 + l*DD, be3 + l,
                                    Wm1 + l*DD, bm1 + l*DD,
                                    Wp1 + l*DD, bp1 + l*DD,
                                    Wp2 + l*DD, bp2 + l,
                                    cell, mask, l);
        int doA = (l + 1 < LL);
        k_node<<<BB*NN/8, 128>>>(Wm2 + l*DD*DD, bm2 + l*DD,
                                 W_ih + l*DD*3*DD, W_hh + l*DD*3*DD,
                                 b_ih + l*3*DD,    b_hh + l*3*DD, mask,
                                 We1 + (doA ? (l+1)*257*DD : 0), doA);
    }

    k_pool<<<BB, 128>>>(mask, Wc1, bc1, Wc2, bc2, Wc3, bc3, out);
}

// round 15
// speedup vs baseline: 1.3333x; 1.0064x over previous
#include <cuda_runtime.h>
#include <cuda_fp16.h>
#include <math.h>
#include <stdint.h>

#define BB 2
#define NN 320
#define DD 128
#define LL 4
#define OHH 100
#define KS 136   // smem row stride in f16 elems (272 bytes)
#define JH 160   // j's per half-block

// ---------------- device scratch (no allocs allowed) ----------------
__device__ float g_h[BB*NN*DD];
__device__ float g_x[BB*NN*3];
__device__ float g_A[BB*NN*DD];
__device__ float g_Bv[BB*NN*DD];
__device__ float g_Sp[2*BB*NN*DD];     // per-half partial S
__device__ float g_dxp[2*BB*NN*3];     // per-half partial (dx + bp2*sum_r)
__device__ float g_invC[BB*9];
__device__ unsigned short g_We2h[LL*DD*DD];   // per-layer B[n][k] = We2[k][n] in f16

// ---------------- math helpers ----------------
__device__ __forceinline__ float tanh_ap(float x){
    float t; asm("tanh.approx.f32 %0, %1;" : "=f"(t) : "f"(x)); return t;
}
__device__ __forceinline__ float silu_f(float x){
    return 0.5f*x*(1.f + tanh_ap(0.5f*x));
}
__device__ __forceinline__ float sigm_f(float x){
    return 0.5f*(1.f + tanh_ap(0.5f*x));
}
// pack two f32 into f16x2 (lo in low half)
__device__ __forceinline__ uint32_t f16x2_from2f(float lo, float hi){
    uint32_t r; asm("cvt.rn.f16x2.f32 %0, %1, %2;" : "=r"(r) : "f"(hi), "f"(lo)); return r;
}
// packed silu on f16x2: one MUFU for two values
__device__ __forceinline__ uint32_t silu2_h2(uint32_t x){
    const uint32_t half2c = 0x38003800u;   // f16 {0.5, 0.5}
    uint32_t hx, t, r;
    asm("mul.rn.f16x2 %0, %1, %2;" : "=r"(hx) : "r"(x), "r"(half2c));
    asm("tanh.approx.f16x2 %0, %1;" : "=r"(t) : "r"(hx));
    asm("fma.rn.f16x2 %0, %1, %2, %3;" : "=r"(r) : "r"(hx), "r"(t), "r"(hx));
    return r;   // 0.5x + 0.5x*tanh(0.5x) = silu(x)
}
__device__ __forceinline__ float2 unpack_h2(uint32_t v){
    __half2 h = *reinterpret_cast<__half2*>(&v);
    return __half22float2(h);
}

__device__ __forceinline__ uint32_t smem_u32(const void* p){
    uint32_t a;
    asm("{ .reg .u64 t; cvta.to.shared.u64 t, %1; cvt.u32.u64 %0, t; }" : "=r"(a) : "l"(p));
    return a;
}
__device__ __forceinline__ void ldsm4(uint32_t& r0, uint32_t& r1, uint32_t& r2, uint32_t& r3, uint32_t a){
    asm volatile("ldmatrix.sync.aligned.m8n8.x4.shared.b16 {%0,%1,%2,%3}, [%4];"
                 : "=r"(r0),"=r"(r1),"=r"(r2),"=r"(r3) : "r"(a));
}
__device__ __forceinline__ void mma16816(float* c, uint32_t a0,uint32_t a1,uint32_t a2,uint32_t a3,
                                         uint32_t b0,uint32_t b1){
    asm volatile("mma.sync.aligned.m16n8k16.row.col.f32.f16.f16.f32 "
        "{%0,%1,%2,%3}, {%4,%5,%6,%7}, {%8,%9}, {%0,%1,%2,%3};"
        : "+f"(c[0]),"+f"(c[1]),"+f"(c[2]),"+f"(c[3])
        : "r"(a0),"r"(a1),"r"(a2),"r"(a3),"r"(b0),"r"(b1));
}

// ---------------- small kernels ----------------
__global__ void k_inv(const float* __restrict__ cell){
    int b = threadIdx.x;
    if (b >= BB) return;
    const float* c = cell + b*9;
    float a00=c[0],a01=c[1],a02=c[2];
    float a10=c[3],a11=c[4],a12=c[5];
    float a20=c[6],a21=c[7],a22=c[8];
    float C00 =  a11*a22 - a12*a21;
    float C01 = -(a10*a22 - a12*a20);
    float C02 =  a10*a21 - a11*a20;
    float C10 = -(a01*a22 - a02*a21);
    float C11 =  a00*a22 - a02*a20;
    float C12 = -(a00*a21 - a01*a20);
    float C20 =  a01*a12 - a02*a11;
    float C21 = -(a00*a12 - a02*a10);
    float C22 =  a00*a11 - a01*a10;
    float det = a00*C00 + a01*C01 + a02*C02;
    float id = 1.f/det;
    float* o = g_invC + b*9;
    o[0]=C00*id; o[1]=C10*id; o[2]=C20*id;
    o[3]=C01*id; o[4]=C11*id; o[5]=C21*id;
    o[6]=C02*id; o[7]=C12*id; o[8]=C22*id;
}

__global__ void k_init(const float* __restrict__ pos){
    int t = blockIdx.x*blockDim.x + threadIdx.x;
    if (t < BB*NN*3) g_x[t] = pos[t];
}

// prepare We2^T f16: B[n][k] = We2[k][n];  grid = LL*8 blocks
__global__ void k_prepW(const float* __restrict__ We2){
    int l = blockIdx.x >> 3, part = blockIdx.x & 7, tid = threadIdx.x;
    const float* W = We2 + l*DD*DD;
    unsigned short* dst = g_We2h + l*DD*DD;
    int e0 = part*2048;
    for (int q = 0; q < 8; q++){
        int e = e0 + q*256 + tid;
        int n = e >> 7, k = e & 127;
        __half v = __float2half_rn(W[k*DD + n]);
        dst[e] = *reinterpret_cast<unsigned short*>(&v);
    }
}

// per-atom input embedding (640 blocks — measured best shape)
__global__ void k_embed(const float* __restrict__ pos, const float* __restrict__ oneh,
                        const float* __restrict__ W1, const float* __restrict__ b1,
                        const float* __restrict__ W2, const float* __restrict__ b2){
    int i = blockIdx.x, b = blockIdx.y, tid = threadIdx.x;
    __shared__ float sin_[OHH+3];
    __shared__ float sh1[DD];
    if (tid < OHH+3){
        sin_[tid] = (tid < 3) ? pos[(b*NN+i)*3 + tid] : oneh[(b*NN+i)*OHH + (tid-3)];
    }
    __syncthreads();
    float t = b1[tid];
    #pragma unroll 8
    for (int k = 0; k < OHH+3; k++) t += sin_[k]*W1[k*DD + tid];
    sh1[tid] = silu_f(t);
    __syncthreads();
    float t2 = b2[tid];
    #pragma unroll 8
    for (int k = 0; k < DD; k++) t2 += sh1[k]*W2[k*DD + tid];
    g_h[(b*NN+i)*DD + tid] = t2;
}

// blocked A/Bv: 8 atoms/block (used once, for layer 0)
__global__ void __launch_bounds__(128) k_A8(const float* __restrict__ We1l){
    __shared__ float sh[8*128];
    int g0 = blockIdx.x*8, tid = threadIdx.x;
    #pragma unroll
    for (int q = 0; q < 8; q++) sh[q*128+tid] = g_h[(g0+q)*DD + tid];
    __syncthreads();
    float a[8], bv[8];
    #pragma unroll
    for (int q = 0; q < 8; q++){ a[q] = 0.f; bv[q] = 0.f; }
    for (int k = 0; k < DD; k += 4){
        float w1a = We1l[(k+0)*DD + tid], w2a = We1l[(DD+k+0)*DD + tid];
        float w1b = We1l[(k+1)*DD + tid], w2b = We1l[(DD+k+1)*DD + tid];
        float w1c = We1l[(k+2)*DD + tid], w2c = We1l[(DD+k+2)*DD + tid];
        float w1d = We1l[(k+3)*DD + tid], w2d = We1l[(DD+k+3)*DD + tid];
        #pragma unroll
        for (int q = 0; q < 8; q++){
            float4 h4 = *(const float4*)(sh + q*128 + k);
            a[q]  += h4.x*w1a + h4.y*w1b + h4.z*w1c + h4.w*w1d;
            bv[q] += h4.x*w2a + h4.y*w2b + h4.z*w2c + h4.w*w2d;
        }
    }
    #pragma unroll
    for (int q = 0; q < 8; q++){
        g_A[(g0+q)*DD + tid]  = a[q];
        g_Bv[(g0+q)*DD + tid] = bv[q];
    }
}

// ---------------- heavy kernel: per-(b,i,half), pipelined tcore GEMM + messages ----------------
#define TROWS    16
#define NTH      (JH/TROWS)              // 10 tiles per half
#define OFF_B    0                       // f16 [128][KS]  = 34816
#define OFF_M1   34816                   // 2 x f16[16][KS] = 8704
#define M1BUF    4352
#define OFF_GEO  43520                   // 5 x 160 floats  = 3200
#define OFF_WT   46720                   // 1280 floats     = 5120
#define OFF_MIJ  51840                   // 160 floats      = 640
#define OFF_PART 52480                   // 2 x 128 floats  = 1024
#define OFF_RED  53504                   // 32 floats       = 128
#define SMEMB    53632

__global__ void __launch_bounds__(256, 4) k_edge(
    const float* __restrict__ We1l, const float* __restrict__ be1l,
    const float* __restrict__ be2l, const float* __restrict__ We3l,
    const float* __restrict__ be3l,
    const float* __restrict__ Wm1l, const float* __restrict__ bm1l,
    const float* __restrict__ Wp1l, const float* __restrict__ bp1l,
    const float* __restrict__ Wp2l, const float* __restrict__ bp2l,
    const float* __restrict__ cell, const float* __restrict__ mask, int layer)
{
    extern __shared__ char base[];
    __half* sB  = (__half*)(base + OFF_B);
    float* sDij = (float*)(base + OFF_GEO);       // [160] local j
    float* sRx  = sDij + JH;
    float* sRy  = sRx + JH;
    float* sRz  = sRy + JH;
    float* sPm  = sRz + JH;
    float* sWt  = (float*)(base + OFF_WT);
    float* sMij = (float*)(base + OFF_MIJ);       // [160]
    float* sPart= (float*)(base + OFF_PART);      // [2][128]
    float* sRed = (float*)(base + OFF_RED);

    int i = blockIdx.x, b = blockIdx.y, half = blockIdx.z;
    int j0 = half*JH;
    int tid = threadIdx.x, wid = tid >> 5, lane = tid & 31;

    // stage B[n][k] f16 into padded smem
    {
        const uint4* src = (const uint4*)(g_We2h + layer*DD*DD);
        #pragma unroll
        for (int q = 0; q < 8; q++){
            int e = tid + q*256;
            int n = e >> 4, k0 = (e & 15) << 3;
            *(uint4*)(sB + n*KS + k0) = src[e];
        }
    }
    if (tid < 128){
        sWt[tid]       = be2l[tid];
        sWt[128+tid]   = We3l[tid];
        sWt[256+tid]   = Wm1l[tid];
        sWt[384+tid]   = bm1l[tid];
        ((float4*)(sWt+512))[tid] = make_float4(Wp1l[tid], bp1l[tid], Wp2l[tid], 0.f);
        sWt[1024+tid]  = g_A[(b*NN+i)*DD + tid] + be1l[tid];   // tb
        sWt[1152+tid]  = We1l[256*DD + tid];                    // wd
    }
    float mi = mask[b*NN + i];
    // geometry for this half's 160 j, frac computed inline from g_x
    {
        const float* ic = g_invC + b*9;
        float i0=ic[0],i1=ic[1],i2=ic[2],i3=ic[3],i4=ic[4],i5=ic[5],i6=ic[6],i7=ic[7],i8=ic[8];
        float xi0=g_x[(b*NN+i)*3+0], xi1=g_x[(b*NN+i)*3+1], xi2=g_x[(b*NN+i)*3+2];
        float fi0 = xi0*i0 + xi1*i3 + xi2*i6;
        float fi1 = xi0*i1 + xi1*i4 + xi2*i7;
        float fi2 = xi0*i2 + xi1*i5 + xi2*i8;
        float c0=cell[b*9+0],c1=cell[b*9+1],c2=cell[b*9+2];
        float c3=cell[b*9+3],c4=cell[b*9+4],c5=cell[b*9+5];
        float c6=cell[b*9+6],c7=cell[b*9+7],c8=cell[b*9+8];
        for (int jl = tid; jl < JH; jl += 256){
            int j = j0 + jl;
            float xj0=g_x[(b*NN+j)*3+0], xj1=g_x[(b*NN+j)*3+1], xj2=g_x[(b*NN+j)*3+2];
            float f0 = xj0*i0 + xj1*i3 + xj2*i6 - fi0;
            float f1 = xj0*i1 + xj1*i4 + xj2*i7 - fi1;
            float f2 = xj0*i2 + xj1*i5 + xj2*i8 - fi2;
            f0 -= rintf(f0); f1 -= rintf(f1); f2 -= rintf(f2);
            float rx = f0*c0 + f1*c3 + f2*c6;
            float ry = f0*c1 + f1*c4 + f2*c7;
            float rz = f0*c2 + f1*c5 + f2*c8;
            float dij = sqrtf(rx*rx + ry*ry + rz*rz + 1e-12f);
            float pm = mi * mask[b*NN + j];
            sDij[jl] = dij*pm + (1.f - pm)*1e6f;
            sRx[jl] = rx*pm; sRy[jl] = ry*pm; sRz[jl] = rz*pm;
            sPm[jl] = pm;
        }
    }
    __syncthreads();

    float be3v = be3l[0], bp2v = bp2l[0];

    // warp tiling: all 8 warps share the 16-row tile, each owns 16 N-cols
    int wn = wid * 16;

    uint32_t sM1a = smem_u32(base + OFF_M1);
    uint32_t sBa  = smem_u32(sB);
    uint32_t aOff = (uint32_t)(((lane & 15)*KS + (lane >> 4)*8) * 2);
    int lr = lane & 7;
    int lb3 = (lane >> 3) & 1;
    int lb4 = lane >> 4;
    uint32_t bBase = sBa + (uint32_t)(((wn + lb4*8 + lr)*KS + lb3*8) * 2);

    // m1 thread mapping: row = tid>>4 (0..15), k0 = (tid&15)*8
    int m1row = tid >> 4;
    int m1k0 = (tid & 15) * 8;
    const float4* tb4 = (const float4*)(sWt + 1024 + m1k0);
    const float4* wd4 = (const float4*)(sWt + 1152 + m1k0);

    // ---- prologue: m1 tile 0 into buffer 0 ----
    {
        float dij = sDij[m1row];
        const float4* bv = (const float4*)(g_Bv + (size_t)(b*NN + j0 + m1row)*DD + m1k0);
        float4 bva = bv[0], bvb = bv[1];
        float4 tba = tb4[0], tbb = tb4[1];
        float4 wda = wd4[0], wdb = wd4[1];
        uint4 pk;
        pk.x = silu2_h2(f16x2_from2f(tba.x + bva.x + dij*wda.x, tba.y + bva.y + dij*wda.y));
        pk.y = silu2_h2(f16x2_from2f(tba.z + bva.z + dij*wda.z, tba.w + bva.w + dij*wda.w));
        pk.z = silu2_h2(f16x2_from2f(tbb.x + bvb.x + dij*wdb.x, tbb.y + bvb.y + dij*wdb.y));
        pk.w = silu2_h2(f16x2_from2f(tbb.z + bvb.z + dij*wdb.z, tbb.w + bvb.w + dij*wdb.w));
        *(uint4*)(base + OFF_M1 + m1row*(KS*2) + m1k0*2) = pk;
    }
    __syncthreads();

    for (int T = 0; T < NTH; T++){
        int buf = T & 1;

        // ---- prefetch g_Bv for tile T+1 into registers BEFORE GEMM ----
        float4 nbva, nbvb;
        float ndij = 0.f;
        if (T + 1 < NTH){
            int jl = (T+1)*TROWS + m1row;
            ndij = sDij[jl];
            const float4* bv = (const float4*)(g_Bv + (size_t)(b*NN + j0 + jl)*DD + m1k0);
            nbva = bv[0];
            nbvb = bv[1];
        }

        // ---- GEMM(T): warp computes C[16 j][16 t] from buf ----
        float acc[2][4];
        #pragma unroll
        for (int s = 0; s < 2; s++)
            #pragma unroll
            for (int c = 0; c < 4; c++) acc[s][c] = 0.f;

        uint32_t aA = sM1a + buf*M1BUF + aOff;
        uint32_t bA = bBase;
        #pragma unroll
        for (int ks = 0; ks < 8; ks++){
            uint32_t a0,a1,a2,a3, b0,b1,b2,b3;
            ldsm4(a0,a1,a2,a3, aA);
            ldsm4(b0,b1,b2,b3, bA);
            mma16816(acc[0], a0,a1,a2,a3, b0,b1);
            mma16816(acc[1], a0,a1,a2,a3, b2,b3);
            aA += 32; bA += 32;
        }

        // ---- m1(T+1) into other buffer from prefetched registers ----
        if (T + 1 < NTH){
            float4 tba = tb4[0], tbb = tb4[1];
            float4 wda = wd4[0], wdb = wd4[1];
            uint4 pk;
            pk.x = silu2_h2(f16x2_from2f(tba.x + nbva.x + ndij*wda.x, tba.y + nbva.y + ndij*wda.y));
            pk.y = silu2_h2(f16x2_from2f(tba.z + nbva.z + ndij*wda.z, tba.w + nbva.w + ndij*wda.w));
            pk.z = silu2_h2(f16x2_from2f(tbb.x + nbvb.x + ndij*wdb.x, tbb.y + nbvb.y + ndij*wdb.y));
            pk.w = silu2_h2(f16x2_from2f(tbb.z + nbvb.z + ndij*wdb.z, tbb.w + nbvb.w + ndij*wdb.w));
            *(uint4*)(base + OFF_M1 + (buf^1)*M1BUF + m1row*(KS*2) + m1k0*2) = pk;
        }

        // ---- epilogue(T): m2 = silu(C + be2) via packed f16x2, dot with we3 ----
        {
            int colq = wn + (lane & 3)*2;
            float d0 = 0.f, d1 = 0.f;
            #pragma unroll
            for (int s = 0; s < 2; s++){
                int col = colq + s*8;
                float w0 = sWt[128+col], w1 = sWt[128+col+1];
                float e0 = sWt[col], e1 = sWt[col+1];
                float2 f01 = unpack_h2(silu2_h2(f16x2_from2f(acc[s][0] + e0, acc[s][1] + e1)));
                float2 f23 = unpack_h2(silu2_h2(f16x2_from2f(acc[s][2] + e0, acc[s][3] + e1)));
                d0 += f01.x*w0 + f01.y*w1;
                d1 += f23.x*w0 + f23.y*w1;
            }
            d0 += __shfl_xor_sync(0xffffffffu, d0, 1);
            d0 += __shfl_xor_sync(0xffffffffu, d0, 2);
            d1 += __shfl_xor_sync(0xffffffffu, d1, 1);
            d1 += __shfl_xor_sync(0xffffffffu, d1, 2);
            if ((lane & 3) == 0){
                int row = lane >> 2;   // 0..7
                sPart[buf*128 + wid*16 + row]     = d0;
                sPart[buf*128 + wid*16 + row + 8] = d1;
            }
        }
        __syncthreads();   // the ONE barrier per tile

        // ---- fold sMij(T) (tid<16) ----
        if (tid < 16){
            int jl = T*TROWS + tid;
            float s = 0.f;
            #pragma unroll
            for (int w = 0; w < 8; w++) s += sPart[buf*128 + w*16 + tid];
            sMij[jl] = (s + be3v) * sPm[jl];
        }
    }
    __syncthreads();

    // -------- balanced warp-split tail over 160 local j's (packed silu) --------
    if (wid < 4){
        int t = tid;   // 0..127
        float wm1 = sWt[256+t], bm1v = sWt[384+t];
        float s = 0.f;
        #pragma unroll 4
        for (int jl = 0; jl < JH; jl += 2){
            float2 f = unpack_h2(silu2_h2(f16x2_from2f(
                fmaf(sMij[jl],   wm1, bm1v),
                fmaf(sMij[jl+1], wm1, bm1v))));
            s += f.x + f.y;
        }
        g_Sp[half*(BB*NN*DD) + (b*NN+i)*DD + t] = s;
        // warp 0 also computes sum_r (cheap)
        if (wid == 0){
            float s0=0.f, s1=0.f, s2=0.f;
            #pragma unroll
            for (int jl = lane; jl < JH; jl += 32){
                s0 += sRx[jl]; s1 += sRy[jl]; s2 += sRz[jl];
            }
            #pragma unroll
            for (int o = 16; o; o >>= 1){
                s0 += __shfl_xor_sync(0xffffffffu, s0, o);
                s1 += __shfl_xor_sync(0xffffffffu, s1, o);
                s2 += __shfl_xor_sync(0xffffffffu, s2, o);
            }
            if (lane == 0){ sRed[20] = s0; sRed[21] = s1; sRed[22] = s2; }
        }
    } else {
        // transposed phi: thread p owns hidden col p; loops all 160 j (packed silu)
        int p = tid - 128;
        float4 w = ((const float4*)(sWt + 512))[p];   // (wp1, bp1, wp2)
        float ux=0.f, uy=0.f, uz=0.f;
        #pragma unroll 4
        for (int jl = 0; jl < JH; jl += 2){
            float2 u = unpack_h2(silu2_h2(f16x2_from2f(
                fmaf(sMij[jl],   w.x, w.y),
                fmaf(sMij[jl+1], w.x, w.y))));
            ux = fmaf(u.x, sRx[jl], fmaf(u.y, sRx[jl+1], ux));
            uy = fmaf(u.x, sRy[jl], fmaf(u.y, sRy[jl+1], uy));
            uz = fmaf(u.x, sRz[jl], fmaf(u.y, sRz[jl+1], uz));
        }
        ux *= w.z; uy *= w.z; uz *= w.z;
        #pragma unroll
        for (int o = 16; o; o >>= 1){
            ux += __shfl_xor_sync(0xffffffffu, ux, o);
            uy += __shfl_xor_sync(0xffffffffu, uy, o);
            uz += __shfl_xor_sync(0xffffffffu, uz, o);
        }
        if (lane == 0){
            sRed[(wid-4)*4 + 0] = ux;
            sRed[(wid-4)*4 + 1] = uy;
            sRed[(wid-4)*4 + 2] = uz;
        }
    }
    __syncthreads();
    if (tid == 0){
        float a0=0,a1=0,a2=0;
        #pragma unroll
        for (int w = 0; w < 4; w++){
            a0 += sRed[w*4+0]; a1 += sRed[w*4+1]; a2 += sRed[w*4+2];
        }
        int idx = (b*NN+i)*3;
        g_dxp[half*(BB*NN*3) + idx + 0] = a0 + bp2v*sRed[20];
        g_dxp[half*(BB*NN*3) + idx + 1] = a1 + bp2v*sRed[21];
        g_dxp[half*(BB*NN*3) + idx + 2] = a2 + bp2v*sRed[22];
    }
}

// ---------------- blocked node update: fold halves, S@Wm2 -> GRU, x update; 8 nodes/block ----------------
// Also fused: compute A/Bv for the NEXT layer from the freshly produced h (doA != 0).
__global__ void __launch_bounds__(128) k_node(
    const float* __restrict__ Wm2l, const float* __restrict__ bm2l,
    const float* __restrict__ Wihl, const float* __restrict__ Whhl,
    const float* __restrict__ bihl, const float* __restrict__ bhhl,
    const float* __restrict__ mask,
    const float* __restrict__ We1n, int doA)
{
    __shared__ float sS[8*128], shh[8*128], smn[8*128], sG[8*384], sHn[8*128];
    int g0 = blockIdx.x*8, tid = threadIdx.x;

    // fold the two halves of S; also update x from dx partials
    #pragma unroll
    for (int q = 0; q < 8; q++){
        int idx = (g0+q)*DD + tid;
        sS[q*128+tid]  = g_Sp[idx] + g_Sp[BB*NN*DD + idx];
        shh[q*128+tid] = g_h[idx];
    }
    if (tid < 24){
        int q = tid / 3, c = tid % 3;
        int idx = (g0+q)*3 + c;
        g_x[idx] += g_dxp[idx] + g_dxp[BB*NN*3 + idx];
    }
    __syncthreads();

    // mn = S @ Wm2 + NN*bm2 (col = tid)
    {
        float acc[8];
        float bm = (float)NN * bm2l[tid];
        #pragma unroll
        for (int q = 0; q < 8; q++) acc[q] = bm;
        for (int k = 0; k < DD; k += 4){
            float4 w4;
            w4.x = Wm2l[(k+0)*DD + tid];
            w4.y = Wm2l[(k+1)*DD + tid];
            w4.z = Wm2l[(k+2)*DD + tid];
            w4.w = Wm2l[(k+3)*DD + tid];
            #pragma unroll
            for (int q = 0; q < 8; q++){
                float4 s4 = *(const float4*)(sS + q*128 + k);
                acc[q] += s4.x*w4.x + s4.y*w4.y + s4.z*w4.z + s4.w*w4.w;
            }
        }
        #pragma unroll
        for (int q = 0; q < 8; q++) smn[q*128+tid] = acc[q];
    }
    __syncthreads();

    // gates: thread owns cols tid, tid+128, tid+256
    for (int c3 = 0; c3 < 3; c3++){
        int col = tid + c3*128;
        float gi[8], gh[8];
        float bi = bihl[col], bh = bhhl[col];
        #pragma unroll
        for (int q = 0; q < 8; q++){ gi[q] = bi; gh[q] = bh; }
        for (int k = 0; k < DD; k += 4){
            #pragma unroll
            for (int kk = 0; kk < 4; kk++){
                float wi = Wihl[(k+kk)*384 + col];
                float wh = Whhl[(k+kk)*384 + col];
                #pragma unroll
                for (int q = 0; q < 8; q++){
                    gi[q] = fmaf(smn[q*128 + k+kk], wi, gi[q]);
                    gh[q] = fmaf(shh[q*128 + k+kk], wh, gh[q]);
                }
            }
        }
        if (c3 < 2){
            #pragma unroll
            for (int q = 0; q < 8; q++) sG[q*384+col] = gi[q] + gh[q];
        } else {
            #pragma unroll
            for (int q = 0; q < 8; q++){ sG[q*384+col] = gi[q]; sHn[q*128+tid] = gh[q]; }
        }
    }
    __syncthreads();

    // finalize h; overwrite shh with new h for the fused A/Bv stage
    #pragma unroll
    for (int q = 0; q < 8; q++){
        float r = sigm_f(sG[q*384 + tid]);
        float z = sigm_f(sG[q*384 + 128 + tid]);
        float n = tanh_ap(sG[q*384 + 256 + tid] + r*sHn[q*128+tid]);
        float hn = ((1.f - z)*n + z*shh[q*128+tid]) * mask[g0+q];
        g_h[(g0+q)*DD + tid] = hn;
        shh[q*128+tid] = hn;
    }

    if (doA){
        __syncthreads();
        float a[8], bv[8];
        #pragma unroll
        for (int q = 0; q < 8; q++){ a[q] = 0.f; bv[q] = 0.f; }
        for (int k = 0; k < DD; k += 4){
            float w1a = We1n[(k+0)*DD + tid], w2a = We1n[(DD+k+0)*DD + tid];
            float w1b = We1n[(k+1)*DD + tid], w2b = We1n[(DD+k+1)*DD + tid];
            float w1c = We1n[(k+2)*DD + tid], w2c = We1n[(DD+k+2)*DD + tid];
            float w1d = We1n[(k+3)*DD + tid], w2d = We1n[(DD+k+3)*DD + tid];
            #pragma unroll
            for (int q = 0; q < 8; q++){
                float4 h4 = *(const float4*)(shh + q*128 + k);
                a[q]  += h4.x*w1a + h4.y*w1b + h4.z*w1c + h4.w*w1d;
                bv[q] += h4.x*w2a + h4.y*w2b + h4.z*w2c + h4.w*w2d;
            }
        }
        #pragma unroll
        for (int q = 0; q < 8; q++){
            g_A[(g0+q)*DD + tid]  = a[q];
            g_Bv[(g0+q)*DD + tid] = bv[q];
        }
    }
}

// ---------------- pool + head ----------------
__global__ void k_pool(const float* __restrict__ mask,
                       const float* __restrict__ Wc1, const float* __restrict__ bc1,
                       const float* __restrict__ Wc2, const float* __restrict__ bc2,
                       const float* __restrict__ Wc3, const float* __restrict__ bc3,
                       float* __restrict__ out){
    int b = blockIdx.x, tid = threadIdx.x;
    __shared__ float feat[DD], o1[DD], o2[64];
    float s = 0.f, ms = 0.f;
    for (int i = 0; i < NN; i++){
        float mk = mask[b*NN + i];
        s  += g_h[(b*NN+i)*DD + tid]*mk;
        ms += mk;
    }
    feat[tid] = s / fmaxf(ms, 1.f);
    __syncthreads();
    float t = bc1[tid];
    #pragma unroll 8
    for (int k = 0; k < DD; k++) t += feat[k]*Wc1[k*DD + tid];
    o1[tid] = silu_f(t);
    __syncthreads();
    if (tid < 64){
        float t2 = bc2[tid];
        #pragma unroll 8
        for (int k = 0; k < DD; k++) t2 += o1[k]*Wc2[k*64 + tid];
        o2[tid] = silu_f(t2);
    }
    __syncthreads();
    if (tid < 6){
        float t3 = bc3[tid];
        #pragma unroll
        for (int k = 0; k < 64; k++) t3 += o2[k]*Wc3[k*6 + tid];
        float r;
        if (tid < 3){
            r = (t3 > 20.f) ? t3 : log1pf(expf(t3));
        } else {
            r = (1.f / (1.f + expf(-t3))) * 180.f;
        }
        out[b*6 + tid] = r;
    }
}

extern "C" void kernel_launch(void* const* d_in, const int* in_sizes, int n_in,
                              void* d_out, int out_size){
    const float* pos   = (const float*)d_in[0];
    const float* oneh  = (const float*)d_in[1];
    const float* mask  = (const float*)d_in[2];
    const float* cell  = (const float*)d_in[3];
    const float* W_in1 = (const float*)d_in[4];
    const float* b_in1 = (const float*)d_in[5];
    const float* W_in2 = (const float*)d_in[6];
    const float* b_in2 = (const float*)d_in[7];
    const float* We1   = (const float*)d_in[8];
    const float* be1   = (const float*)d_in[9];
    const float* We2   = (const float*)d_in[10];
    const float* be2   = (const float*)d_in[11];
    const float* We3   = (const float*)d_in[12];
    const float* be3   = (const float*)d_in[13];
    const float* Wm1   = (const float*)d_in[14];
    const float* bm1   = (const float*)d_in[15];
    const float* Wm2   = (const float*)d_in[16];
    const float* bm2   = (const float*)d_in[17];
    const float* Wp1   = (const float*)d_in[18];
    const float* bp1   = (const float*)d_in[19];
    const float* Wp2   = (const float*)d_in[20];
    const float* bp2   = (const float*)d_in[21];
    const float* W_ih  = (const float*)d_in[22];
    const float* W_hh  = (const float*)d_in[23];
    const float* b_ih  = (const float*)d_in[24];
    const float* b_hh  = (const float*)d_in[25];
    const float* Wc1   = (const float*)d_in[26];
    const float* bc1   = (const float*)d_in[27];
    const float* Wc2   = (const float*)d_in[28];
    const float* bc2   = (const float*)d_in[29];
    const float* Wc3   = (const float*)d_in[30];
    const float* bc3   = (const float*)d_in[31];
    float* out = (float*)d_out;

    cudaFuncSetAttribute(k_edge, cudaFuncAttributeMaxDynamicSharedMemorySize, SMEMB);

    k_inv<<<1, 32>>>(cell);
    k_init<<<(BB*NN*3 + 127)/128, 128>>>(pos);
    k_prepW<<<LL*8, 256>>>(We2);
    k_embed<<<dim3(NN, BB), 128>>>(pos, oneh, W_in1, b_in1, W_in2, b_in2);
    k_A8<<<BB*NN/8, 128>>>(We1);   // layer 0 A/Bv

    for (int l = 0; l < LL; l++){
        k_edge<<<dim3(NN, BB, 2), 256, SMEMB>>>(We1 + l*257*DD, be1 + l*DD,
                                    be2 + l*DD, We3 + l*DD, be3 + l,
                                    Wm1 + l*DD, bm1 + l*DD,
                                    Wp1 + l*DD, bp1 + l*DD,
                                    Wp2 + l*DD, bp2 + l,
                                    cell, mask, l);
        int doA = (l + 1 < LL);
        k_node<<<BB*NN/8, 128>>>(Wm2 + l*DD*DD, bm2 + l*DD,
                                 W_ih + l*DD*3*DD, W_hh + l*DD*3*DD,
                                 b_ih + l*3*DD,    b_hh + l*3*DD, mask,
                                 We1 + (doA ? (l+1)*257*DD : 0), doA);
    }

    k_pool<<<BB, 128>>>(mask, Wc1, bc1, Wc2, bc2, Wc3, bc3, out);
}